// round 1
// baseline (speedup 1.0000x reference)
#include <cuda_runtime.h>
#include <cuda_bf16.h>
#include <math.h>
#include <stdint.h>

// Problem dims
#define B_  4
#define S_  2048
#define D_  1024
#define H_  16
#define DKH 64
#define DFF_ 4096
#define NT  (B_ * S_)   // 8192 tokens

// ---------------- scratch (device globals; no allocations allowed) ----------
__device__ float g_z[(size_t)NT * D_];     // LN output (reused for LN1 and LN2)
__device__ float g_q[(size_t)NT * D_];
__device__ float g_k[(size_t)NT * D_];
__device__ float g_v[(size_t)NT * D_];
__device__ float g_attn[(size_t)NT * D_];
__device__ float g_h1[(size_t)NT * D_];
__device__ float g_mid[(size_t)NT * DFF_];

// ---------------- LayerNorm (Bessel ddof=1, eps=1e-9) -----------------------
__global__ __launch_bounds__(256) void layernorm_kernel(
    const float* __restrict__ x, const float* __restrict__ gamma,
    const float* __restrict__ beta, float* __restrict__ y)
{
    int row = blockIdx.x;
    int t = threadIdx.x;
    const float4* xr = (const float4*)(x + (size_t)row * D_);
    float4 v = xr[t];  // 256 threads * 4 = 1024 = D_
    float s  = v.x + v.y + v.z + v.w;
    float ss = v.x*v.x + v.y*v.y + v.z*v.z + v.w*v.w;

    #pragma unroll
    for (int o = 16; o > 0; o >>= 1) {
        s  += __shfl_xor_sync(0xffffffffu, s,  o);
        ss += __shfl_xor_sync(0xffffffffu, ss, o);
    }
    __shared__ float shs[8], shq[8];
    int w = t >> 5, l = t & 31;
    if (l == 0) { shs[w] = s; shq[w] = ss; }
    __syncthreads();
    float S = 0.f, Q = 0.f;
    #pragma unroll
    for (int i = 0; i < 8; i++) { S += shs[i]; Q += shq[i]; }

    float mean = S * (1.f / (float)D_);
    float var  = (Q - (float)D_ * mean * mean) * (1.f / (float)(D_ - 1));
    float inv  = rsqrtf(var + 1e-9f);

    const float4 g  = ((const float4*)gamma)[t];
    const float4 be = ((const float4*)beta)[t];
    float4 out;
    out.x = g.x * (v.x - mean) * inv + be.x;
    out.y = g.y * (v.y - mean) * inv + be.y;
    out.z = g.z * (v.z - mean) * inv + be.z;
    out.w = g.w * (v.w - mean) * inv + be.w;
    ((float4*)(y + (size_t)row * D_))[t] = out;
}

// ---------------- SGEMM: C[M,N] = act(A[M,K] @ W[N,K]^T + bias) (+res) ------
// 128x128x8 tile, 256 threads, 8x8 per thread, register-prefetch pipeline.
#define BM 128
#define BN 128
#define BKG 8
#define SMPAD 132  // row stride; 132*4B = 528B = 33*16B (float4-aligned, conflict-free)

template<bool RELU, bool BIAS, bool RES>
__global__ __launch_bounds__(256, 2) void sgemm_kernel(
    const float* __restrict__ A, const float* __restrict__ W,
    const float* __restrict__ bias, const float* __restrict__ res,
    float* __restrict__ C, int M, int N, int K)
{
    __shared__ float As[BKG][SMPAD];
    __shared__ float Bs[BKG][SMPAD];

    int tid = threadIdx.x;
    int tx = tid & 15;        // 0..15 -> 8 output cols each
    int ty = tid >> 4;        // 0..15 -> 8 output rows each
    int lrow = tid >> 1;      // 0..127
    int lk   = (tid & 1) * 4; // 0 or 4

    const float* Aptr = A + (size_t)(blockIdx.y * BM + lrow) * K + lk;
    const float* Wptr = W + (size_t)(blockIdx.x * BN + lrow) * K + lk;

    float acc[8][8];
    #pragma unroll
    for (int i = 0; i < 8; i++)
        #pragma unroll
        for (int j = 0; j < 8; j++) acc[i][j] = 0.f;

    int KT = K / BKG;
    float4 ra = *(const float4*)Aptr;
    float4 rb = *(const float4*)Wptr;

    for (int kt = 0; kt < KT; ++kt) {
        As[lk+0][lrow] = ra.x; As[lk+1][lrow] = ra.y;
        As[lk+2][lrow] = ra.z; As[lk+3][lrow] = ra.w;
        Bs[lk+0][lrow] = rb.x; Bs[lk+1][lrow] = rb.y;
        Bs[lk+2][lrow] = rb.z; Bs[lk+3][lrow] = rb.w;
        __syncthreads();
        if (kt + 1 < KT) {
            ra = *(const float4*)(Aptr + (size_t)(kt + 1) * BKG);
            rb = *(const float4*)(Wptr + (size_t)(kt + 1) * BKG);
        }
        #pragma unroll
        for (int kk = 0; kk < BKG; ++kk) {
            float4 a0 = *(const float4*)&As[kk][ty * 8];
            float4 a1 = *(const float4*)&As[kk][ty * 8 + 4];
            float4 b0 = *(const float4*)&Bs[kk][tx * 8];
            float4 b1 = *(const float4*)&Bs[kk][tx * 8 + 4];
            float a[8] = {a0.x,a0.y,a0.z,a0.w,a1.x,a1.y,a1.z,a1.w};
            float b[8] = {b0.x,b0.y,b0.z,b0.w,b1.x,b1.y,b1.z,b1.w};
            #pragma unroll
            for (int i = 0; i < 8; i++)
                #pragma unroll
                for (int j = 0; j < 8; j++)
                    acc[i][j] = fmaf(a[i], b[j], acc[i][j]);
        }
        __syncthreads();
    }

    int col0 = blockIdx.x * BN + tx * 8;
    float4 bi0, bi1;
    if (BIAS) {
        bi0 = *(const float4*)&bias[col0];
        bi1 = *(const float4*)&bias[col0 + 4];
    }
    #pragma unroll
    for (int i = 0; i < 8; i++) {
        int row = blockIdx.y * BM + ty * 8 + i;
        size_t base = (size_t)row * N + col0;
        float4 v0 = make_float4(acc[i][0], acc[i][1], acc[i][2], acc[i][3]);
        float4 v1 = make_float4(acc[i][4], acc[i][5], acc[i][6], acc[i][7]);
        if (BIAS) {
            v0.x += bi0.x; v0.y += bi0.y; v0.z += bi0.z; v0.w += bi0.w;
            v1.x += bi1.x; v1.y += bi1.y; v1.z += bi1.z; v1.w += bi1.w;
        }
        if (RELU) {
            v0.x = fmaxf(v0.x, 0.f); v0.y = fmaxf(v0.y, 0.f);
            v0.z = fmaxf(v0.z, 0.f); v0.w = fmaxf(v0.w, 0.f);
            v1.x = fmaxf(v1.x, 0.f); v1.y = fmaxf(v1.y, 0.f);
            v1.z = fmaxf(v1.z, 0.f); v1.w = fmaxf(v1.w, 0.f);
        }
        if (RES) {
            float4 r0 = *(const float4*)&res[base];
            float4 r1 = *(const float4*)&res[base + 4];
            v0.x += r0.x; v0.y += r0.y; v0.z += r0.z; v0.w += r0.w;
            v1.x += r1.x; v1.y += r1.y; v1.z += r1.z; v1.w += r1.w;
        }
        *(float4*)&C[base]     = v0;
        *(float4*)&C[base + 4] = v1;
    }
}

// ---------------- Flash attention (fp32, online softmax) --------------------
// grid: (S/64, B*H). 256 threads. 64 q-rows per block, 64-key chunks.
// smem: Qs[k][r] (k-major), KP = K tile k-major then reused for swizzled P, Vs[c][d].
__global__ __launch_bounds__(256, 4) void attention_kernel(
    const float* __restrict__ qbuf, const float* __restrict__ kbuf,
    const float* __restrict__ vbuf, const int* __restrict__ mask,
    float* __restrict__ obuf)
{
    __shared__ float Qs[DKH][64];
    __shared__ float KP[DKH * 64];
    __shared__ float Vs[64][DKH];

    int tid = threadIdx.x;
    int bh = blockIdx.y;
    int b = bh >> 4;
    int h = bh & 15;
    int q0 = blockIdx.x * 64;
    int tx = tid & 15;   // key cols / out dims (x4)
    int ty = tid >> 4;   // q rows (x4)
    int lr = tid >> 2;          // 0..63 (row for tile loads)
    int lseg = (tid & 3) * 16;  // 0,16,32,48

    size_t headoff = (size_t)h * DKH;
    const float* qsrc = qbuf + ((size_t)(b * S_ + q0 + lr)) * D_ + headoff + lseg;
    #pragma unroll
    for (int i = 0; i < 4; i++) {
        float4 xv = *(const float4*)(qsrc + i * 4);
        int kb = lseg + i * 4;
        Qs[kb+0][lr] = xv.x * 0.125f;  // 1/sqrt(64)
        Qs[kb+1][lr] = xv.y * 0.125f;
        Qs[kb+2][lr] = xv.z * 0.125f;
        Qs[kb+3][lr] = xv.w * 0.125f;
    }

    float m[4], l[4], acc[4][4];
    #pragma unroll
    for (int i = 0; i < 4; i++) {
        m[i] = -1e30f; l[i] = 0.f;
        #pragma unroll
        for (int j = 0; j < 4; j++) acc[i][j] = 0.f;
    }

    const float* kbase = kbuf + (size_t)b * S_ * D_ + headoff;
    const float* vbase = vbuf + (size_t)b * S_ * D_ + headoff;
    const int* mrow = mask + (size_t)b * S_;

    for (int c0 = 0; c0 < S_; c0 += 64) {
        __syncthreads();  // protect prior-chunk reads (and Q stores on iter 0)
        {
            const float* ks = kbase + (size_t)(c0 + lr) * D_ + lseg;
            const float* vs = vbase + (size_t)(c0 + lr) * D_ + lseg;
            #pragma unroll
            for (int i = 0; i < 4; i++) {
                float4 kv = *(const float4*)(ks + i * 4);
                int kb = lseg + i * 4;
                KP[(kb+0)*64 + lr] = kv.x;
                KP[(kb+1)*64 + lr] = kv.y;
                KP[(kb+2)*64 + lr] = kv.z;
                KP[(kb+3)*64 + lr] = kv.w;
                *(float4*)&Vs[lr][lseg + i * 4] = *(const float4*)(vs + i * 4);
            }
        }
        int4 mv = *(const int4*)(mrow + c0 + tx * 4);
        __syncthreads();

        float s[4][4];
        #pragma unroll
        for (int i = 0; i < 4; i++)
            #pragma unroll
            for (int j = 0; j < 4; j++) s[i][j] = 0.f;

        #pragma unroll 8
        for (int kk = 0; kk < DKH; ++kk) {
            float4 a = *(const float4*)&Qs[kk][ty * 4];
            float4 bq = *(const float4*)&KP[kk * 64 + tx * 4];
            float av[4] = {a.x, a.y, a.z, a.w};
            float bv[4] = {bq.x, bq.y, bq.z, bq.w};
            #pragma unroll
            for (int i = 0; i < 4; i++)
                #pragma unroll
                for (int j = 0; j < 4; j++)
                    s[i][j] = fmaf(av[i], bv[j], s[i][j]);
        }
        // mask (set, not add)
        #pragma unroll
        for (int i = 0; i < 4; i++) {
            if (mv.x == 0) s[i][0] = -1e9f;
            if (mv.y == 0) s[i][1] = -1e9f;
            if (mv.z == 0) s[i][2] = -1e9f;
            if (mv.w == 0) s[i][3] = -1e9f;
        }
        // online softmax
        float sc[4];
        #pragma unroll
        for (int i = 0; i < 4; i++) {
            float cm = fmaxf(fmaxf(s[i][0], s[i][1]), fmaxf(s[i][2], s[i][3]));
            #pragma unroll
            for (int o = 1; o < 16; o <<= 1)
                cm = fmaxf(cm, __shfl_xor_sync(0xffffffffu, cm, o));
            float mn = fmaxf(m[i], cm);
            sc[i] = __expf(m[i] - mn);
            m[i] = mn;
            float rs = 0.f;
            #pragma unroll
            for (int j = 0; j < 4; j++) {
                s[i][j] = __expf(s[i][j] - mn);
                rs += s[i][j];
            }
            #pragma unroll
            for (int o = 1; o < 16; o <<= 1)
                rs += __shfl_xor_sync(0xffffffffu, rs, o);
            l[i] = l[i] * sc[i] + rs;
            #pragma unroll
            for (int j = 0; j < 4; j++) acc[i][j] *= sc[i];
        }
        __syncthreads();  // done reading KP as K
        // store P into KP with XOR swizzle: idx = c*64 + (r ^ (c&31))
        #pragma unroll
        for (int i = 0; i < 4; i++) {
            int r = ty * 4 + i;
            #pragma unroll
            for (int j = 0; j < 4; j++) {
                int c = tx * 4 + j;
                KP[c * 64 + (r ^ (c & 31))] = s[i][j];
            }
        }
        __syncthreads();
        // acc += P @ V
        #pragma unroll 8
        for (int kk = 0; kk < 64; ++kk) {
            float4 vv = *(const float4*)&Vs[kk][tx * 4];
            float vvv[4] = {vv.x, vv.y, vv.z, vv.w};
            #pragma unroll
            for (int i = 0; i < 4; i++) {
                float pr = KP[kk * 64 + ((ty * 4 + i) ^ (kk & 31))];
                #pragma unroll
                for (int j = 0; j < 4; j++)
                    acc[i][j] = fmaf(pr, vvv[j], acc[i][j]);
            }
        }
    }

    #pragma unroll
    for (int i = 0; i < 4; i++) {
        float inv = 1.f / l[i];
        int r = q0 + ty * 4 + i;
        float4 ov = make_float4(acc[i][0]*inv, acc[i][1]*inv, acc[i][2]*inv, acc[i][3]*inv);
        *(float4*)&obuf[((size_t)(b * S_ + r)) * D_ + headoff + tx * 4] = ov;
    }
}

// ---------------- launch ----------------------------------------------------
extern "C" void kernel_launch(void* const* d_in, const int* in_sizes, int n_in,
                              void* d_out, int out_size)
{
    (void)in_sizes; (void)n_in; (void)out_size;
    const float* x    = (const float*)d_in[0];
    const int*   mask = (const int*)  d_in[1];
    const float* wq   = (const float*)d_in[2];
    const float* wk   = (const float*)d_in[3];
    const float* wv   = (const float*)d_in[4];
    const float* wo   = (const float*)d_in[5];
    const float* w1   = (const float*)d_in[6];
    const float* b1   = (const float*)d_in[7];
    const float* w2   = (const float*)d_in[8];
    const float* b2   = (const float*)d_in[9];
    const float* g1   = (const float*)d_in[10];
    const float* be1  = (const float*)d_in[11];
    const float* g2   = (const float*)d_in[12];
    const float* be2  = (const float*)d_in[13];
    float* out = (float*)d_out;

    float *z, *q, *k, *v, *attn, *h1, *mid;
    cudaGetSymbolAddress((void**)&z,    g_z);
    cudaGetSymbolAddress((void**)&q,    g_q);
    cudaGetSymbolAddress((void**)&k,    g_k);
    cudaGetSymbolAddress((void**)&v,    g_v);
    cudaGetSymbolAddress((void**)&attn, g_attn);
    cudaGetSymbolAddress((void**)&h1,   g_h1);
    cudaGetSymbolAddress((void**)&mid,  g_mid);

    dim3 thr(256);

    // z = LN1(x)
    layernorm_kernel<<<NT, thr>>>(x, g1, be1, z);

    // q/k/v = z @ w{q,k,v}^T
    dim3 gQKV(D_ / BN, NT / BM);
    sgemm_kernel<false,false,false><<<gQKV, thr>>>(z, wq, nullptr, nullptr, q, NT, D_, D_);
    sgemm_kernel<false,false,false><<<gQKV, thr>>>(z, wk, nullptr, nullptr, k, NT, D_, D_);
    sgemm_kernel<false,false,false><<<gQKV, thr>>>(z, wv, nullptr, nullptr, v, NT, D_, D_);

    // attn = softmax(q k^T / 8 + mask) v
    dim3 gAtt(S_ / 64, B_ * H_);
    attention_kernel<<<gAtt, thr>>>(q, k, v, mask, attn);

    // h1 = x + attn @ wo^T
    sgemm_kernel<false,false,true><<<gQKV, thr>>>(attn, wo, nullptr, x, h1, NT, D_, D_);

    // z = LN2(h1)
    layernorm_kernel<<<NT, thr>>>(h1, g2, be2, z);

    // mid = relu(z @ w1^T + b1)
    dim3 gF1(DFF_ / BN, NT / BM);
    sgemm_kernel<true,true,false><<<gF1, thr>>>(z, w1, b1, nullptr, mid, NT, DFF_, D_);

    // out = h1 + mid @ w2^T + b2
    dim3 gF2(D_ / BN, NT / BM);
    sgemm_kernel<false,true,true><<<gF2, thr>>>(mid, w2, b2, h1, out, NT, D_, DFF_);
}

// round 3
// speedup vs baseline: 1.5924x; 1.5924x over previous
#include <cuda_runtime.h>
#include <cuda_bf16.h>
#include <math.h>
#include <stdint.h>

// Problem dims
#define B_  4
#define S_  2048
#define D_  1024
#define H_  16
#define DKH 64
#define DFF_ 4096
#define NT  (B_ * S_)   // 8192 tokens

typedef __nv_bfloat16 bf16;

// ====================== PTX helpers (baseline ISA, sm_80+) ==================
__device__ __forceinline__ uint32_t smem_to_u32(const void* p) {
    uint32_t a;
    asm("{ .reg .u64 t; cvta.to.shared.u64 t, %1; cvt.u32.u64 %0, t; }" : "=r"(a) : "l"(p));
    return a;
}
__device__ __forceinline__ void cp16(uint32_t dst, const void* src) {
    asm volatile("cp.async.cg.shared.global [%0], [%1], 16;" :: "r"(dst), "l"(src));
}
#define CP_COMMIT() asm volatile("cp.async.commit_group;" ::: "memory")
#define CP_WAIT2()  asm volatile("cp.async.wait_group 2;" ::: "memory")

__device__ __forceinline__ void ldm4(uint32_t* r, uint32_t addr) {
    asm volatile("ldmatrix.sync.aligned.m8n8.x4.shared.b16 {%0,%1,%2,%3}, [%4];"
        : "=r"(r[0]), "=r"(r[1]), "=r"(r[2]), "=r"(r[3]) : "r"(addr));
}
__device__ __forceinline__ void mma_bf16(float* d, const uint32_t* a,
                                         uint32_t b0, uint32_t b1) {
    asm volatile(
        "mma.sync.aligned.m16n8k16.row.col.f32.bf16.bf16.f32 "
        "{%0,%1,%2,%3}, {%4,%5,%6,%7}, {%8,%9}, {%0,%1,%2,%3};"
        : "+f"(d[0]), "+f"(d[1]), "+f"(d[2]), "+f"(d[3])
        : "r"(a[0]), "r"(a[1]), "r"(a[2]), "r"(a[3]), "r"(b0), "r"(b1));
}

// ============ bf16 hi/lo split helpers ======================================
__device__ __forceinline__ uint32_t pk2(float a, float b) {
    return (uint32_t)__bfloat16_as_ushort(__float2bfloat16(a)) |
           ((uint32_t)__bfloat16_as_ushort(__float2bfloat16(b)) << 16);
}
__device__ __forceinline__ float bfres(float a) {
    return a - __bfloat162float(__float2bfloat16(a));
}

// ---------------- scratch (device globals) ----------------------------------
__device__ __align__(256) float g_q[(size_t)NT * D_];
__device__ __align__(256) float g_k[(size_t)NT * D_];
__device__ __align__(256) float g_v[(size_t)NT * D_];
__device__ __align__(256) float g_h1[(size_t)NT * D_];
__device__ __align__(256) bf16 g_zh[(size_t)NT * D_],  g_zl[(size_t)NT * D_];
__device__ __align__(256) bf16 g_ah[(size_t)NT * D_],  g_al[(size_t)NT * D_];
__device__ __align__(256) bf16 g_mh[(size_t)NT * DFF_], g_ml[(size_t)NT * DFF_];
__device__ __align__(256) bf16 g_wqh[(size_t)D_*D_], g_wql[(size_t)D_*D_];
__device__ __align__(256) bf16 g_wkh[(size_t)D_*D_], g_wkl[(size_t)D_*D_];
__device__ __align__(256) bf16 g_wvh[(size_t)D_*D_], g_wvl[(size_t)D_*D_];
__device__ __align__(256) bf16 g_woh[(size_t)D_*D_], g_wol[(size_t)D_*D_];
__device__ __align__(256) bf16 g_w1h[(size_t)DFF_*D_], g_w1l[(size_t)DFF_*D_];
__device__ __align__(256) bf16 g_w2h[(size_t)D_*DFF_], g_w2l[(size_t)D_*DFF_];

// ---------------- fp32 -> bf16 hi/lo convert --------------------------------
__global__ __launch_bounds__(256) void convert_hilo(
    const float* __restrict__ src, bf16* __restrict__ hi, bf16* __restrict__ lo, int n4)
{
    int i = blockIdx.x * 256 + threadIdx.x;
    if (i >= n4) return;
    float4 v = ((const float4*)src)[i];
    ((uint2*)hi)[i] = make_uint2(pk2(v.x, v.y), pk2(v.z, v.w));
    ((uint2*)lo)[i] = make_uint2(pk2(bfres(v.x), bfres(v.y)), pk2(bfres(v.z), bfres(v.w)));
}

// ---------------- LayerNorm (Bessel ddof=1, eps=1e-9) -> bf16 hi/lo ---------
__global__ __launch_bounds__(256) void layernorm_kernel(
    const float* __restrict__ x, const float* __restrict__ gamma,
    const float* __restrict__ beta, bf16* __restrict__ yh, bf16* __restrict__ yl)
{
    int row = blockIdx.x;
    int t = threadIdx.x;
    const float4* xr = (const float4*)(x + (size_t)row * D_);
    float4 v = xr[t];
    float s  = v.x + v.y + v.z + v.w;
    float ss = v.x*v.x + v.y*v.y + v.z*v.z + v.w*v.w;
    #pragma unroll
    for (int o = 16; o > 0; o >>= 1) {
        s  += __shfl_xor_sync(0xffffffffu, s,  o);
        ss += __shfl_xor_sync(0xffffffffu, ss, o);
    }
    __shared__ float shs[8], shq[8];
    int w = t >> 5, l = t & 31;
    if (l == 0) { shs[w] = s; shq[w] = ss; }
    __syncthreads();
    float S = 0.f, Q = 0.f;
    #pragma unroll
    for (int i = 0; i < 8; i++) { S += shs[i]; Q += shq[i]; }
    float mean = S * (1.f / (float)D_);
    float var  = (Q - (float)D_ * mean * mean) * (1.f / (float)(D_ - 1));
    float inv  = rsqrtf(var + 1e-9f);
    const float4 g  = ((const float4*)gamma)[t];
    const float4 be = ((const float4*)beta)[t];
    float o0 = g.x * (v.x - mean) * inv + be.x;
    float o1 = g.y * (v.y - mean) * inv + be.y;
    float o2 = g.z * (v.z - mean) * inv + be.z;
    float o3 = g.w * (v.w - mean) * inv + be.w;
    size_t idx = (size_t)row * (D_/4) + t;
    ((uint2*)yh)[idx] = make_uint2(pk2(o0, o1), pk2(o2, o3));
    ((uint2*)yl)[idx] = make_uint2(pk2(bfres(o0), bfres(o1)), pk2(bfres(o2), bfres(o3)));
}

// ---------------- mma.sync bf16-split GEMM ----------------------------------
// C[M,N] = act(A[M,K] @ W[N,K]^T + bias) (+res).  A,W given as bf16 hi/lo.
// 128x128x32 CTA tile, 256 threads (8 warps, 2m x 4n), 3-stage cp.async.
// Smem rows: 32 bf16 = 64B data + 16B pad = 80B stride (conflict-free ldmatrix).
#define ROWB 80
#define MAT_BYTES (128 * ROWB)          // 10240
#define STAGE_BYTES (4 * MAT_BYTES)     // 40960: Ah | Al | Bh | Bl
#define SMEM_GEMM (3 * STAGE_BYTES)     // 122880

template<bool RELU, bool BIAS, bool RES, bool OUTBF16>
__global__ __launch_bounds__(256, 1) void tc_gemm(
    const bf16* __restrict__ Ah, const bf16* __restrict__ Al,
    const bf16* __restrict__ Bh, const bf16* __restrict__ Bl,
    const float* __restrict__ bias, const float* __restrict__ res,
    float* __restrict__ Cf, bf16* __restrict__ Ch, bf16* __restrict__ Cl,
    int M, int N, int K)
{
    extern __shared__ char smem[];
    uint32_t sb = smem_to_u32(smem);
    int tid = threadIdx.x;
    int lane = tid & 31, wid = tid >> 5;
    int wm = wid & 1, wn = wid >> 1;
    int row0 = blockIdx.y * 128, col0 = blockIdx.x * 128;

    // ---- loader mapping: thread -> (row lm, chunk pair lc) ----
    int lm = tid >> 1;
    int lc = (tid & 1) * 2;       // chunks lc, lc+1 (16B each, 8 bf16)
    const bf16* aHs = Ah + (size_t)(row0 + lm) * K + lc * 8;
    const bf16* aLs = Al + (size_t)(row0 + lm) * K + lc * 8;
    const bf16* bHs = Bh + (size_t)(col0 + lm) * K + lc * 8;
    const bf16* bLs = Bl + (size_t)(col0 + lm) * K + lc * 8;
    uint32_t dA = (uint32_t)(lm * ROWB + lc * 16);

    auto load_stage = [&](int p, int kt) {
        uint32_t s0 = sb + p * STAGE_BYTES;
        size_t ko = (size_t)kt * 32;
        cp16(s0 + dA,                    aHs + ko);
        cp16(s0 + dA + 16,               aHs + ko + 8);
        cp16(s0 + MAT_BYTES + dA,        aLs + ko);
        cp16(s0 + MAT_BYTES + dA + 16,   aLs + ko + 8);
        cp16(s0 + 2*MAT_BYTES + dA,      bHs + ko);
        cp16(s0 + 2*MAT_BYTES + dA + 16, bHs + ko + 8);
        cp16(s0 + 3*MAT_BYTES + dA,      bLs + ko);
        cp16(s0 + 3*MAT_BYTES + dA + 16, bLs + ko + 8);
    };

    // ---- ldmatrix lane offsets ----
    int g = lane >> 3, r = lane & 7;
    uint32_t aoff = (uint32_t)((wm * 64 + (g & 1) * 8 + r) * ROWB + (g >> 1) * 16);
    uint32_t boff = (uint32_t)((wn * 32 + (g >> 1) * 8 + r) * ROWB + (g & 1) * 16);

    float acc[4][4][4];
    #pragma unroll
    for (int i = 0; i < 4; i++)
        #pragma unroll
        for (int j = 0; j < 4; j++)
            #pragma unroll
            for (int e = 0; e < 4; e++) acc[i][j][e] = 0.f;

    int KT = K / 32;
    load_stage(0, 0); CP_COMMIT();
    load_stage(1, 1); CP_COMMIT();
    load_stage(2, 2); CP_COMMIT();

    for (int kt = 0; kt < KT; kt++) {
        int s = kt % 3;
        CP_WAIT2();
        __syncthreads();
        uint32_t st = sb + s * STAGE_BYTES;
        #pragma unroll
        for (int h = 0; h < 2; h++) {
            uint32_t ah[4][4], al[4][4], bh[2][4], bl[2][4];
            #pragma unroll
            for (int mt = 0; mt < 4; mt++) {
                ldm4(ah[mt], st + aoff + mt * (16 * ROWB) + h * 32);
                ldm4(al[mt], st + MAT_BYTES + aoff + mt * (16 * ROWB) + h * 32);
            }
            #pragma unroll
            for (int nb = 0; nb < 2; nb++) {
                ldm4(bh[nb], st + 2*MAT_BYTES + boff + nb * (16 * ROWB) + h * 32);
                ldm4(bl[nb], st + 3*MAT_BYTES + boff + nb * (16 * ROWB) + h * 32);
            }
            #pragma unroll
            for (int mt = 0; mt < 4; mt++) {
                #pragma unroll
                for (int nt = 0; nt < 4; nt++) {
                    uint32_t b0h = bh[nt >> 1][(nt & 1) * 2];
                    uint32_t b1h = bh[nt >> 1][(nt & 1) * 2 + 1];
                    uint32_t b0l = bl[nt >> 1][(nt & 1) * 2];
                    uint32_t b1l = bl[nt >> 1][(nt & 1) * 2 + 1];
                    mma_bf16(acc[mt][nt], ah[mt], b0h, b1h);
                    mma_bf16(acc[mt][nt], ah[mt], b0l, b1l);
                    mma_bf16(acc[mt][nt], al[mt], b0h, b1h);
                }
            }
        }
        __syncthreads();
        if (kt + 3 < KT) load_stage(s, kt + 3);
        CP_COMMIT();
    }

    // ---------------- epilogue ----------------
    #pragma unroll
    for (int mt = 0; mt < 4; mt++) {
        int r_lo = row0 + wm * 64 + mt * 16 + (lane >> 2);
        #pragma unroll
        for (int nt = 0; nt < 4; nt++) {
            int col = col0 + wn * 32 + nt * 8 + (lane & 3) * 2;
            float* d = acc[mt][nt];
            float bi0 = 0.f, bi1 = 0.f;
            if (BIAS) { bi0 = __ldg(bias + col); bi1 = __ldg(bias + col + 1); }
            #pragma unroll
            for (int half = 0; half < 2; half++) {
                int row = r_lo + half * 8;
                float v0 = d[half * 2 + 0], v1 = d[half * 2 + 1];
                if (BIAS) { v0 += bi0; v1 += bi1; }
                if (RELU) { v0 = fmaxf(v0, 0.f); v1 = fmaxf(v1, 0.f); }
                size_t base = (size_t)row * N + col;
                if (RES) {
                    float2 rr = *(const float2*)(res + base);
                    v0 += rr.x; v1 += rr.y;
                }
                if (OUTBF16) {
                    *(uint32_t*)(Ch + base) = pk2(v0, v1);
                    *(uint32_t*)(Cl + base) = pk2(bfres(v0), bfres(v1));
                } else {
                    *(float2*)(Cf + base) = make_float2(v0, v1);
                }
            }
        }
    }
}

// ---------------- Flash attention (fp32, online softmax) --------------------
__global__ __launch_bounds__(256, 4) void attention_kernel(
    const float* __restrict__ qbuf, const float* __restrict__ kbuf,
    const float* __restrict__ vbuf, const int* __restrict__ mask,
    bf16* __restrict__ oh, bf16* __restrict__ ol)
{
    __shared__ float Qs[DKH][64];
    __shared__ float KP[DKH * 64];
    __shared__ float Vs[64][DKH];

    int tid = threadIdx.x;
    int bh = blockIdx.y;
    int b = bh >> 4;
    int h = bh & 15;
    int q0 = blockIdx.x * 64;
    int tx = tid & 15;
    int ty = tid >> 4;
    int lr = tid >> 2;
    int lseg = (tid & 3) * 16;

    size_t headoff = (size_t)h * DKH;
    const float* qsrc = qbuf + ((size_t)(b * S_ + q0 + lr)) * D_ + headoff + lseg;
    #pragma unroll
    for (int i = 0; i < 4; i++) {
        float4 xv = *(const float4*)(qsrc + i * 4);
        int kb = lseg + i * 4;
        Qs[kb+0][lr] = xv.x * 0.125f;
        Qs[kb+1][lr] = xv.y * 0.125f;
        Qs[kb+2][lr] = xv.z * 0.125f;
        Qs[kb+3][lr] = xv.w * 0.125f;
    }

    float m[4], l[4], acc[4][4];
    #pragma unroll
    for (int i = 0; i < 4; i++) {
        m[i] = -1e30f; l[i] = 0.f;
        #pragma unroll
        for (int j = 0; j < 4; j++) acc[i][j] = 0.f;
    }

    const float* kbase = kbuf + (size_t)b * S_ * D_ + headoff;
    const float* vbase = vbuf + (size_t)b * S_ * D_ + headoff;
    const int* mrow = mask + (size_t)b * S_;

    for (int c0 = 0; c0 < S_; c0 += 64) {
        __syncthreads();
        {
            const float* ks = kbase + (size_t)(c0 + lr) * D_ + lseg;
            const float* vs = vbase + (size_t)(c0 + lr) * D_ + lseg;
            #pragma unroll
            for (int i = 0; i < 4; i++) {
                float4 kv = *(const float4*)(ks + i * 4);
                int kb = lseg + i * 4;
                KP[(kb+0)*64 + lr] = kv.x;
                KP[(kb+1)*64 + lr] = kv.y;
                KP[(kb+2)*64 + lr] = kv.z;
                KP[(kb+3)*64 + lr] = kv.w;
                *(float4*)&Vs[lr][lseg + i * 4] = *(const float4*)(vs + i * 4);
            }
        }
        int4 mv = *(const int4*)(mrow + c0 + tx * 4);
        __syncthreads();

        float s[4][4];
        #pragma unroll
        for (int i = 0; i < 4; i++)
            #pragma unroll
            for (int j = 0; j < 4; j++) s[i][j] = 0.f;

        #pragma unroll 8
        for (int kk = 0; kk < DKH; ++kk) {
            float4 a = *(const float4*)&Qs[kk][ty * 4];
            float4 bq = *(const float4*)&KP[kk * 64 + tx * 4];
            float av[4] = {a.x, a.y, a.z, a.w};
            float bv[4] = {bq.x, bq.y, bq.z, bq.w};
            #pragma unroll
            for (int i = 0; i < 4; i++)
                #pragma unroll
                for (int j = 0; j < 4; j++)
                    s[i][j] = fmaf(av[i], bv[j], s[i][j]);
        }
        #pragma unroll
        for (int i = 0; i < 4; i++) {
            if (mv.x == 0) s[i][0] = -1e9f;
            if (mv.y == 0) s[i][1] = -1e9f;
            if (mv.z == 0) s[i][2] = -1e9f;
            if (mv.w == 0) s[i][3] = -1e9f;
        }
        float sc[4];
        #pragma unroll
        for (int i = 0; i < 4; i++) {
            float cm = fmaxf(fmaxf(s[i][0], s[i][1]), fmaxf(s[i][2], s[i][3]));
            #pragma unroll
            for (int o = 1; o < 16; o <<= 1)
                cm = fmaxf(cm, __shfl_xor_sync(0xffffffffu, cm, o));
            float mn = fmaxf(m[i], cm);
            sc[i] = __expf(m[i] - mn);
            m[i] = mn;
            float rs = 0.f;
            #pragma unroll
            for (int j = 0; j < 4; j++) {
                s[i][j] = __expf(s[i][j] - mn);
                rs += s[i][j];
            }
            #pragma unroll
            for (int o = 1; o < 16; o <<= 1)
                rs += __shfl_xor_sync(0xffffffffu, rs, o);
            l[i] = l[i] * sc[i] + rs;
            #pragma unroll
            for (int j = 0; j < 4; j++) acc[i][j] *= sc[i];
        }
        __syncthreads();
        #pragma unroll
        for (int i = 0; i < 4; i++) {
            int rr = ty * 4 + i;
            #pragma unroll
            for (int j = 0; j < 4; j++) {
                int c = tx * 4 + j;
                KP[c * 64 + (rr ^ (c & 31))] = s[i][j];
            }
        }
        __syncthreads();
        #pragma unroll 8
        for (int kk = 0; kk < 64; ++kk) {
            float4 vv = *(const float4*)&Vs[kk][tx * 4];
            float vvv[4] = {vv.x, vv.y, vv.z, vv.w};
            #pragma unroll
            for (int i = 0; i < 4; i++) {
                float pr = KP[kk * 64 + ((ty * 4 + i) ^ (kk & 31))];
                #pragma unroll
                for (int j = 0; j < 4; j++)
                    acc[i][j] = fmaf(pr, vvv[j], acc[i][j]);
            }
        }
    }

    #pragma unroll
    for (int i = 0; i < 4; i++) {
        float inv = 1.f / l[i];
        int rq = q0 + ty * 4 + i;
        float o0 = acc[i][0]*inv, o1 = acc[i][1]*inv, o2 = acc[i][2]*inv, o3 = acc[i][3]*inv;
        size_t idx = ((size_t)(b * S_ + rq)) * D_ + headoff + tx * 4;
        *(uint2*)(oh + idx) = make_uint2(pk2(o0, o1), pk2(o2, o3));
        *(uint2*)(ol + idx) = make_uint2(pk2(bfres(o0), bfres(o1)), pk2(bfres(o2), bfres(o3)));
    }
}

// ---------------- launch ----------------------------------------------------
extern "C" void kernel_launch(void* const* d_in, const int* in_sizes, int n_in,
                              void* d_out, int out_size)
{
    (void)in_sizes; (void)n_in; (void)out_size;
    const float* x    = (const float*)d_in[0];
    const int*   mask = (const int*)  d_in[1];
    const float* wq   = (const float*)d_in[2];
    const float* wk   = (const float*)d_in[3];
    const float* wv   = (const float*)d_in[4];
    const float* wo   = (const float*)d_in[5];
    const float* w1   = (const float*)d_in[6];
    const float* b1   = (const float*)d_in[7];
    const float* w2   = (const float*)d_in[8];
    const float* b2   = (const float*)d_in[9];
    const float* g1   = (const float*)d_in[10];
    const float* be1  = (const float*)d_in[11];
    const float* g2   = (const float*)d_in[12];
    const float* be2  = (const float*)d_in[13];
    float* out = (float*)d_out;

    float *q, *k, *v, *h1;
    bf16 *zh, *zl, *ah, *al, *mh, *ml;
    bf16 *wqh,*wql,*wkh,*wkl,*wvh,*wvl,*woh,*wol,*w1h,*w1l,*w2h,*w2l;
    cudaGetSymbolAddress((void**)&q,  g_q);
    cudaGetSymbolAddress((void**)&k,  g_k);
    cudaGetSymbolAddress((void**)&v,  g_v);
    cudaGetSymbolAddress((void**)&h1, g_h1);
    cudaGetSymbolAddress((void**)&zh, g_zh);  cudaGetSymbolAddress((void**)&zl, g_zl);
    cudaGetSymbolAddress((void**)&ah, g_ah);  cudaGetSymbolAddress((void**)&al, g_al);
    cudaGetSymbolAddress((void**)&mh, g_mh);  cudaGetSymbolAddress((void**)&ml, g_ml);
    cudaGetSymbolAddress((void**)&wqh, g_wqh); cudaGetSymbolAddress((void**)&wql, g_wql);
    cudaGetSymbolAddress((void**)&wkh, g_wkh); cudaGetSymbolAddress((void**)&wkl, g_wkl);
    cudaGetSymbolAddress((void**)&wvh, g_wvh); cudaGetSymbolAddress((void**)&wvl, g_wvl);
    cudaGetSymbolAddress((void**)&woh, g_woh); cudaGetSymbolAddress((void**)&wol, g_wol);
    cudaGetSymbolAddress((void**)&w1h, g_w1h); cudaGetSymbolAddress((void**)&w1l, g_w1l);
    cudaGetSymbolAddress((void**)&w2h, g_w2h); cudaGetSymbolAddress((void**)&w2l, g_w2l);

    cudaFuncSetAttribute(tc_gemm<false,false,false,false>, cudaFuncAttributeMaxDynamicSharedMemorySize, SMEM_GEMM);
    cudaFuncSetAttribute(tc_gemm<false,false,true ,false>, cudaFuncAttributeMaxDynamicSharedMemorySize, SMEM_GEMM);
    cudaFuncSetAttribute(tc_gemm<true ,true ,false,true >, cudaFuncAttributeMaxDynamicSharedMemorySize, SMEM_GEMM);
    cudaFuncSetAttribute(tc_gemm<false,true ,true ,false>, cudaFuncAttributeMaxDynamicSharedMemorySize, SMEM_GEMM);

    // weight conversions
    int nW = D_ * D_ / 4;
    convert_hilo<<<(nW + 255)/256, 256>>>(wq, wqh, wql, nW);
    convert_hilo<<<(nW + 255)/256, 256>>>(wk, wkh, wkl, nW);
    convert_hilo<<<(nW + 255)/256, 256>>>(wv, wvh, wvl, nW);
    convert_hilo<<<(nW + 255)/256, 256>>>(wo, woh, wol, nW);
    int nF = DFF_ * D_ / 4;
    convert_hilo<<<(nF + 255)/256, 256>>>(w1, w1h, w1l, nF);
    convert_hilo<<<(nF + 255)/256, 256>>>(w2, w2h, w2l, nF);

    // LN1
    layernorm_kernel<<<NT, 256>>>(x, g1, be1, zh, zl);

    // QKV
    dim3 gP(D_ / 128, NT / 128);
    tc_gemm<false,false,false,false><<<gP, 256, SMEM_GEMM>>>(zh, zl, wqh, wql, nullptr, nullptr, q, nullptr, nullptr, NT, D_, D_);
    tc_gemm<false,false,false,false><<<gP, 256, SMEM_GEMM>>>(zh, zl, wkh, wkl, nullptr, nullptr, k, nullptr, nullptr, NT, D_, D_);
    tc_gemm<false,false,false,false><<<gP, 256, SMEM_GEMM>>>(zh, zl, wvh, wvl, nullptr, nullptr, v, nullptr, nullptr, NT, D_, D_);

    // attention -> bf16 hi/lo
    dim3 gAtt(S_ / 64, B_ * H_);
    attention_kernel<<<gAtt, 256>>>(q, k, v, mask, ah, al);

    // h1 = x + attn @ wo^T
    tc_gemm<false,false,true,false><<<gP, 256, SMEM_GEMM>>>(ah, al, woh, wol, nullptr, x, h1, nullptr, nullptr, NT, D_, D_);

    // LN2
    layernorm_kernel<<<NT, 256>>>(h1, g2, be2, zh, zl);

    // FFN1: mid = relu(z @ w1^T + b1) -> bf16 hi/lo
    dim3 gF1(DFF_ / 128, NT / 128);
    tc_gemm<true,true,false,true><<<gF1, 256, SMEM_GEMM>>>(zh, zl, w1h, w1l, b1, nullptr, nullptr, mh, ml, NT, DFF_, D_);

    // FFN2: out = h1 + mid @ w2^T + b2
    dim3 gF2(D_ / 128, NT / 128);
    tc_gemm<false,true,true,false><<<gF2, 256, SMEM_GEMM>>>(mh, ml, w2h, w2l, b2, h1, out, nullptr, nullptr, NT, D_, DFF_);
}

// round 4
// speedup vs baseline: 2.8125x; 1.7662x over previous
#include <cuda_runtime.h>
#include <cuda_bf16.h>
#include <math.h>
#include <stdint.h>

// Problem dims
#define B_  4
#define S_  2048
#define D_  1024
#define H_  16
#define DKH 64
#define DFF_ 4096
#define NT  (B_ * S_)   // 8192 tokens

typedef __nv_bfloat16 bf16;

// ====================== PTX helpers (baseline ISA, sm_80+) ==================
__device__ __forceinline__ uint32_t smem_to_u32(const void* p) {
    uint32_t a;
    asm("{ .reg .u64 t; cvta.to.shared.u64 t, %1; cvt.u32.u64 %0, t; }" : "=r"(a) : "l"(p));
    return a;
}
__device__ __forceinline__ void cp16(uint32_t dst, const void* src) {
    asm volatile("cp.async.cg.shared.global [%0], [%1], 16;" :: "r"(dst), "l"(src));
}
#define CP_COMMIT() asm volatile("cp.async.commit_group;" ::: "memory")
#define CP_WAIT2()  asm volatile("cp.async.wait_group 2;" ::: "memory")

__device__ __forceinline__ void ldm4(uint32_t* r, uint32_t addr) {
    asm volatile("ldmatrix.sync.aligned.m8n8.x4.shared.b16 {%0,%1,%2,%3}, [%4];"
        : "=r"(r[0]), "=r"(r[1]), "=r"(r[2]), "=r"(r[3]) : "r"(addr));
}
__device__ __forceinline__ void ldm4t(uint32_t* r, uint32_t addr) {
    asm volatile("ldmatrix.sync.aligned.m8n8.x4.trans.shared.b16 {%0,%1,%2,%3}, [%4];"
        : "=r"(r[0]), "=r"(r[1]), "=r"(r[2]), "=r"(r[3]) : "r"(addr));
}
__device__ __forceinline__ void mma_bf16(float* d, const uint32_t* a,
                                         uint32_t b0, uint32_t b1) {
    asm volatile(
        "mma.sync.aligned.m16n8k16.row.col.f32.bf16.bf16.f32 "
        "{%0,%1,%2,%3}, {%4,%5,%6,%7}, {%8,%9}, {%0,%1,%2,%3};"
        : "+f"(d[0]), "+f"(d[1]), "+f"(d[2]), "+f"(d[3])
        : "r"(a[0]), "r"(a[1]), "r"(a[2]), "r"(a[3]), "r"(b0), "r"(b1));
}

// ============ bf16 hi/lo split helpers ======================================
__device__ __forceinline__ uint32_t pk2(float a, float b) {
    return (uint32_t)__bfloat16_as_ushort(__float2bfloat16(a)) |
           ((uint32_t)__bfloat16_as_ushort(__float2bfloat16(b)) << 16);
}
__device__ __forceinline__ float bfres(float a) {
    return a - __bfloat162float(__float2bfloat16(a));
}

// ---------------- scratch (device globals) ----------------------------------
__device__ __align__(256) float g_h1[(size_t)NT * D_];
__device__ __align__(256) bf16 g_zh[(size_t)NT * D_],  g_zl[(size_t)NT * D_];
__device__ __align__(256) bf16 g_qh[(size_t)NT * D_],  g_ql[(size_t)NT * D_];
__device__ __align__(256) bf16 g_kh[(size_t)NT * D_],  g_kl[(size_t)NT * D_];
__device__ __align__(256) bf16 g_vh[(size_t)NT * D_],  g_vl[(size_t)NT * D_];
__device__ __align__(256) bf16 g_ah[(size_t)NT * D_],  g_al[(size_t)NT * D_];
__device__ __align__(256) bf16 g_mh[(size_t)NT * DFF_], g_ml[(size_t)NT * DFF_];
__device__ __align__(256) bf16 g_wqh[(size_t)D_*D_], g_wql[(size_t)D_*D_];
__device__ __align__(256) bf16 g_wkh[(size_t)D_*D_], g_wkl[(size_t)D_*D_];
__device__ __align__(256) bf16 g_wvh[(size_t)D_*D_], g_wvl[(size_t)D_*D_];
__device__ __align__(256) bf16 g_woh[(size_t)D_*D_], g_wol[(size_t)D_*D_];
__device__ __align__(256) bf16 g_w1h[(size_t)DFF_*D_], g_w1l[(size_t)DFF_*D_];
__device__ __align__(256) bf16 g_w2h[(size_t)D_*DFF_], g_w2l[(size_t)D_*DFF_];

// ---------------- fp32 -> bf16 hi/lo convert --------------------------------
__global__ __launch_bounds__(256) void convert_hilo(
    const float* __restrict__ src, bf16* __restrict__ hi, bf16* __restrict__ lo, int n4)
{
    int i = blockIdx.x * 256 + threadIdx.x;
    if (i >= n4) return;
    float4 v = ((const float4*)src)[i];
    ((uint2*)hi)[i] = make_uint2(pk2(v.x, v.y), pk2(v.z, v.w));
    ((uint2*)lo)[i] = make_uint2(pk2(bfres(v.x), bfres(v.y)), pk2(bfres(v.z), bfres(v.w)));
}

// ---------------- LayerNorm (Bessel ddof=1, eps=1e-9) -> bf16 hi/lo ---------
__global__ __launch_bounds__(256) void layernorm_kernel(
    const float* __restrict__ x, const float* __restrict__ gamma,
    const float* __restrict__ beta, bf16* __restrict__ yh, bf16* __restrict__ yl)
{
    int row = blockIdx.x;
    int t = threadIdx.x;
    const float4* xr = (const float4*)(x + (size_t)row * D_);
    float4 v = xr[t];
    float s  = v.x + v.y + v.z + v.w;
    float ss = v.x*v.x + v.y*v.y + v.z*v.z + v.w*v.w;
    #pragma unroll
    for (int o = 16; o > 0; o >>= 1) {
        s  += __shfl_xor_sync(0xffffffffu, s,  o);
        ss += __shfl_xor_sync(0xffffffffu, ss, o);
    }
    __shared__ float shs[8], shq[8];
    int w = t >> 5, l = t & 31;
    if (l == 0) { shs[w] = s; shq[w] = ss; }
    __syncthreads();
    float S = 0.f, Q = 0.f;
    #pragma unroll
    for (int i = 0; i < 8; i++) { S += shs[i]; Q += shq[i]; }
    float mean = S * (1.f / (float)D_);
    float var  = (Q - (float)D_ * mean * mean) * (1.f / (float)(D_ - 1));
    float inv  = rsqrtf(var + 1e-9f);
    const float4 g  = ((const float4*)gamma)[t];
    const float4 be = ((const float4*)beta)[t];
    float o0 = g.x * (v.x - mean) * inv + be.x;
    float o1 = g.y * (v.y - mean) * inv + be.y;
    float o2 = g.z * (v.z - mean) * inv + be.z;
    float o3 = g.w * (v.w - mean) * inv + be.w;
    size_t idx = (size_t)row * (D_/4) + t;
    ((uint2*)yh)[idx] = make_uint2(pk2(o0, o1), pk2(o2, o3));
    ((uint2*)yl)[idx] = make_uint2(pk2(bfres(o0), bfres(o1)), pk2(bfres(o2), bfres(o3)));
}

// ---------------- mma.sync bf16-split GEMM ----------------------------------
#define ROWB 80
#define MAT_BYTES (128 * ROWB)          // 10240
#define STAGE_BYTES (4 * MAT_BYTES)     // 40960: Ah | Al | Bh | Bl
#define SMEM_GEMM (3 * STAGE_BYTES)     // 122880

template<bool RELU, bool BIAS, bool RES, bool OUTBF16>
__global__ __launch_bounds__(256, 1) void tc_gemm(
    const bf16* __restrict__ Ah, const bf16* __restrict__ Al,
    const bf16* __restrict__ Bh, const bf16* __restrict__ Bl,
    const float* __restrict__ bias, const float* __restrict__ res,
    float* __restrict__ Cf, bf16* __restrict__ Ch, bf16* __restrict__ Cl,
    int M, int N, int K)
{
    extern __shared__ char smem[];
    uint32_t sb = smem_to_u32(smem);
    int tid = threadIdx.x;
    int lane = tid & 31, wid = tid >> 5;
    int wm = wid & 1, wn = wid >> 1;
    int row0 = blockIdx.y * 128, col0 = blockIdx.x * 128;

    int lm = tid >> 1;
    int lc = (tid & 1) * 2;
    const bf16* aHs = Ah + (size_t)(row0 + lm) * K + lc * 8;
    const bf16* aLs = Al + (size_t)(row0 + lm) * K + lc * 8;
    const bf16* bHs = Bh + (size_t)(col0 + lm) * K + lc * 8;
    const bf16* bLs = Bl + (size_t)(col0 + lm) * K + lc * 8;
    uint32_t dA = (uint32_t)(lm * ROWB + lc * 16);

    auto load_stage = [&](int p, int kt) {
        uint32_t s0 = sb + p * STAGE_BYTES;
        size_t ko = (size_t)kt * 32;
        cp16(s0 + dA,                    aHs + ko);
        cp16(s0 + dA + 16,               aHs + ko + 8);
        cp16(s0 + MAT_BYTES + dA,        aLs + ko);
        cp16(s0 + MAT_BYTES + dA + 16,   aLs + ko + 8);
        cp16(s0 + 2*MAT_BYTES + dA,      bHs + ko);
        cp16(s0 + 2*MAT_BYTES + dA + 16, bHs + ko + 8);
        cp16(s0 + 3*MAT_BYTES + dA,      bLs + ko);
        cp16(s0 + 3*MAT_BYTES + dA + 16, bLs + ko + 8);
    };

    int g = lane >> 3, r = lane & 7;
    uint32_t aoff = (uint32_t)((wm * 64 + (g & 1) * 8 + r) * ROWB + (g >> 1) * 16);
    uint32_t boff = (uint32_t)((wn * 32 + (g >> 1) * 8 + r) * ROWB + (g & 1) * 16);

    float acc[4][4][4];
    #pragma unroll
    for (int i = 0; i < 4; i++)
        #pragma unroll
        for (int j = 0; j < 4; j++)
            #pragma unroll
            for (int e = 0; e < 4; e++) acc[i][j][e] = 0.f;

    int KT = K / 32;
    load_stage(0, 0); CP_COMMIT();
    load_stage(1, 1); CP_COMMIT();
    load_stage(2, 2); CP_COMMIT();

    for (int kt = 0; kt < KT; kt++) {
        int s = kt % 3;
        CP_WAIT2();
        __syncthreads();
        uint32_t st = sb + s * STAGE_BYTES;
        #pragma unroll
        for (int h = 0; h < 2; h++) {
            uint32_t ah[4][4], al[4][4], bh[2][4], bl[2][4];
            #pragma unroll
            for (int mt = 0; mt < 4; mt++) {
                ldm4(ah[mt], st + aoff + mt * (16 * ROWB) + h * 32);
                ldm4(al[mt], st + MAT_BYTES + aoff + mt * (16 * ROWB) + h * 32);
            }
            #pragma unroll
            for (int nb = 0; nb < 2; nb++) {
                ldm4(bh[nb], st + 2*MAT_BYTES + boff + nb * (16 * ROWB) + h * 32);
                ldm4(bl[nb], st + 3*MAT_BYTES + boff + nb * (16 * ROWB) + h * 32);
            }
            #pragma unroll
            for (int mt = 0; mt < 4; mt++) {
                #pragma unroll
                for (int nt = 0; nt < 4; nt++) {
                    uint32_t b0h = bh[nt >> 1][(nt & 1) * 2];
                    uint32_t b1h = bh[nt >> 1][(nt & 1) * 2 + 1];
                    uint32_t b0l = bl[nt >> 1][(nt & 1) * 2];
                    uint32_t b1l = bl[nt >> 1][(nt & 1) * 2 + 1];
                    mma_bf16(acc[mt][nt], ah[mt], b0h, b1h);
                    mma_bf16(acc[mt][nt], ah[mt], b0l, b1l);
                    mma_bf16(acc[mt][nt], al[mt], b0h, b1h);
                }
            }
        }
        __syncthreads();
        if (kt + 3 < KT) load_stage(s, kt + 3);
        CP_COMMIT();
    }

    // epilogue
    #pragma unroll
    for (int mt = 0; mt < 4; mt++) {
        int r_lo = row0 + wm * 64 + mt * 16 + (lane >> 2);
        #pragma unroll
        for (int nt = 0; nt < 4; nt++) {
            int col = col0 + wn * 32 + nt * 8 + (lane & 3) * 2;
            float* d = acc[mt][nt];
            float bi0 = 0.f, bi1 = 0.f;
            if (BIAS) { bi0 = __ldg(bias + col); bi1 = __ldg(bias + col + 1); }
            #pragma unroll
            for (int half = 0; half < 2; half++) {
                int row = r_lo + half * 8;
                float v0 = d[half * 2 + 0], v1 = d[half * 2 + 1];
                if (BIAS) { v0 += bi0; v1 += bi1; }
                if (RELU) { v0 = fmaxf(v0, 0.f); v1 = fmaxf(v1, 0.f); }
                size_t base = (size_t)row * N + col;
                if (RES) {
                    float2 rr = *(const float2*)(res + base);
                    v0 += rr.x; v1 += rr.y;
                }
                if (OUTBF16) {
                    *(uint32_t*)(Ch + base) = pk2(v0, v1);
                    *(uint32_t*)(Cl + base) = pk2(bfres(v0), bfres(v1));
                } else {
                    *(float2*)(Cf + base) = make_float2(v0, v1);
                }
            }
        }
    }
}

// ---------------- Tensor-core flash attention -------------------------------
// CTA: 128 q-rows x one head. 8 warps x 16 rows. 64-key chunks, double buffer.
// Smem per stage: Khi(9216) Klo(9216) V(9216) mask(256) -> 27904.
#define AROWB 144
#define A_KL  9216
#define A_V   18432
#define A_M   27648
#define A_STRIDE 27904
#define A_SMEM (2 * A_STRIDE)   // 55808

__global__ __launch_bounds__(256, 1) void attention_tc(
    const bf16* __restrict__ qh, const bf16* __restrict__ ql,
    const bf16* __restrict__ kh, const bf16* __restrict__ kl,
    const bf16* __restrict__ vh, const int* __restrict__ mask,
    bf16* __restrict__ oh, bf16* __restrict__ ol)
{
    extern __shared__ char smem[];
    uint32_t sb = smem_to_u32(smem);
    int tid = threadIdx.x, lane = tid & 31, w = tid >> 5;
    int bh_ = blockIdx.y, b = bh_ >> 4, h = bh_ & 15;
    int q0 = blockIdx.x * 128;
    size_t hoff = (size_t)h * DKH;
    int g = lane >> 3, r = lane & 7;

    // ---- stage Q: hi -> buf0 region, lo -> buf1 region ----
    {
        int lm = tid >> 1;
        int lc = (tid & 1) * 4;
        size_t go = (size_t)(b * S_ + q0 + lm) * D_ + hoff + lc * 8;
        uint32_t d0 = sb + (uint32_t)(lm * AROWB + lc * 16);
        #pragma unroll
        for (int j = 0; j < 4; j++) {
            cp16(d0 + j * 16, qh + go + j * 8);
            cp16(d0 + A_STRIDE + j * 16, ql + go + j * 8);
        }
        CP_COMMIT();
    }
    asm volatile("cp.async.wait_group 0;" ::: "memory");
    __syncthreads();

    uint32_t Qh4[4][4], Ql4[4][4];
    {
        uint32_t aoff = sb + (uint32_t)((w * 16 + (g & 1) * 8 + r) * AROWB + (g >> 1) * 16);
        #pragma unroll
        for (int ks = 0; ks < 4; ks++) {
            ldm4(Qh4[ks], aoff + ks * 32);
            ldm4(Ql4[ks], aoff + A_STRIDE + ks * 32);
        }
    }
    __syncthreads();

    float m0 = -1e30f, m1 = -1e30f, l0 = 0.f, l1 = 0.f;
    float acc[8][4];
    #pragma unroll
    for (int i = 0; i < 8; i++)
        #pragma unroll
        for (int e = 0; e < 4; e++) acc[i][e] = 0.f;

    const bf16* kbh = kh + (size_t)b * S_ * D_ + hoff;
    const bf16* kbl = kl + (size_t)b * S_ * D_ + hoff;
    const bf16* vb  = vh + (size_t)b * S_ * D_ + hoff;
    const int* mrow = mask + (size_t)b * S_;

    auto load_chunk = [&](int c) {
        uint32_t stg = sb + (c & 1) * A_STRIDE;
        int lm = tid >> 2;
        int lc = (tid & 3) * 2;
        size_t go = (size_t)(c * 64 + lm) * D_ + lc * 8;
        uint32_t d = stg + (uint32_t)(lm * AROWB + lc * 16);
        cp16(d,             kbh + go);
        cp16(d + 16,        kbh + go + 8);
        cp16(d + A_KL,      kbl + go);
        cp16(d + A_KL + 16, kbl + go + 8);
        cp16(d + A_V,       vb + go);
        cp16(d + A_V + 16,  vb + go + 8);
        if (tid < 64)
            asm volatile("cp.async.ca.shared.global [%0], [%1], 4;"
                :: "r"(stg + A_M + tid * 4), "l"(mrow + c * 64 + tid));
    };

    const int NC = S_ / 64;   // 32
    load_chunk(0); CP_COMMIT();
    load_chunk(1); CP_COMMIT();

    uint32_t bKoff = (uint32_t)(((g >> 1) * 8 + r) * AROWB + (g & 1) * 16);
    uint32_t vOff  = (uint32_t)(((g & 1) * 8 + r) * AROWB + (g >> 1) * 16);

    for (int c = 0; c < NC; c++) {
        if (c + 1 < NC) { asm volatile("cp.async.wait_group 1;" ::: "memory"); }
        else            { asm volatile("cp.async.wait_group 0;" ::: "memory"); }
        __syncthreads();
        uint32_t stg = sb + (c & 1) * A_STRIDE;

        float s[8][4];
        #pragma unroll
        for (int i = 0; i < 8; i++)
            #pragma unroll
            for (int e = 0; e < 4; e++) s[i][e] = 0.f;

        // S = Q K^T  (3-term hi/lo split)
        #pragma unroll
        for (int ks = 0; ks < 4; ks++) {
            #pragma unroll
            for (int nb = 0; nb < 4; nb++) {
                uint32_t bh4[4], bl4[4];
                ldm4(bh4, stg + bKoff + nb * (16 * AROWB) + ks * 32);
                ldm4(bl4, stg + A_KL + bKoff + nb * (16 * AROWB) + ks * 32);
                mma_bf16(s[nb*2],   Qh4[ks], bh4[0], bh4[1]);
                mma_bf16(s[nb*2],   Qh4[ks], bl4[0], bl4[1]);
                mma_bf16(s[nb*2],   Ql4[ks], bh4[0], bh4[1]);
                mma_bf16(s[nb*2+1], Qh4[ks], bh4[2], bh4[3]);
                mma_bf16(s[nb*2+1], Qh4[ks], bl4[2], bl4[3]);
                mma_bf16(s[nb*2+1], Ql4[ks], bh4[2], bh4[3]);
            }
        }

        // scale + mask
        const int* ms = (const int*)(smem + (size_t)(c & 1) * A_STRIDE + A_M);
        #pragma unroll
        for (int nt = 0; nt < 8; nt++) {
            int cc = nt * 8 + (lane & 3) * 2;
            int mv0 = ms[cc], mv1 = ms[cc + 1];
            #pragma unroll
            for (int e = 0; e < 4; e++) s[nt][e] *= 0.125f;
            if (mv0 == 0) { s[nt][0] = -1e9f; s[nt][2] = -1e9f; }
            if (mv1 == 0) { s[nt][1] = -1e9f; s[nt][3] = -1e9f; }
        }

        // online softmax (rows r and r+8 per thread)
        float mx0 = -1e30f, mx1 = -1e30f;
        #pragma unroll
        for (int nt = 0; nt < 8; nt++) {
            mx0 = fmaxf(mx0, fmaxf(s[nt][0], s[nt][1]));
            mx1 = fmaxf(mx1, fmaxf(s[nt][2], s[nt][3]));
        }
        mx0 = fmaxf(mx0, __shfl_xor_sync(0xffffffffu, mx0, 1));
        mx0 = fmaxf(mx0, __shfl_xor_sync(0xffffffffu, mx0, 2));
        mx1 = fmaxf(mx1, __shfl_xor_sync(0xffffffffu, mx1, 1));
        mx1 = fmaxf(mx1, __shfl_xor_sync(0xffffffffu, mx1, 2));
        float mn0 = fmaxf(m0, mx0), mn1 = fmaxf(m1, mx1);
        float sc0 = __expf(m0 - mn0), sc1 = __expf(m1 - mn1);
        m0 = mn0; m1 = mn1;
        float rs0 = 0.f, rs1 = 0.f;
        #pragma unroll
        for (int nt = 0; nt < 8; nt++) {
            s[nt][0] = __expf(s[nt][0] - mn0); rs0 += s[nt][0];
            s[nt][1] = __expf(s[nt][1] - mn0); rs0 += s[nt][1];
            s[nt][2] = __expf(s[nt][2] - mn1); rs1 += s[nt][2];
            s[nt][3] = __expf(s[nt][3] - mn1); rs1 += s[nt][3];
        }
        rs0 += __shfl_xor_sync(0xffffffffu, rs0, 1);
        rs0 += __shfl_xor_sync(0xffffffffu, rs0, 2);
        rs1 += __shfl_xor_sync(0xffffffffu, rs1, 1);
        rs1 += __shfl_xor_sync(0xffffffffu, rs1, 2);
        l0 = l0 * sc0 + rs0;
        l1 = l1 * sc1 + rs1;
        #pragma unroll
        for (int no = 0; no < 8; no++) {
            acc[no][0] *= sc0; acc[no][1] *= sc0;
            acc[no][2] *= sc1; acc[no][3] *= sc1;
        }

        // O += P V   (P fragments repacked directly as A operand)
        #pragma unroll
        for (int kb = 0; kb < 4; kb++) {
            uint32_t a4[4];
            a4[0] = pk2(s[kb*2][0],   s[kb*2][1]);
            a4[1] = pk2(s[kb*2][2],   s[kb*2][3]);
            a4[2] = pk2(s[kb*2+1][0], s[kb*2+1][1]);
            a4[3] = pk2(s[kb*2+1][2], s[kb*2+1][3]);
            #pragma unroll
            for (int db = 0; db < 4; db++) {
                uint32_t bv[4];
                ldm4t(bv, stg + A_V + vOff + kb * (16 * AROWB) + db * 32);
                mma_bf16(acc[db*2],   a4, bv[0], bv[1]);
                mma_bf16(acc[db*2+1], a4, bv[2], bv[3]);
            }
        }

        __syncthreads();
        if (c + 2 < NC) { load_chunk(c + 2); CP_COMMIT(); }
    }

    // ---- output: O / l -> bf16 hi/lo ----
    float inv0 = 1.f / l0, inv1 = 1.f / l1;
    int row0 = q0 + w * 16 + (lane >> 2);
    size_t t0 = (size_t)(b * S_ + row0) * D_ + hoff;
    size_t t1 = t0 + (size_t)8 * D_;
    #pragma unroll
    for (int no = 0; no < 8; no++) {
        int cc = no * 8 + (lane & 3) * 2;
        float o0 = acc[no][0] * inv0, o1 = acc[no][1] * inv0;
        float o2 = acc[no][2] * inv1, o3 = acc[no][3] * inv1;
        *(uint32_t*)(oh + t0 + cc) = pk2(o0, o1);
        *(uint32_t*)(ol + t0 + cc) = pk2(bfres(o0), bfres(o1));
        *(uint32_t*)(oh + t1 + cc) = pk2(o2, o3);
        *(uint32_t*)(ol + t1 + cc) = pk2(bfres(o2), bfres(o3));
    }
}

// ---------------- launch ----------------------------------------------------
extern "C" void kernel_launch(void* const* d_in, const int* in_sizes, int n_in,
                              void* d_out, int out_size)
{
    (void)in_sizes; (void)n_in; (void)out_size;
    const float* x    = (const float*)d_in[0];
    const int*   mask = (const int*)  d_in[1];
    const float* wq   = (const float*)d_in[2];
    const float* wk   = (const float*)d_in[3];
    const float* wv   = (const float*)d_in[4];
    const float* wo   = (const float*)d_in[5];
    const float* w1   = (const float*)d_in[6];
    const float* b1   = (const float*)d_in[7];
    const float* w2   = (const float*)d_in[8];
    const float* b2   = (const float*)d_in[9];
    const float* g1   = (const float*)d_in[10];
    const float* be1  = (const float*)d_in[11];
    const float* g2   = (const float*)d_in[12];
    const float* be2  = (const float*)d_in[13];
    float* out = (float*)d_out;

    float *h1;
    bf16 *zh, *zl, *qhp, *qlp, *khp, *klp, *vhp, *vlp, *ah, *al, *mh, *ml;
    bf16 *wqh,*wql,*wkh,*wkl,*wvh,*wvl,*woh,*wol,*w1h,*w1l,*w2h,*w2l;
    cudaGetSymbolAddress((void**)&h1, g_h1);
    cudaGetSymbolAddress((void**)&zh, g_zh);  cudaGetSymbolAddress((void**)&zl, g_zl);
    cudaGetSymbolAddress((void**)&qhp, g_qh); cudaGetSymbolAddress((void**)&qlp, g_ql);
    cudaGetSymbolAddress((void**)&khp, g_kh); cudaGetSymbolAddress((void**)&klp, g_kl);
    cudaGetSymbolAddress((void**)&vhp, g_vh); cudaGetSymbolAddress((void**)&vlp, g_vl);
    cudaGetSymbolAddress((void**)&ah, g_ah);  cudaGetSymbolAddress((void**)&al, g_al);
    cudaGetSymbolAddress((void**)&mh, g_mh);  cudaGetSymbolAddress((void**)&ml, g_ml);
    cudaGetSymbolAddress((void**)&wqh, g_wqh); cudaGetSymbolAddress((void**)&wql, g_wql);
    cudaGetSymbolAddress((void**)&wkh, g_wkh); cudaGetSymbolAddress((void**)&wkl, g_wkl);
    cudaGetSymbolAddress((void**)&wvh, g_wvh); cudaGetSymbolAddress((void**)&wvl, g_wvl);
    cudaGetSymbolAddress((void**)&woh, g_woh); cudaGetSymbolAddress((void**)&wol, g_wol);
    cudaGetSymbolAddress((void**)&w1h, g_w1h); cudaGetSymbolAddress((void**)&w1l, g_w1l);
    cudaGetSymbolAddress((void**)&w2h, g_w2h); cudaGetSymbolAddress((void**)&w2l, g_w2l);

    cudaFuncSetAttribute(tc_gemm<false,false,false,true >, cudaFuncAttributeMaxDynamicSharedMemorySize, SMEM_GEMM);
    cudaFuncSetAttribute(tc_gemm<false,false,true ,false>, cudaFuncAttributeMaxDynamicSharedMemorySize, SMEM_GEMM);
    cudaFuncSetAttribute(tc_gemm<true ,true ,false,true >, cudaFuncAttributeMaxDynamicSharedMemorySize, SMEM_GEMM);
    cudaFuncSetAttribute(tc_gemm<false,true ,true ,false>, cudaFuncAttributeMaxDynamicSharedMemorySize, SMEM_GEMM);
    cudaFuncSetAttribute(attention_tc, cudaFuncAttributeMaxDynamicSharedMemorySize, A_SMEM);

    // weight conversions
    int nW = D_ * D_ / 4;
    convert_hilo<<<(nW + 255)/256, 256>>>(wq, wqh, wql, nW);
    convert_hilo<<<(nW + 255)/256, 256>>>(wk, wkh, wkl, nW);
    convert_hilo<<<(nW + 255)/256, 256>>>(wv, wvh, wvl, nW);
    convert_hilo<<<(nW + 255)/256, 256>>>(wo, woh, wol, nW);
    int nF = DFF_ * D_ / 4;
    convert_hilo<<<(nF + 255)/256, 256>>>(w1, w1h, w1l, nF);
    convert_hilo<<<(nF + 255)/256, 256>>>(w2, w2h, w2l, nF);

    // LN1
    layernorm_kernel<<<NT, 256>>>(x, g1, be1, zh, zl);

    // QKV (-> bf16 hi/lo)
    dim3 gP(D_ / 128, NT / 128);
    tc_gemm<false,false,false,true><<<gP, 256, SMEM_GEMM>>>(zh, zl, wqh, wql, nullptr, nullptr, nullptr, qhp, qlp, NT, D_, D_);
    tc_gemm<false,false,false,true><<<gP, 256, SMEM_GEMM>>>(zh, zl, wkh, wkl, nullptr, nullptr, nullptr, khp, klp, NT, D_, D_);
    tc_gemm<false,false,false,true><<<gP, 256, SMEM_GEMM>>>(zh, zl, wvh, wvl, nullptr, nullptr, nullptr, vhp, vlp, NT, D_, D_);

    // attention (tensor core) -> bf16 hi/lo
    dim3 gAtt(S_ / 128, B_ * H_);
    attention_tc<<<gAtt, 256, A_SMEM>>>(qhp, qlp, khp, klp, vhp, mask, ah, al);

    // h1 = x + attn @ wo^T
    tc_gemm<false,false,true,false><<<gP, 256, SMEM_GEMM>>>(ah, al, woh, wol, nullptr, x, h1, nullptr, nullptr, NT, D_, D_);

    // LN2
    layernorm_kernel<<<NT, 256>>>(h1, g2, be2, zh, zl);

    // FFN1: mid = relu(z @ w1^T + b1) -> bf16 hi/lo
    dim3 gF1(DFF_ / 128, NT / 128);
    tc_gemm<true,true,false,true><<<gF1, 256, SMEM_GEMM>>>(zh, zl, w1h, w1l, b1, nullptr, nullptr, mh, ml, NT, DFF_, D_);

    // FFN2: out = h1 + mid @ w2^T + b2
    dim3 gF2(D_ / 128, NT / 128);
    tc_gemm<false,true,true,false><<<gF2, 256, SMEM_GEMM>>>(mh, ml, w2h, w2l, b2, h1, out, nullptr, nullptr, NT, D_, DFF_);
}

// round 5
// speedup vs baseline: 3.3346x; 1.1857x over previous
#include <cuda_runtime.h>
#include <cuda_bf16.h>
#include <math.h>
#include <stdint.h>

// Problem dims
#define B_  4
#define S_  2048
#define D_  1024
#define H_  16
#define DKH 64
#define DFF_ 4096
#define NT  (B_ * S_)   // 8192 tokens
#define QKVS 3072       // fused qkv row stride

typedef __nv_bfloat16 bf16;

// ====================== PTX helpers (baseline ISA, sm_80+) ==================
__device__ __forceinline__ uint32_t smem_to_u32(const void* p) {
    uint32_t a;
    asm("{ .reg .u64 t; cvta.to.shared.u64 t, %1; cvt.u32.u64 %0, t; }" : "=r"(a) : "l"(p));
    return a;
}
__device__ __forceinline__ void cp16(uint32_t dst, const void* src) {
    asm volatile("cp.async.cg.shared.global [%0], [%1], 16;" :: "r"(dst), "l"(src));
}
#define CP_COMMIT() asm volatile("cp.async.commit_group;" ::: "memory")

__device__ __forceinline__ void ldm4(uint32_t* r, uint32_t addr) {
    asm volatile("ldmatrix.sync.aligned.m8n8.x4.shared.b16 {%0,%1,%2,%3}, [%4];"
        : "=r"(r[0]), "=r"(r[1]), "=r"(r[2]), "=r"(r[3]) : "r"(addr));
}
__device__ __forceinline__ void ldm4t(uint32_t* r, uint32_t addr) {
    asm volatile("ldmatrix.sync.aligned.m8n8.x4.trans.shared.b16 {%0,%1,%2,%3}, [%4];"
        : "=r"(r[0]), "=r"(r[1]), "=r"(r[2]), "=r"(r[3]) : "r"(addr));
}
__device__ __forceinline__ void mma_bf16(float* d, const uint32_t* a,
                                         uint32_t b0, uint32_t b1) {
    asm volatile(
        "mma.sync.aligned.m16n8k16.row.col.f32.bf16.bf16.f32 "
        "{%0,%1,%2,%3}, {%4,%5,%6,%7}, {%8,%9}, {%0,%1,%2,%3};"
        : "+f"(d[0]), "+f"(d[1]), "+f"(d[2]), "+f"(d[3])
        : "r"(a[0]), "r"(a[1]), "r"(a[2]), "r"(a[3]), "r"(b0), "r"(b1));
}

// ============ bf16 hi/lo split helpers ======================================
__device__ __forceinline__ uint32_t pk2(float a, float b) {
    return (uint32_t)__bfloat16_as_ushort(__float2bfloat16(a)) |
           ((uint32_t)__bfloat16_as_ushort(__float2bfloat16(b)) << 16);
}
__device__ __forceinline__ float bfres(float a) {
    return a - __bfloat162float(__float2bfloat16(a));
}

// ---------------- scratch (device globals) ----------------------------------
__device__ __align__(256) float g_h1[(size_t)NT * D_];
__device__ __align__(256) bf16 g_zh[(size_t)NT * D_],  g_zl[(size_t)NT * D_];
__device__ __align__(256) bf16 g_qkvh[(size_t)NT * QKVS], g_qkvl[(size_t)NT * QKVS];
__device__ __align__(256) bf16 g_ah[(size_t)NT * D_],  g_al[(size_t)NT * D_];
__device__ __align__(256) bf16 g_mh[(size_t)NT * DFF_], g_ml[(size_t)NT * DFF_];
__device__ __align__(256) bf16 g_wch[(size_t)3*D_*D_], g_wcl[(size_t)3*D_*D_];
__device__ __align__(256) bf16 g_woh[(size_t)D_*D_], g_wol[(size_t)D_*D_];
__device__ __align__(256) bf16 g_w1h[(size_t)DFF_*D_], g_w1l[(size_t)DFF_*D_];
__device__ __align__(256) bf16 g_w2h[(size_t)D_*DFF_], g_w2l[(size_t)D_*DFF_];

// ---------------- fp32 -> bf16 hi/lo convert --------------------------------
__global__ __launch_bounds__(256) void convert_hilo(
    const float* __restrict__ src, bf16* __restrict__ hi, bf16* __restrict__ lo, int n4)
{
    int i = blockIdx.x * 256 + threadIdx.x;
    if (i >= n4) return;
    float4 v = ((const float4*)src)[i];
    ((uint2*)hi)[i] = make_uint2(pk2(v.x, v.y), pk2(v.z, v.w));
    ((uint2*)lo)[i] = make_uint2(pk2(bfres(v.x), bfres(v.y)), pk2(bfres(v.z), bfres(v.w)));
}

// ---------------- LayerNorm (Bessel ddof=1, eps=1e-9) -> bf16 hi/lo ---------
__global__ __launch_bounds__(256) void layernorm_kernel(
    const float* __restrict__ x, const float* __restrict__ gamma,
    const float* __restrict__ beta, bf16* __restrict__ yh, bf16* __restrict__ yl)
{
    int row = blockIdx.x;
    int t = threadIdx.x;
    const float4* xr = (const float4*)(x + (size_t)row * D_);
    float4 v = xr[t];
    float s  = v.x + v.y + v.z + v.w;
    float ss = v.x*v.x + v.y*v.y + v.z*v.z + v.w*v.w;
    #pragma unroll
    for (int o = 16; o > 0; o >>= 1) {
        s  += __shfl_xor_sync(0xffffffffu, s,  o);
        ss += __shfl_xor_sync(0xffffffffu, ss, o);
    }
    __shared__ float shs[8], shq[8];
    int w = t >> 5, l = t & 31;
    if (l == 0) { shs[w] = s; shq[w] = ss; }
    __syncthreads();
    float S = 0.f, Q = 0.f;
    #pragma unroll
    for (int i = 0; i < 8; i++) { S += shs[i]; Q += shq[i]; }
    float mean = S * (1.f / (float)D_);
    float var  = (Q - (float)D_ * mean * mean) * (1.f / (float)(D_ - 1));
    float inv  = rsqrtf(var + 1e-9f);
    const float4 g  = ((const float4*)gamma)[t];
    const float4 be = ((const float4*)beta)[t];
    float o0 = g.x * (v.x - mean) * inv + be.x;
    float o1 = g.y * (v.y - mean) * inv + be.y;
    float o2 = g.z * (v.z - mean) * inv + be.z;
    float o3 = g.w * (v.w - mean) * inv + be.w;
    size_t idx = (size_t)row * (D_/4) + t;
    ((uint2*)yh)[idx] = make_uint2(pk2(o0, o1), pk2(o2, o3));
    ((uint2*)yl)[idx] = make_uint2(pk2(bfres(o0), bfres(o1)), pk2(bfres(o2), bfres(o3)));
}

// ---------------- mma.sync bf16-split GEMM ----------------------------------
// 128x128x32 CTA tile, 256 threads (8 warps, 2m x 4n), 2-stage cp.async,
// 2 CTAs/SM. Term-outer MMA ordering (no accumulator RAW chains).
#define ROWB 80
#define MAT_BYTES (128 * ROWB)          // 10240
#define STAGE_BYTES (4 * MAT_BYTES)     // 40960: Ah | Al | Bh | Bl
#define SMEM_GEMM (2 * STAGE_BYTES)     // 81920

template<bool RELU, bool BIAS, bool RES, bool OUTBF16>
__global__ __launch_bounds__(256, 2) void tc_gemm(
    const bf16* __restrict__ Ah, const bf16* __restrict__ Al,
    const bf16* __restrict__ Bh, const bf16* __restrict__ Bl,
    const float* __restrict__ bias, const float* __restrict__ res,
    float* __restrict__ Cf, bf16* __restrict__ Ch, bf16* __restrict__ Cl,
    int M, int N, int K)
{
    extern __shared__ char smem[];
    uint32_t sb = smem_to_u32(smem);
    int tid = threadIdx.x;
    int lane = tid & 31, wid = tid >> 5;
    int wm = wid & 1, wn = wid >> 1;
    int row0 = blockIdx.y * 128, col0 = blockIdx.x * 128;

    int lm = tid >> 1;
    int lc = (tid & 1) * 2;
    const bf16* aHs = Ah + (size_t)(row0 + lm) * K + lc * 8;
    const bf16* aLs = Al + (size_t)(row0 + lm) * K + lc * 8;
    const bf16* bHs = Bh + (size_t)(col0 + lm) * K + lc * 8;
    const bf16* bLs = Bl + (size_t)(col0 + lm) * K + lc * 8;
    uint32_t dA = (uint32_t)(lm * ROWB + lc * 16);

    auto load_stage = [&](int p, int kt) {
        uint32_t s0 = sb + p * STAGE_BYTES;
        size_t ko = (size_t)kt * 32;
        cp16(s0 + dA,                    aHs + ko);
        cp16(s0 + dA + 16,               aHs + ko + 8);
        cp16(s0 + MAT_BYTES + dA,        aLs + ko);
        cp16(s0 + MAT_BYTES + dA + 16,   aLs + ko + 8);
        cp16(s0 + 2*MAT_BYTES + dA,      bHs + ko);
        cp16(s0 + 2*MAT_BYTES + dA + 16, bHs + ko + 8);
        cp16(s0 + 3*MAT_BYTES + dA,      bLs + ko);
        cp16(s0 + 3*MAT_BYTES + dA + 16, bLs + ko + 8);
    };

    int g = lane >> 3, r = lane & 7;
    uint32_t aoff = (uint32_t)((wm * 64 + (g & 1) * 8 + r) * ROWB + (g >> 1) * 16);
    uint32_t boff = (uint32_t)((wn * 32 + (g >> 1) * 8 + r) * ROWB + (g & 1) * 16);

    float acc[4][4][4];
    #pragma unroll
    for (int i = 0; i < 4; i++)
        #pragma unroll
        for (int j = 0; j < 4; j++)
            #pragma unroll
            for (int e = 0; e < 4; e++) acc[i][j][e] = 0.f;

    int KT = K / 32;
    load_stage(0, 0); CP_COMMIT();
    load_stage(1, 1); CP_COMMIT();

    for (int kt = 0; kt < KT; kt++) {
        int s = kt & 1;
        asm volatile("cp.async.wait_group 1;" ::: "memory");
        __syncthreads();
        uint32_t st = sb + s * STAGE_BYTES;
        #pragma unroll
        for (int h = 0; h < 2; h++) {
            uint32_t ah[4][4], bh[2][4];
            #pragma unroll
            for (int mt = 0; mt < 4; mt++)
                ldm4(ah[mt], st + aoff + mt * (16 * ROWB) + h * 32);
            #pragma unroll
            for (int nb = 0; nb < 2; nb++)
                ldm4(bh[nb], st + 2*MAT_BYTES + boff + nb * (16 * ROWB) + h * 32);
            // term hh: 16 independent MMAs
            #pragma unroll
            for (int mt = 0; mt < 4; mt++)
                #pragma unroll
                for (int nt = 0; nt < 4; nt++)
                    mma_bf16(acc[mt][nt], ah[mt],
                             bh[nt >> 1][(nt & 1) * 2], bh[nt >> 1][(nt & 1) * 2 + 1]);
            // term lh
            {
                uint32_t al[4][4];
                #pragma unroll
                for (int mt = 0; mt < 4; mt++)
                    ldm4(al[mt], st + MAT_BYTES + aoff + mt * (16 * ROWB) + h * 32);
                #pragma unroll
                for (int mt = 0; mt < 4; mt++)
                    #pragma unroll
                    for (int nt = 0; nt < 4; nt++)
                        mma_bf16(acc[mt][nt], al[mt],
                                 bh[nt >> 1][(nt & 1) * 2], bh[nt >> 1][(nt & 1) * 2 + 1]);
            }
            // term hl
            {
                uint32_t bl[2][4];
                #pragma unroll
                for (int nb = 0; nb < 2; nb++)
                    ldm4(bl[nb], st + 3*MAT_BYTES + boff + nb * (16 * ROWB) + h * 32);
                #pragma unroll
                for (int mt = 0; mt < 4; mt++)
                    #pragma unroll
                    for (int nt = 0; nt < 4; nt++)
                        mma_bf16(acc[mt][nt], ah[mt],
                                 bl[nt >> 1][(nt & 1) * 2], bl[nt >> 1][(nt & 1) * 2 + 1]);
            }
        }
        __syncthreads();
        if (kt + 2 < KT) load_stage(s, kt + 2);
        CP_COMMIT();
    }

    // epilogue
    #pragma unroll
    for (int mt = 0; mt < 4; mt++) {
        int r_lo = row0 + wm * 64 + mt * 16 + (lane >> 2);
        #pragma unroll
        for (int nt = 0; nt < 4; nt++) {
            int col = col0 + wn * 32 + nt * 8 + (lane & 3) * 2;
            float* d = acc[mt][nt];
            float bi0 = 0.f, bi1 = 0.f;
            if (BIAS) { bi0 = __ldg(bias + col); bi1 = __ldg(bias + col + 1); }
            #pragma unroll
            for (int half = 0; half < 2; half++) {
                int row = r_lo + half * 8;
                float v0 = d[half * 2 + 0], v1 = d[half * 2 + 1];
                if (BIAS) { v0 += bi0; v1 += bi1; }
                if (RELU) { v0 = fmaxf(v0, 0.f); v1 = fmaxf(v1, 0.f); }
                size_t base = (size_t)row * N + col;
                if (RES) {
                    float2 rr = *(const float2*)(res + base);
                    v0 += rr.x; v1 += rr.y;
                }
                if (OUTBF16) {
                    *(uint32_t*)(Ch + base) = pk2(v0, v1);
                    *(uint32_t*)(Cl + base) = pk2(bfres(v0), bfres(v1));
                } else {
                    *(float2*)(Cf + base) = make_float2(v0, v1);
                }
            }
        }
    }
}

// ---------------- Tensor-core flash attention -------------------------------
// CTA: 128 q-rows x one head. 8 warps x 16 rows. 64-key chunks, double buffer,
// 2 CTAs/SM. Q/K/V read from fused qkv buffer (row stride QKVS).
#define AROWB 144
#define A_KL  9216
#define A_V   18432
#define A_M   27648
#define A_STRIDE 27904
#define A_SMEM (2 * A_STRIDE)   // 55808

__global__ __launch_bounds__(256, 2) void attention_tc(
    const bf16* __restrict__ qkvh, const bf16* __restrict__ qkvl,
    const int* __restrict__ mask,
    bf16* __restrict__ oh, bf16* __restrict__ ol)
{
    extern __shared__ char smem[];
    uint32_t sb = smem_to_u32(smem);
    int tid = threadIdx.x, lane = tid & 31, w = tid >> 5;
    int bh_ = blockIdx.y, b = bh_ >> 4, h = bh_ & 15;
    int q0 = blockIdx.x * 128;
    size_t hoff = (size_t)h * DKH;
    int g = lane >> 3, r = lane & 7;

    // ---- stage Q: hi -> buf0 region, lo -> buf1 region ----
    {
        int lm = tid >> 1;
        int lc = (tid & 1) * 4;
        size_t go = (size_t)(b * S_ + q0 + lm) * QKVS + hoff + lc * 8;
        uint32_t d0 = sb + (uint32_t)(lm * AROWB + lc * 16);
        #pragma unroll
        for (int j = 0; j < 4; j++) {
            cp16(d0 + j * 16, qkvh + go + j * 8);
            cp16(d0 + A_STRIDE + j * 16, qkvl + go + j * 8);
        }
        CP_COMMIT();
    }
    asm volatile("cp.async.wait_group 0;" ::: "memory");
    __syncthreads();

    uint32_t Qh4[4][4], Ql4[4][4];
    {
        uint32_t aoff = sb + (uint32_t)((w * 16 + (g & 1) * 8 + r) * AROWB + (g >> 1) * 16);
        #pragma unroll
        for (int ks = 0; ks < 4; ks++) {
            ldm4(Qh4[ks], aoff + ks * 32);
            ldm4(Ql4[ks], aoff + A_STRIDE + ks * 32);
        }
    }
    __syncthreads();

    float m0 = -1e30f, m1 = -1e30f, l0 = 0.f, l1 = 0.f;
    float acc[8][4];
    #pragma unroll
    for (int i = 0; i < 8; i++)
        #pragma unroll
        for (int e = 0; e < 4; e++) acc[i][e] = 0.f;

    const bf16* kbh = qkvh + (size_t)b * S_ * QKVS + D_ + hoff;
    const bf16* kbl = qkvl + (size_t)b * S_ * QKVS + D_ + hoff;
    const bf16* vb  = qkvh + (size_t)b * S_ * QKVS + 2 * D_ + hoff;
    const int* mrow = mask + (size_t)b * S_;

    auto load_chunk = [&](int c) {
        uint32_t stg = sb + (c & 1) * A_STRIDE;
        int lm = tid >> 2;
        int lc = (tid & 3) * 2;
        size_t go = (size_t)(c * 64 + lm) * QKVS + lc * 8;
        uint32_t d = stg + (uint32_t)(lm * AROWB + lc * 16);
        cp16(d,             kbh + go);
        cp16(d + 16,        kbh + go + 8);
        cp16(d + A_KL,      kbl + go);
        cp16(d + A_KL + 16, kbl + go + 8);
        cp16(d + A_V,       vb + go);
        cp16(d + A_V + 16,  vb + go + 8);
        if (tid < 64)
            asm volatile("cp.async.ca.shared.global [%0], [%1], 4;"
                :: "r"(stg + A_M + tid * 4), "l"(mrow + c * 64 + tid));
    };

    const int NC = S_ / 64;   // 32
    load_chunk(0); CP_COMMIT();
    load_chunk(1); CP_COMMIT();

    uint32_t bKoff = (uint32_t)(((g >> 1) * 8 + r) * AROWB + (g & 1) * 16);
    uint32_t vOff  = (uint32_t)(((g & 1) * 8 + r) * AROWB + (g >> 1) * 16);

    for (int c = 0; c < NC; c++) {
        if (c + 1 < NC) { asm volatile("cp.async.wait_group 1;" ::: "memory"); }
        else            { asm volatile("cp.async.wait_group 0;" ::: "memory"); }
        __syncthreads();
        uint32_t stg = sb + (c & 1) * A_STRIDE;

        float s[8][4];
        #pragma unroll
        for (int i = 0; i < 8; i++)
            #pragma unroll
            for (int e = 0; e < 4; e++) s[i][e] = 0.f;

        // S = Q K^T  (3-term hi/lo split, interleaved chains)
        #pragma unroll
        for (int ks = 0; ks < 4; ks++) {
            #pragma unroll
            for (int nb = 0; nb < 4; nb++) {
                uint32_t bh4[4], bl4[4];
                ldm4(bh4, stg + bKoff + nb * (16 * AROWB) + ks * 32);
                ldm4(bl4, stg + A_KL + bKoff + nb * (16 * AROWB) + ks * 32);
                mma_bf16(s[nb*2],   Qh4[ks], bh4[0], bh4[1]);
                mma_bf16(s[nb*2+1], Qh4[ks], bh4[2], bh4[3]);
                mma_bf16(s[nb*2],   Ql4[ks], bh4[0], bh4[1]);
                mma_bf16(s[nb*2+1], Ql4[ks], bh4[2], bh4[3]);
                mma_bf16(s[nb*2],   Qh4[ks], bl4[0], bl4[1]);
                mma_bf16(s[nb*2+1], Qh4[ks], bl4[2], bl4[3]);
            }
        }

        // scale + mask
        const int* ms = (const int*)(smem + (size_t)(c & 1) * A_STRIDE + A_M);
        #pragma unroll
        for (int nt = 0; nt < 8; nt++) {
            int cc = nt * 8 + (lane & 3) * 2;
            int mv0 = ms[cc], mv1 = ms[cc + 1];
            #pragma unroll
            for (int e = 0; e < 4; e++) s[nt][e] *= 0.125f;
            if (mv0 == 0) { s[nt][0] = -1e9f; s[nt][2] = -1e9f; }
            if (mv1 == 0) { s[nt][1] = -1e9f; s[nt][3] = -1e9f; }
        }

        // online softmax (rows r and r+8 per thread)
        float mx0 = -1e30f, mx1 = -1e30f;
        #pragma unroll
        for (int nt = 0; nt < 8; nt++) {
            mx0 = fmaxf(mx0, fmaxf(s[nt][0], s[nt][1]));
            mx1 = fmaxf(mx1, fmaxf(s[nt][2], s[nt][3]));
        }
        mx0 = fmaxf(mx0, __shfl_xor_sync(0xffffffffu, mx0, 1));
        mx0 = fmaxf(mx0, __shfl_xor_sync(0xffffffffu, mx0, 2));
        mx1 = fmaxf(mx1, __shfl_xor_sync(0xffffffffu, mx1, 1));
        mx1 = fmaxf(mx1, __shfl_xor_sync(0xffffffffu, mx1, 2));
        float mn0 = fmaxf(m0, mx0), mn1 = fmaxf(m1, mx1);
        float sc0 = __expf(m0 - mn0), sc1 = __expf(m1 - mn1);
        m0 = mn0; m1 = mn1;
        float rs0 = 0.f, rs1 = 0.f;
        #pragma unroll
        for (int nt = 0; nt < 8; nt++) {
            s[nt][0] = __expf(s[nt][0] - mn0); rs0 += s[nt][0];
            s[nt][1] = __expf(s[nt][1] - mn0); rs0 += s[nt][1];
            s[nt][2] = __expf(s[nt][2] - mn1); rs1 += s[nt][2];
            s[nt][3] = __expf(s[nt][3] - mn1); rs1 += s[nt][3];
        }
        rs0 += __shfl_xor_sync(0xffffffffu, rs0, 1);
        rs0 += __shfl_xor_sync(0xffffffffu, rs0, 2);
        rs1 += __shfl_xor_sync(0xffffffffu, rs1, 1);
        rs1 += __shfl_xor_sync(0xffffffffu, rs1, 2);
        l0 = l0 * sc0 + rs0;
        l1 = l1 * sc1 + rs1;
        #pragma unroll
        for (int no = 0; no < 8; no++) {
            acc[no][0] *= sc0; acc[no][1] *= sc0;
            acc[no][2] *= sc1; acc[no][3] *= sc1;
        }

        // O += P V   (P fragments repacked directly as A operand)
        #pragma unroll
        for (int kb = 0; kb < 4; kb++) {
            uint32_t a4[4];
            a4[0] = pk2(s[kb*2][0],   s[kb*2][1]);
            a4[1] = pk2(s[kb*2][2],   s[kb*2][3]);
            a4[2] = pk2(s[kb*2+1][0], s[kb*2+1][1]);
            a4[3] = pk2(s[kb*2+1][2], s[kb*2+1][3]);
            #pragma unroll
            for (int db = 0; db < 4; db++) {
                uint32_t bv[4];
                ldm4t(bv, stg + A_V + vOff + kb * (16 * AROWB) + db * 32);
                mma_bf16(acc[db*2],   a4, bv[0], bv[1]);
                mma_bf16(acc[db*2+1], a4, bv[2], bv[3]);
            }
        }

        __syncthreads();
        if (c + 2 < NC) { load_chunk(c + 2); CP_COMMIT(); }
    }

    // ---- output: O / l -> bf16 hi/lo ----
    float inv0 = 1.f / l0, inv1 = 1.f / l1;
    int row0 = q0 + w * 16 + (lane >> 2);
    size_t t0 = (size_t)(b * S_ + row0) * D_ + hoff;
    size_t t1 = t0 + (size_t)8 * D_;
    #pragma unroll
    for (int no = 0; no < 8; no++) {
        int cc = no * 8 + (lane & 3) * 2;
        float o0 = acc[no][0] * inv0, o1 = acc[no][1] * inv0;
        float o2 = acc[no][2] * inv1, o3 = acc[no][3] * inv1;
        *(uint32_t*)(oh + t0 + cc) = pk2(o0, o1);
        *(uint32_t*)(ol + t0 + cc) = pk2(bfres(o0), bfres(o1));
        *(uint32_t*)(oh + t1 + cc) = pk2(o2, o3);
        *(uint32_t*)(ol + t1 + cc) = pk2(bfres(o2), bfres(o3));
    }
}

// ---------------- launch ----------------------------------------------------
extern "C" void kernel_launch(void* const* d_in, const int* in_sizes, int n_in,
                              void* d_out, int out_size)
{
    (void)in_sizes; (void)n_in; (void)out_size;
    const float* x    = (const float*)d_in[0];
    const int*   mask = (const int*)  d_in[1];
    const float* wq   = (const float*)d_in[2];
    const float* wk   = (const float*)d_in[3];
    const float* wv   = (const float*)d_in[4];
    const float* wo   = (const float*)d_in[5];
    const float* w1   = (const float*)d_in[6];
    const float* b1   = (const float*)d_in[7];
    const float* w2   = (const float*)d_in[8];
    const float* b2   = (const float*)d_in[9];
    const float* g1   = (const float*)d_in[10];
    const float* be1  = (const float*)d_in[11];
    const float* g2   = (const float*)d_in[12];
    const float* be2  = (const float*)d_in[13];
    float* out = (float*)d_out;

    float *h1;
    bf16 *zh, *zl, *qkvh, *qkvl, *ah, *al, *mh, *ml;
    bf16 *wch, *wcl, *woh, *wol, *w1h, *w1l, *w2h, *w2l;
    cudaGetSymbolAddress((void**)&h1, g_h1);
    cudaGetSymbolAddress((void**)&zh, g_zh);    cudaGetSymbolAddress((void**)&zl, g_zl);
    cudaGetSymbolAddress((void**)&qkvh, g_qkvh); cudaGetSymbolAddress((void**)&qkvl, g_qkvl);
    cudaGetSymbolAddress((void**)&ah, g_ah);    cudaGetSymbolAddress((void**)&al, g_al);
    cudaGetSymbolAddress((void**)&mh, g_mh);    cudaGetSymbolAddress((void**)&ml, g_ml);
    cudaGetSymbolAddress((void**)&wch, g_wch);  cudaGetSymbolAddress((void**)&wcl, g_wcl);
    cudaGetSymbolAddress((void**)&woh, g_woh);  cudaGetSymbolAddress((void**)&wol, g_wol);
    cudaGetSymbolAddress((void**)&w1h, g_w1h);  cudaGetSymbolAddress((void**)&w1l, g_w1l);
    cudaGetSymbolAddress((void**)&w2h, g_w2h);  cudaGetSymbolAddress((void**)&w2l, g_w2l);

    cudaFuncSetAttribute(tc_gemm<false,false,false,true >, cudaFuncAttributeMaxDynamicSharedMemorySize, SMEM_GEMM);
    cudaFuncSetAttribute(tc_gemm<false,false,true ,false>, cudaFuncAttributeMaxDynamicSharedMemorySize, SMEM_GEMM);
    cudaFuncSetAttribute(tc_gemm<true ,true ,false,true >, cudaFuncAttributeMaxDynamicSharedMemorySize, SMEM_GEMM);
    cudaFuncSetAttribute(tc_gemm<false,true ,true ,false>, cudaFuncAttributeMaxDynamicSharedMemorySize, SMEM_GEMM);
    cudaFuncSetAttribute(attention_tc, cudaFuncAttributeMaxDynamicSharedMemorySize, A_SMEM);

    // weight conversions (qkv concatenated)
    int nW = D_ * D_ / 4;
    convert_hilo<<<(nW + 255)/256, 256>>>(wq, wch,             wcl,             nW);
    convert_hilo<<<(nW + 255)/256, 256>>>(wk, wch + (size_t)D_*D_, wcl + (size_t)D_*D_, nW);
    convert_hilo<<<(nW + 255)/256, 256>>>(wv, wch + (size_t)2*D_*D_, wcl + (size_t)2*D_*D_, nW);
    convert_hilo<<<(nW + 255)/256, 256>>>(wo, woh, wol, nW);
    int nF = DFF_ * D_ / 4;
    convert_hilo<<<(nF + 255)/256, 256>>>(w1, w1h, w1l, nF);
    convert_hilo<<<(nF + 255)/256, 256>>>(w2, w2h, w2l, nF);

    // LN1
    layernorm_kernel<<<NT, 256>>>(x, g1, be1, zh, zl);

    // fused QKV GEMM (N = 3072) -> bf16 hi/lo
    dim3 gQKV(QKVS / 128, NT / 128);
    tc_gemm<false,false,false,true><<<gQKV, 256, SMEM_GEMM>>>(zh, zl, wch, wcl, nullptr, nullptr, nullptr, qkvh, qkvl, NT, QKVS, D_);

    // attention (tensor core) -> bf16 hi/lo
    dim3 gAtt(S_ / 128, B_ * H_);
    attention_tc<<<gAtt, 256, A_SMEM>>>(qkvh, qkvl, mask, ah, al);

    // h1 = x + attn @ wo^T
    dim3 gP(D_ / 128, NT / 128);
    tc_gemm<false,false,true,false><<<gP, 256, SMEM_GEMM>>>(ah, al, woh, wol, nullptr, x, h1, nullptr, nullptr, NT, D_, D_);

    // LN2
    layernorm_kernel<<<NT, 256>>>(h1, g2, be2, zh, zl);

    // FFN1: mid = relu(z @ w1^T + b1) -> bf16 hi/lo
    dim3 gF1(DFF_ / 128, NT / 128);
    tc_gemm<true,true,false,true><<<gF1, 256, SMEM_GEMM>>>(zh, zl, w1h, w1l, b1, nullptr, nullptr, mh, ml, NT, DFF_, D_);

    // FFN2: out = h1 + mid @ w2^T + b2
    dim3 gF2(D_ / 128, NT / 128);
    tc_gemm<false,true,true,false><<<gF2, 256, SMEM_GEMM>>>(mh, ml, w2h, w2l, b2, h1, out, nullptr, nullptr, NT, D_, DFF_);
}

// round 6
// speedup vs baseline: 4.3113x; 1.2929x over previous
#include <cuda_runtime.h>
#include <cuda_fp16.h>
#include <math.h>
#include <stdint.h>

// Problem dims
#define B_  4
#define S_  2048
#define D_  1024
#define H_  16
#define DKH 64
#define DFF_ 4096
#define NT  (B_ * S_)   // 8192 tokens
#define QKVS 3072       // fused qkv row stride

typedef __half h16;

// ====================== PTX helpers (baseline ISA, sm_80+) ==================
__device__ __forceinline__ uint32_t smem_to_u32(const void* p) {
    uint32_t a;
    asm("{ .reg .u64 t; cvta.to.shared.u64 t, %1; cvt.u32.u64 %0, t; }" : "=r"(a) : "l"(p));
    return a;
}
__device__ __forceinline__ void cp16(uint32_t dst, const void* src) {
    asm volatile("cp.async.cg.shared.global [%0], [%1], 16;" :: "r"(dst), "l"(src));
}
#define CP_COMMIT() asm volatile("cp.async.commit_group;" ::: "memory")

__device__ __forceinline__ void ldm4(uint32_t* r, uint32_t addr) {
    asm volatile("ldmatrix.sync.aligned.m8n8.x4.shared.b16 {%0,%1,%2,%3}, [%4];"
        : "=r"(r[0]), "=r"(r[1]), "=r"(r[2]), "=r"(r[3]) : "r"(addr));
}
__device__ __forceinline__ void ldm4t(uint32_t* r, uint32_t addr) {
    asm volatile("ldmatrix.sync.aligned.m8n8.x4.trans.shared.b16 {%0,%1,%2,%3}, [%4];"
        : "=r"(r[0]), "=r"(r[1]), "=r"(r[2]), "=r"(r[3]) : "r"(addr));
}
__device__ __forceinline__ void mma_f16(float* d, const uint32_t* a,
                                        uint32_t b0, uint32_t b1) {
    asm volatile(
        "mma.sync.aligned.m16n8k16.row.col.f32.f16.f16.f32 "
        "{%0,%1,%2,%3}, {%4,%5,%6,%7}, {%8,%9}, {%0,%1,%2,%3};"
        : "+f"(d[0]), "+f"(d[1]), "+f"(d[2]), "+f"(d[3])
        : "r"(a[0]), "r"(a[1]), "r"(a[2]), "r"(a[3]), "r"(b0), "r"(b1));
}

// ============ fp16 hi/lo split helpers ======================================
__device__ __forceinline__ uint32_t pk2h(float a, float b) {
    return (uint32_t)__half_as_ushort(__float2half_rn(a)) |
           ((uint32_t)__half_as_ushort(__float2half_rn(b)) << 16);
}
__device__ __forceinline__ float hres(float a) {
    return a - __half2float(__float2half_rn(a));
}

// ---------------- scratch (device globals) ----------------------------------
__device__ __align__(256) float g_h1[(size_t)NT * D_];
__device__ __align__(256) h16 g_zh[(size_t)NT * D_],  g_zl[(size_t)NT * D_];
__device__ __align__(256) h16 g_qkvh[(size_t)NT * QKVS], g_qkvl[(size_t)NT * QKVS];
__device__ __align__(256) h16 g_ah[(size_t)NT * D_],  g_al[(size_t)NT * D_];
__device__ __align__(256) h16 g_mh[(size_t)NT * DFF_], g_ml[(size_t)NT * DFF_];
__device__ __align__(256) h16 g_wc[(size_t)3*D_*D_];
__device__ __align__(256) h16 g_wo[(size_t)D_*D_];
__device__ __align__(256) h16 g_w1[(size_t)DFF_*D_];
__device__ __align__(256) h16 g_w2[(size_t)D_*DFF_];

// ---------------- fp32 -> fp16 weight convert -------------------------------
__global__ __launch_bounds__(256) void convert_h(
    const float* __restrict__ src, h16* __restrict__ hi, int n4)
{
    int i = blockIdx.x * 256 + threadIdx.x;
    if (i >= n4) return;
    float4 v = ((const float4*)src)[i];
    ((uint2*)hi)[i] = make_uint2(pk2h(v.x, v.y), pk2h(v.z, v.w));
}

// ---------------- LayerNorm (Bessel ddof=1, eps=1e-9) -> fp16 hi/lo ---------
__global__ __launch_bounds__(256) void layernorm_kernel(
    const float* __restrict__ x, const float* __restrict__ gamma,
    const float* __restrict__ beta, h16* __restrict__ yh, h16* __restrict__ yl)
{
    int row = blockIdx.x;
    int t = threadIdx.x;
    const float4* xr = (const float4*)(x + (size_t)row * D_);
    float4 v = xr[t];
    float s  = v.x + v.y + v.z + v.w;
    float ss = v.x*v.x + v.y*v.y + v.z*v.z + v.w*v.w;
    #pragma unroll
    for (int o = 16; o > 0; o >>= 1) {
        s  += __shfl_xor_sync(0xffffffffu, s,  o);
        ss += __shfl_xor_sync(0xffffffffu, ss, o);
    }
    __shared__ float shs[8], shq[8];
    int w = t >> 5, l = t & 31;
    if (l == 0) { shs[w] = s; shq[w] = ss; }
    __syncthreads();
    float S = 0.f, Q = 0.f;
    #pragma unroll
    for (int i = 0; i < 8; i++) { S += shs[i]; Q += shq[i]; }
    float mean = S * (1.f / (float)D_);
    float var  = (Q - (float)D_ * mean * mean) * (1.f / (float)(D_ - 1));
    float inv  = rsqrtf(var + 1e-9f);
    const float4 g  = ((const float4*)gamma)[t];
    const float4 be = ((const float4*)beta)[t];
    float o0 = g.x * (v.x - mean) * inv + be.x;
    float o1 = g.y * (v.y - mean) * inv + be.y;
    float o2 = g.z * (v.z - mean) * inv + be.z;
    float o3 = g.w * (v.w - mean) * inv + be.w;
    size_t idx = (size_t)row * (D_/4) + t;
    ((uint2*)yh)[idx] = make_uint2(pk2h(o0, o1), pk2h(o2, o3));
    ((uint2*)yl)[idx] = make_uint2(pk2h(hres(o0), hres(o1)), pk2h(hres(o2), hres(o3)));
}

// ---------------- mma.sync fp16 2-term GEMM ---------------------------------
// C = act((Ah+Al) @ Bh^T + bias) (+res). A exact via hi/lo; B fp16-rounded.
// 128x128x32 CTA tile, 256 threads (8 warps, 2m x 4n), 3-stage cp.async,
// 2 CTAs/SM. Term-outer MMA ordering.
#define ROWB 80
#define MAT_BYTES (128 * ROWB)          // 10240
#define STAGE_BYTES (3 * MAT_BYTES)     // 30720: Ah | Al | Bh
#define SMEM_GEMM (3 * STAGE_BYTES)     // 92160

template<bool RELU, bool BIAS, bool RES, bool OUTF16>
__global__ __launch_bounds__(256, 2) void tc_gemm(
    const h16* __restrict__ Ah, const h16* __restrict__ Al,
    const h16* __restrict__ Bh,
    const float* __restrict__ bias, const float* __restrict__ res,
    float* __restrict__ Cf, h16* __restrict__ Ch, h16* __restrict__ Cl,
    int M, int N, int K)
{
    extern __shared__ char smem[];
    uint32_t sb = smem_to_u32(smem);
    int tid = threadIdx.x;
    int lane = tid & 31, wid = tid >> 5;
    int wm = wid & 1, wn = wid >> 1;
    int row0 = blockIdx.y * 128, col0 = blockIdx.x * 128;

    int lm = tid >> 1;
    int lc = (tid & 1) * 2;
    const h16* aHs = Ah + (size_t)(row0 + lm) * K + lc * 8;
    const h16* aLs = Al + (size_t)(row0 + lm) * K + lc * 8;
    const h16* bHs = Bh + (size_t)(col0 + lm) * K + lc * 8;
    uint32_t dA = (uint32_t)(lm * ROWB + lc * 16);

    auto load_stage = [&](int p, int kt) {
        uint32_t s0 = sb + p * STAGE_BYTES;
        size_t ko = (size_t)kt * 32;
        cp16(s0 + dA,                    aHs + ko);
        cp16(s0 + dA + 16,               aHs + ko + 8);
        cp16(s0 + MAT_BYTES + dA,        aLs + ko);
        cp16(s0 + MAT_BYTES + dA + 16,   aLs + ko + 8);
        cp16(s0 + 2*MAT_BYTES + dA,      bHs + ko);
        cp16(s0 + 2*MAT_BYTES + dA + 16, bHs + ko + 8);
    };

    int g = lane >> 3, r = lane & 7;
    uint32_t aoff = (uint32_t)((wm * 64 + (g & 1) * 8 + r) * ROWB + (g >> 1) * 16);
    uint32_t boff = (uint32_t)((wn * 32 + (g >> 1) * 8 + r) * ROWB + (g & 1) * 16);

    float acc[4][4][4];
    #pragma unroll
    for (int i = 0; i < 4; i++)
        #pragma unroll
        for (int j = 0; j < 4; j++)
            #pragma unroll
            for (int e = 0; e < 4; e++) acc[i][j][e] = 0.f;

    int KT = K / 32;
    load_stage(0, 0); CP_COMMIT();
    load_stage(1, 1); CP_COMMIT();
    load_stage(2, 2); CP_COMMIT();

    for (int kt = 0; kt < KT; kt++) {
        int s = kt % 3;
        asm volatile("cp.async.wait_group 2;" ::: "memory");
        __syncthreads();
        uint32_t st = sb + s * STAGE_BYTES;
        #pragma unroll
        for (int h = 0; h < 2; h++) {
            uint32_t ah[4][4], bh[2][4];
            #pragma unroll
            for (int mt = 0; mt < 4; mt++)
                ldm4(ah[mt], st + aoff + mt * (16 * ROWB) + h * 32);
            #pragma unroll
            for (int nb = 0; nb < 2; nb++)
                ldm4(bh[nb], st + 2*MAT_BYTES + boff + nb * (16 * ROWB) + h * 32);
            // term hh: 16 independent MMAs
            #pragma unroll
            for (int mt = 0; mt < 4; mt++)
                #pragma unroll
                for (int nt = 0; nt < 4; nt++)
                    mma_f16(acc[mt][nt], ah[mt],
                            bh[nt >> 1][(nt & 1) * 2], bh[nt >> 1][(nt & 1) * 2 + 1]);
            // term lh
            {
                uint32_t al[4][4];
                #pragma unroll
                for (int mt = 0; mt < 4; mt++)
                    ldm4(al[mt], st + MAT_BYTES + aoff + mt * (16 * ROWB) + h * 32);
                #pragma unroll
                for (int mt = 0; mt < 4; mt++)
                    #pragma unroll
                    for (int nt = 0; nt < 4; nt++)
                        mma_f16(acc[mt][nt], al[mt],
                                bh[nt >> 1][(nt & 1) * 2], bh[nt >> 1][(nt & 1) * 2 + 1]);
            }
        }
        __syncthreads();
        if (kt + 3 < KT) load_stage(s, kt + 3);
        CP_COMMIT();
    }

    // epilogue
    #pragma unroll
    for (int mt = 0; mt < 4; mt++) {
        int r_lo = row0 + wm * 64 + mt * 16 + (lane >> 2);
        #pragma unroll
        for (int nt = 0; nt < 4; nt++) {
            int col = col0 + wn * 32 + nt * 8 + (lane & 3) * 2;
            float* d = acc[mt][nt];
            float bi0 = 0.f, bi1 = 0.f;
            if (BIAS) { bi0 = __ldg(bias + col); bi1 = __ldg(bias + col + 1); }
            #pragma unroll
            for (int half = 0; half < 2; half++) {
                int row = r_lo + half * 8;
                float v0 = d[half * 2 + 0], v1 = d[half * 2 + 1];
                if (BIAS) { v0 += bi0; v1 += bi1; }
                if (RELU) { v0 = fmaxf(v0, 0.f); v1 = fmaxf(v1, 0.f); }
                size_t base = (size_t)row * N + col;
                if (RES) {
                    float2 rr = *(const float2*)(res + base);
                    v0 += rr.x; v1 += rr.y;
                }
                if (OUTF16) {
                    *(uint32_t*)(Ch + base) = pk2h(v0, v1);
                    *(uint32_t*)(Cl + base) = pk2h(hres(v0), hres(v1));
                } else {
                    *(float2*)(Cf + base) = make_float2(v0, v1);
                }
            }
        }
    }
}

// ---------------- Tensor-core flash attention (fp16) ------------------------
// CTA: 128 q-rows x one head. 8 warps x 16 rows. 64-key chunks, double buffer,
// 2 CTAs/SM. Q exact (hi/lo), K fp16 (hi only), V fp16.
#define AROWB 144
#define A_V   9216
#define A_M   18432
#define A_STRIDE 18688
#define A_SMEM (2 * A_STRIDE)   // 37376

__global__ __launch_bounds__(256, 2) void attention_tc(
    const h16* __restrict__ qkvh, const h16* __restrict__ qkvl,
    const int* __restrict__ mask,
    h16* __restrict__ oh, h16* __restrict__ ol)
{
    extern __shared__ char smem[];
    uint32_t sb = smem_to_u32(smem);
    int tid = threadIdx.x, lane = tid & 31, w = tid >> 5;
    int bh_ = blockIdx.y, b = bh_ >> 4, h = bh_ & 15;
    int q0 = blockIdx.x * 128;
    size_t hoff = (size_t)h * DKH;
    int g = lane >> 3, r = lane & 7;

    // ---- stage Q: hi -> buf0 region, lo -> buf1 region ----
    {
        int lm = tid >> 1;
        int lc = (tid & 1) * 4;
        size_t go = (size_t)(b * S_ + q0 + lm) * QKVS + hoff + lc * 8;
        uint32_t d0 = sb + (uint32_t)(lm * AROWB + lc * 16);
        #pragma unroll
        for (int j = 0; j < 4; j++) {
            cp16(d0 + j * 16, qkvh + go + j * 8);
            cp16(d0 + A_STRIDE + j * 16, qkvl + go + j * 8);
        }
        CP_COMMIT();
    }
    asm volatile("cp.async.wait_group 0;" ::: "memory");
    __syncthreads();

    uint32_t Qh4[4][4], Ql4[4][4];
    {
        uint32_t aoff = sb + (uint32_t)((w * 16 + (g & 1) * 8 + r) * AROWB + (g >> 1) * 16);
        #pragma unroll
        for (int ks = 0; ks < 4; ks++) {
            ldm4(Qh4[ks], aoff + ks * 32);
            ldm4(Ql4[ks], aoff + A_STRIDE + ks * 32);
        }
    }
    __syncthreads();

    float m0 = -1e30f, m1 = -1e30f, l0 = 0.f, l1 = 0.f;
    float acc[8][4];
    #pragma unroll
    for (int i = 0; i < 8; i++)
        #pragma unroll
        for (int e = 0; e < 4; e++) acc[i][e] = 0.f;

    const h16* kbh = qkvh + (size_t)b * S_ * QKVS + D_ + hoff;
    const h16* vb  = qkvh + (size_t)b * S_ * QKVS + 2 * D_ + hoff;
    const int* mrow = mask + (size_t)b * S_;

    auto load_chunk = [&](int c) {
        uint32_t stg = sb + (c & 1) * A_STRIDE;
        int lm = tid >> 2;
        int lc = (tid & 3) * 2;
        size_t go = (size_t)(c * 64 + lm) * QKVS + lc * 8;
        uint32_t d = stg + (uint32_t)(lm * AROWB + lc * 16);
        cp16(d,            kbh + go);
        cp16(d + 16,       kbh + go + 8);
        cp16(d + A_V,      vb + go);
        cp16(d + A_V + 16, vb + go + 8);
        if (tid < 64)
            asm volatile("cp.async.ca.shared.global [%0], [%1], 4;"
                :: "r"(stg + A_M + tid * 4), "l"(mrow + c * 64 + tid));
    };

    const int NC = S_ / 64;   // 32
    load_chunk(0); CP_COMMIT();
    load_chunk(1); CP_COMMIT();

    uint32_t bKoff = (uint32_t)(((g >> 1) * 8 + r) * AROWB + (g & 1) * 16);
    uint32_t vOff  = (uint32_t)(((g & 1) * 8 + r) * AROWB + (g >> 1) * 16);

    for (int c = 0; c < NC; c++) {
        if (c + 1 < NC) { asm volatile("cp.async.wait_group 1;" ::: "memory"); }
        else            { asm volatile("cp.async.wait_group 0;" ::: "memory"); }
        __syncthreads();
        uint32_t stg = sb + (c & 1) * A_STRIDE;

        float s[8][4];
        #pragma unroll
        for (int i = 0; i < 8; i++)
            #pragma unroll
            for (int e = 0; e < 4; e++) s[i][e] = 0.f;

        // S = Q K^T  (2-term: Q exact, K fp16)
        #pragma unroll
        for (int ks = 0; ks < 4; ks++) {
            #pragma unroll
            for (int nb = 0; nb < 4; nb++) {
                uint32_t bh4[4];
                ldm4(bh4, stg + bKoff + nb * (16 * AROWB) + ks * 32);
                mma_f16(s[nb*2],   Qh4[ks], bh4[0], bh4[1]);
                mma_f16(s[nb*2+1], Qh4[ks], bh4[2], bh4[3]);
                mma_f16(s[nb*2],   Ql4[ks], bh4[0], bh4[1]);
                mma_f16(s[nb*2+1], Ql4[ks], bh4[2], bh4[3]);
            }
        }

        // scale + mask
        const int* ms = (const int*)(smem + (size_t)(c & 1) * A_STRIDE + A_M);
        #pragma unroll
        for (int nt = 0; nt < 8; nt++) {
            int cc = nt * 8 + (lane & 3) * 2;
            int mv0 = ms[cc], mv1 = ms[cc + 1];
            #pragma unroll
            for (int e = 0; e < 4; e++) s[nt][e] *= 0.125f;
            if (mv0 == 0) { s[nt][0] = -1e9f; s[nt][2] = -1e9f; }
            if (mv1 == 0) { s[nt][1] = -1e9f; s[nt][3] = -1e9f; }
        }

        // online softmax (rows r and r+8 per thread)
        float mx0 = -1e30f, mx1 = -1e30f;
        #pragma unroll
        for (int nt = 0; nt < 8; nt++) {
            mx0 = fmaxf(mx0, fmaxf(s[nt][0], s[nt][1]));
            mx1 = fmaxf(mx1, fmaxf(s[nt][2], s[nt][3]));
        }
        mx0 = fmaxf(mx0, __shfl_xor_sync(0xffffffffu, mx0, 1));
        mx0 = fmaxf(mx0, __shfl_xor_sync(0xffffffffu, mx0, 2));
        mx1 = fmaxf(mx1, __shfl_xor_sync(0xffffffffu, mx1, 1));
        mx1 = fmaxf(mx1, __shfl_xor_sync(0xffffffffu, mx1, 2));
        float mn0 = fmaxf(m0, mx0), mn1 = fmaxf(m1, mx1);
        float sc0 = __expf(m0 - mn0), sc1 = __expf(m1 - mn1);
        m0 = mn0; m1 = mn1;
        float rs0 = 0.f, rs1 = 0.f;
        #pragma unroll
        for (int nt = 0; nt < 8; nt++) {
            s[nt][0] = __expf(s[nt][0] - mn0); rs0 += s[nt][0];
            s[nt][1] = __expf(s[nt][1] - mn0); rs0 += s[nt][1];
            s[nt][2] = __expf(s[nt][2] - mn1); rs1 += s[nt][2];
            s[nt][3] = __expf(s[nt][3] - mn1); rs1 += s[nt][3];
        }
        rs0 += __shfl_xor_sync(0xffffffffu, rs0, 1);
        rs0 += __shfl_xor_sync(0xffffffffu, rs0, 2);
        rs1 += __shfl_xor_sync(0xffffffffu, rs1, 1);
        rs1 += __shfl_xor_sync(0xffffffffu, rs1, 2);
        l0 = l0 * sc0 + rs0;
        l1 = l1 * sc1 + rs1;
        #pragma unroll
        for (int no = 0; no < 8; no++) {
            acc[no][0] *= sc0; acc[no][1] *= sc0;
            acc[no][2] *= sc1; acc[no][3] *= sc1;
        }

        // O += P V   (P fragments repacked directly as A operand)
        #pragma unroll
        for (int kb = 0; kb < 4; kb++) {
            uint32_t a4[4];
            a4[0] = pk2h(s[kb*2][0],   s[kb*2][1]);
            a4[1] = pk2h(s[kb*2][2],   s[kb*2][3]);
            a4[2] = pk2h(s[kb*2+1][0], s[kb*2+1][1]);
            a4[3] = pk2h(s[kb*2+1][2], s[kb*2+1][3]);
            #pragma unroll
            for (int db = 0; db < 4; db++) {
                uint32_t bv[4];
                ldm4t(bv, stg + A_V + vOff + kb * (16 * AROWB) + db * 32);
                mma_f16(acc[db*2],   a4, bv[0], bv[1]);
                mma_f16(acc[db*2+1], a4, bv[2], bv[3]);
            }
        }

        __syncthreads();
        if (c + 2 < NC) { load_chunk(c + 2); CP_COMMIT(); }
    }

    // ---- output: O / l -> fp16 hi/lo ----
    float inv0 = 1.f / l0, inv1 = 1.f / l1;
    int row0 = q0 + w * 16 + (lane >> 2);
    size_t t0 = (size_t)(b * S_ + row0) * D_ + hoff;
    size_t t1 = t0 + (size_t)8 * D_;
    #pragma unroll
    for (int no = 0; no < 8; no++) {
        int cc = no * 8 + (lane & 3) * 2;
        float o0 = acc[no][0] * inv0, o1 = acc[no][1] * inv0;
        float o2 = acc[no][2] * inv1, o3 = acc[no][3] * inv1;
        *(uint32_t*)(oh + t0 + cc) = pk2h(o0, o1);
        *(uint32_t*)(ol + t0 + cc) = pk2h(hres(o0), hres(o1));
        *(uint32_t*)(oh + t1 + cc) = pk2h(o2, o3);
        *(uint32_t*)(ol + t1 + cc) = pk2h(hres(o2), hres(o3));
    }
}

// ---------------- launch ----------------------------------------------------
extern "C" void kernel_launch(void* const* d_in, const int* in_sizes, int n_in,
                              void* d_out, int out_size)
{
    (void)in_sizes; (void)n_in; (void)out_size;
    const float* x    = (const float*)d_in[0];
    const int*   mask = (const int*)  d_in[1];
    const float* wq   = (const float*)d_in[2];
    const float* wk   = (const float*)d_in[3];
    const float* wv   = (const float*)d_in[4];
    const float* wo   = (const float*)d_in[5];
    const float* w1   = (const float*)d_in[6];
    const float* b1   = (const float*)d_in[7];
    const float* w2   = (const float*)d_in[8];
    const float* b2   = (const float*)d_in[9];
    const float* g1   = (const float*)d_in[10];
    const float* be1  = (const float*)d_in[11];
    const float* g2   = (const float*)d_in[12];
    const float* be2  = (const float*)d_in[13];
    float* out = (float*)d_out;

    float *h1;
    h16 *zh, *zl, *qkvh, *qkvl, *ah, *al, *mh, *ml;
    h16 *wc, *wop, *w1p, *w2p;
    cudaGetSymbolAddress((void**)&h1, g_h1);
    cudaGetSymbolAddress((void**)&zh, g_zh);    cudaGetSymbolAddress((void**)&zl, g_zl);
    cudaGetSymbolAddress((void**)&qkvh, g_qkvh); cudaGetSymbolAddress((void**)&qkvl, g_qkvl);
    cudaGetSymbolAddress((void**)&ah, g_ah);    cudaGetSymbolAddress((void**)&al, g_al);
    cudaGetSymbolAddress((void**)&mh, g_mh);    cudaGetSymbolAddress((void**)&ml, g_ml);
    cudaGetSymbolAddress((void**)&wc, g_wc);
    cudaGetSymbolAddress((void**)&wop, g_wo);
    cudaGetSymbolAddress((void**)&w1p, g_w1);
    cudaGetSymbolAddress((void**)&w2p, g_w2);

    cudaFuncSetAttribute(tc_gemm<false,false,false,true >, cudaFuncAttributeMaxDynamicSharedMemorySize, SMEM_GEMM);
    cudaFuncSetAttribute(tc_gemm<false,false,true ,false>, cudaFuncAttributeMaxDynamicSharedMemorySize, SMEM_GEMM);
    cudaFuncSetAttribute(tc_gemm<true ,true ,false,true >, cudaFuncAttributeMaxDynamicSharedMemorySize, SMEM_GEMM);
    cudaFuncSetAttribute(tc_gemm<false,true ,true ,false>, cudaFuncAttributeMaxDynamicSharedMemorySize, SMEM_GEMM);
    cudaFuncSetAttribute(attention_tc, cudaFuncAttributeMaxDynamicSharedMemorySize, A_SMEM);

    // weight conversions (qkv concatenated; fp16 single buffer)
    int nW = D_ * D_ / 4;
    convert_h<<<(nW + 255)/256, 256>>>(wq, wc, nW);
    convert_h<<<(nW + 255)/256, 256>>>(wk, wc + (size_t)D_*D_, nW);
    convert_h<<<(nW + 255)/256, 256>>>(wv, wc + (size_t)2*D_*D_, nW);
    convert_h<<<(nW + 255)/256, 256>>>(wo, wop, nW);
    int nF = DFF_ * D_ / 4;
    convert_h<<<(nF + 255)/256, 256>>>(w1, w1p, nF);
    convert_h<<<(nF + 255)/256, 256>>>(w2, w2p, nF);

    // LN1
    layernorm_kernel<<<NT, 256>>>(x, g1, be1, zh, zl);

    // fused QKV GEMM (N = 3072) -> fp16 hi/lo
    dim3 gQKV(QKVS / 128, NT / 128);
    tc_gemm<false,false,false,true><<<gQKV, 256, SMEM_GEMM>>>(zh, zl, wc, nullptr, nullptr, nullptr, qkvh, qkvl, NT, QKVS, D_);

    // attention (tensor core) -> fp16 hi/lo
    dim3 gAtt(S_ / 128, B_ * H_);
    attention_tc<<<gAtt, 256, A_SMEM>>>(qkvh, qkvl, mask, ah, al);

    // h1 = x + attn @ wo^T
    dim3 gP(D_ / 128, NT / 128);
    tc_gemm<false,false,true,false><<<gP, 256, SMEM_GEMM>>>(ah, al, wop, nullptr, x, h1, nullptr, nullptr, NT, D_, D_);

    // LN2
    layernorm_kernel<<<NT, 256>>>(h1, g2, be2, zh, zl);

    // FFN1: mid = relu(z @ w1^T + b1) -> fp16 hi/lo
    dim3 gF1(DFF_ / 128, NT / 128);
    tc_gemm<true,true,false,true><<<gF1, 256, SMEM_GEMM>>>(zh, zl, w1p, b1, nullptr, nullptr, mh, ml, NT, DFF_, D_);

    // FFN2: out = h1 + mid @ w2^T + b2
    dim3 gF2(D_ / 128, NT / 128);
    tc_gemm<false,true,true,false><<<gF2, 256, SMEM_GEMM>>>(mh, ml, w2p, b2, h1, out, nullptr, nullptr, NT, D_, DFF_);
}

// round 7
// speedup vs baseline: 5.4528x; 1.2648x over previous
#include <cuda_runtime.h>
#include <cuda_fp16.h>
#include <math.h>
#include <stdint.h>

// Problem dims
#define B_  4
#define S_  2048
#define D_  1024
#define H_  16
#define DKH 64
#define DFF_ 4096
#define NT  (B_ * S_)   // 8192 tokens
#define QKVS 3072       // fused qkv row stride

typedef __half h16;

// ====================== PTX helpers (baseline ISA, sm_80+) ==================
__device__ __forceinline__ uint32_t smem_to_u32(const void* p) {
    uint32_t a;
    asm("{ .reg .u64 t; cvta.to.shared.u64 t, %1; cvt.u32.u64 %0, t; }" : "=r"(a) : "l"(p));
    return a;
}
__device__ __forceinline__ void cp16(uint32_t dst, const void* src) {
    asm volatile("cp.async.cg.shared.global [%0], [%1], 16;" :: "r"(dst), "l"(src));
}
#define CP_COMMIT() asm volatile("cp.async.commit_group;" ::: "memory")

__device__ __forceinline__ void ldm4(uint32_t* r, uint32_t addr) {
    asm volatile("ldmatrix.sync.aligned.m8n8.x4.shared.b16 {%0,%1,%2,%3}, [%4];"
        : "=r"(r[0]), "=r"(r[1]), "=r"(r[2]), "=r"(r[3]) : "r"(addr));
}
__device__ __forceinline__ void ldm4t(uint32_t* r, uint32_t addr) {
    asm volatile("ldmatrix.sync.aligned.m8n8.x4.trans.shared.b16 {%0,%1,%2,%3}, [%4];"
        : "=r"(r[0]), "=r"(r[1]), "=r"(r[2]), "=r"(r[3]) : "r"(addr));
}
__device__ __forceinline__ void mma_f16(float* d, const uint32_t* a,
                                        uint32_t b0, uint32_t b1) {
    asm volatile(
        "mma.sync.aligned.m16n8k16.row.col.f32.f16.f16.f32 "
        "{%0,%1,%2,%3}, {%4,%5,%6,%7}, {%8,%9}, {%0,%1,%2,%3};"
        : "+f"(d[0]), "+f"(d[1]), "+f"(d[2]), "+f"(d[3])
        : "r"(a[0]), "r"(a[1]), "r"(a[2]), "r"(a[3]), "r"(b0), "r"(b1));
}

// ============ fp16 hi/lo split helpers ======================================
__device__ __forceinline__ uint32_t pk2h(float a, float b) {
    return (uint32_t)__half_as_ushort(__float2half_rn(a)) |
           ((uint32_t)__half_as_ushort(__float2half_rn(b)) << 16);
}
__device__ __forceinline__ float hres(float a) {
    return a - __half2float(__float2half_rn(a));
}

// ---------------- scratch (device globals) ----------------------------------
__device__ __align__(256) float g_h1[(size_t)NT * D_];
__device__ __align__(256) h16 g_zh[(size_t)NT * D_],  g_zl[(size_t)NT * D_];
__device__ __align__(256) h16 g_qkvh[(size_t)NT * QKVS];
__device__ __align__(256) h16 g_ah[(size_t)NT * D_];
__device__ __align__(256) h16 g_mh[(size_t)NT * DFF_];
__device__ __align__(256) h16 g_wc[(size_t)3*D_*D_];
__device__ __align__(256) h16 g_wo[(size_t)D_*D_];
__device__ __align__(256) h16 g_w1[(size_t)DFF_*D_];
__device__ __align__(256) h16 g_w2[(size_t)D_*DFF_];

// ---------------- fused weight converts (2 launches) ------------------------
// nW/4 float4 per DxD weight = 262144 -> 1024 blocks of 256
__global__ __launch_bounds__(256) void convert_qkv(
    const float* __restrict__ wq, const float* __restrict__ wk,
    const float* __restrict__ wv, h16* __restrict__ wc)
{
    int seg = blockIdx.x >> 10;            // 0..2
    int i = (blockIdx.x & 1023) * 256 + threadIdx.x;
    const float* src = (seg == 0) ? wq : (seg == 1) ? wk : wv;
    float4 v = ((const float4*)src)[i];
    ((uint2*)(wc + (size_t)seg * D_ * D_))[i] =
        make_uint2(pk2h(v.x, v.y), pk2h(v.z, v.w));
}
__global__ __launch_bounds__(256) void convert_rest(
    const float* __restrict__ wo, const float* __restrict__ w1,
    const float* __restrict__ w2, h16* __restrict__ dwo,
    h16* __restrict__ dw1, h16* __restrict__ dw2)
{
    int bidx = blockIdx.x;
    const float* src; h16* dst; int i;
    if (bidx < 1024)       { src = wo; dst = dwo; i = bidx * 256 + threadIdx.x; }
    else if (bidx < 5120)  { src = w1; dst = dw1; i = (bidx - 1024) * 256 + threadIdx.x; }
    else                   { src = w2; dst = dw2; i = (bidx - 5120) * 256 + threadIdx.x; }
    float4 v = ((const float4*)src)[i];
    ((uint2*)dst)[i] = make_uint2(pk2h(v.x, v.y), pk2h(v.z, v.w));
}

// ---------------- LayerNorm (Bessel ddof=1, eps=1e-9) -> fp16 hi/lo ---------
__global__ __launch_bounds__(256) void layernorm_kernel(
    const float* __restrict__ x, const float* __restrict__ gamma,
    const float* __restrict__ beta, h16* __restrict__ yh, h16* __restrict__ yl)
{
    int row = blockIdx.x;
    int t = threadIdx.x;
    const float4* xr = (const float4*)(x + (size_t)row * D_);
    float4 v = xr[t];
    float s  = v.x + v.y + v.z + v.w;
    float ss = v.x*v.x + v.y*v.y + v.z*v.z + v.w*v.w;
    #pragma unroll
    for (int o = 16; o > 0; o >>= 1) {
        s  += __shfl_xor_sync(0xffffffffu, s,  o);
        ss += __shfl_xor_sync(0xffffffffu, ss, o);
    }
    __shared__ float shs[8], shq[8];
    int w = t >> 5, l = t & 31;
    if (l == 0) { shs[w] = s; shq[w] = ss; }
    __syncthreads();
    float S = 0.f, Q = 0.f;
    #pragma unroll
    for (int i = 0; i < 8; i++) { S += shs[i]; Q += shq[i]; }
    float mean = S * (1.f / (float)D_);
    float var  = (Q - (float)D_ * mean * mean) * (1.f / (float)(D_ - 1));
    float inv  = rsqrtf(var + 1e-9f);
    const float4 g  = ((const float4*)gamma)[t];
    const float4 be = ((const float4*)beta)[t];
    float o0 = g.x * (v.x - mean) * inv + be.x;
    float o1 = g.y * (v.y - mean) * inv + be.y;
    float o2 = g.z * (v.z - mean) * inv + be.z;
    float o3 = g.w * (v.w - mean) * inv + be.w;
    size_t idx = (size_t)row * (D_/4) + t;
    ((uint2*)yh)[idx] = make_uint2(pk2h(o0, o1), pk2h(o2, o3));
    ((uint2*)yl)[idx] = make_uint2(pk2h(hres(o0), hres(o1)), pk2h(hres(o2), hres(o3)));
}

// ---------------- mma.sync fp16 GEMM (A optionally exact via hi/lo) ---------
// 128x128x32 CTA tile, 256 threads (8 warps, 2m x 4n), 3-stage cp.async,
// 2 CTAs/SM. Term-outer MMA ordering.
#define ROWB 80
#define MAT_BYTES (128 * ROWB)          // 10240

template<bool ALO, bool RELU, bool BIAS, bool RES, bool OUTF16>
__global__ __launch_bounds__(256, 2) void tc_gemm(
    const h16* __restrict__ Ah, const h16* __restrict__ Al,
    const h16* __restrict__ Bh,
    const float* __restrict__ bias, const float* __restrict__ res,
    float* __restrict__ Cf, h16* __restrict__ Ch,
    int M, int N, int K)
{
    constexpr int STB = (ALO ? 3 : 2) * MAT_BYTES;   // stage bytes
    constexpr int BOFF = (ALO ? 2 : 1) * MAT_BYTES;  // B offset within stage
    extern __shared__ char smem[];
    uint32_t sb = smem_to_u32(smem);
    int tid = threadIdx.x;
    int lane = tid & 31, wid = tid >> 5;
    int wm = wid & 1, wn = wid >> 1;
    int row0 = blockIdx.y * 128, col0 = blockIdx.x * 128;

    int lm = tid >> 1;
    int lc = (tid & 1) * 2;
    const h16* aHs = Ah + (size_t)(row0 + lm) * K + lc * 8;
    const h16* aLs = ALO ? (Al + (size_t)(row0 + lm) * K + lc * 8) : nullptr;
    const h16* bHs = Bh + (size_t)(col0 + lm) * K + lc * 8;
    uint32_t dA = (uint32_t)(lm * ROWB + lc * 16);

    auto load_stage = [&](int p, int kt) {
        uint32_t s0 = sb + p * STB;
        size_t ko = (size_t)kt * 32;
        cp16(s0 + dA,             aHs + ko);
        cp16(s0 + dA + 16,        aHs + ko + 8);
        if (ALO) {
            cp16(s0 + MAT_BYTES + dA,      aLs + ko);
            cp16(s0 + MAT_BYTES + dA + 16, aLs + ko + 8);
        }
        cp16(s0 + BOFF + dA,      bHs + ko);
        cp16(s0 + BOFF + dA + 16, bHs + ko + 8);
    };

    int g = lane >> 3, r = lane & 7;
    uint32_t aoff = (uint32_t)((wm * 64 + (g & 1) * 8 + r) * ROWB + (g >> 1) * 16);
    uint32_t boff = (uint32_t)((wn * 32 + (g >> 1) * 8 + r) * ROWB + (g & 1) * 16);

    float acc[4][4][4];
    #pragma unroll
    for (int i = 0; i < 4; i++)
        #pragma unroll
        for (int j = 0; j < 4; j++)
            #pragma unroll
            for (int e = 0; e < 4; e++) acc[i][j][e] = 0.f;

    int KT = K / 32;
    load_stage(0, 0); CP_COMMIT();
    load_stage(1, 1); CP_COMMIT();
    load_stage(2, 2); CP_COMMIT();

    for (int kt = 0; kt < KT; kt++) {
        int s = kt % 3;
        asm volatile("cp.async.wait_group 2;" ::: "memory");
        __syncthreads();
        uint32_t st = sb + s * STB;
        #pragma unroll
        for (int h = 0; h < 2; h++) {
            uint32_t ah[4][4], bh[2][4];
            #pragma unroll
            for (int mt = 0; mt < 4; mt++)
                ldm4(ah[mt], st + aoff + mt * (16 * ROWB) + h * 32);
            #pragma unroll
            for (int nb = 0; nb < 2; nb++)
                ldm4(bh[nb], st + BOFF + boff + nb * (16 * ROWB) + h * 32);
            // term hh: 16 independent MMAs
            #pragma unroll
            for (int mt = 0; mt < 4; mt++)
                #pragma unroll
                for (int nt = 0; nt < 4; nt++)
                    mma_f16(acc[mt][nt], ah[mt],
                            bh[nt >> 1][(nt & 1) * 2], bh[nt >> 1][(nt & 1) * 2 + 1]);
            // term lh (A exactness)
            if (ALO) {
                uint32_t al[4][4];
                #pragma unroll
                for (int mt = 0; mt < 4; mt++)
                    ldm4(al[mt], st + MAT_BYTES + aoff + mt * (16 * ROWB) + h * 32);
                #pragma unroll
                for (int mt = 0; mt < 4; mt++)
                    #pragma unroll
                    for (int nt = 0; nt < 4; nt++)
                        mma_f16(acc[mt][nt], al[mt],
                                bh[nt >> 1][(nt & 1) * 2], bh[nt >> 1][(nt & 1) * 2 + 1]);
            }
        }
        __syncthreads();
        if (kt + 3 < KT) load_stage(s, kt + 3);
        CP_COMMIT();
    }

    // epilogue
    #pragma unroll
    for (int mt = 0; mt < 4; mt++) {
        int r_lo = row0 + wm * 64 + mt * 16 + (lane >> 2);
        #pragma unroll
        for (int nt = 0; nt < 4; nt++) {
            int col = col0 + wn * 32 + nt * 8 + (lane & 3) * 2;
            float* d = acc[mt][nt];
            float bi0 = 0.f, bi1 = 0.f;
            if (BIAS) { bi0 = __ldg(bias + col); bi1 = __ldg(bias + col + 1); }
            #pragma unroll
            for (int half = 0; half < 2; half++) {
                int row = r_lo + half * 8;
                float v0 = d[half * 2 + 0], v1 = d[half * 2 + 1];
                if (BIAS) { v0 += bi0; v1 += bi1; }
                if (RELU) { v0 = fmaxf(v0, 0.f); v1 = fmaxf(v1, 0.f); }
                size_t base = (size_t)row * N + col;
                if (RES) {
                    float2 rr = *(const float2*)(res + base);
                    v0 += rr.x; v1 += rr.y;
                }
                if (OUTF16) {
                    *(uint32_t*)(Ch + base) = pk2h(v0, v1);
                } else {
                    *(float2*)(Cf + base) = make_float2(v0, v1);
                }
            }
        }
    }
}
#define SMEM_GEMM_ALO (3 * 3 * MAT_BYTES)   // 92160
#define SMEM_GEMM_1T  (3 * 2 * MAT_BYTES)   // 61440

// ---------------- Tensor-core flash attention (all single fp16) -------------
// CTA: 128 q-rows x one head. 8 warps x 16 rows. 64-key chunks, double buffer,
// 2 CTAs/SM.
#define AROWB 144
#define A_V   9216
#define A_M   18432
#define A_STRIDE 18688
#define A_SMEM (2 * A_STRIDE)   // 37376

__global__ __launch_bounds__(256, 2) void attention_tc(
    const h16* __restrict__ qkvh, const int* __restrict__ mask,
    h16* __restrict__ oh)
{
    extern __shared__ char smem[];
    uint32_t sb = smem_to_u32(smem);
    int tid = threadIdx.x, lane = tid & 31, w = tid >> 5;
    int bh_ = blockIdx.y, b = bh_ >> 4, h = bh_ & 15;
    int q0 = blockIdx.x * 128;
    size_t hoff = (size_t)h * DKH;
    int g = lane >> 3, r = lane & 7;

    // ---- stage Q (hi only) ----
    {
        int lm = tid >> 1;
        int lc = (tid & 1) * 4;
        size_t go = (size_t)(b * S_ + q0 + lm) * QKVS + hoff + lc * 8;
        uint32_t d0 = sb + (uint32_t)(lm * AROWB + lc * 16);
        #pragma unroll
        for (int j = 0; j < 4; j++)
            cp16(d0 + j * 16, qkvh + go + j * 8);
        CP_COMMIT();
    }
    asm volatile("cp.async.wait_group 0;" ::: "memory");
    __syncthreads();

    uint32_t Qh4[4][4];
    {
        uint32_t aoff = sb + (uint32_t)((w * 16 + (g & 1) * 8 + r) * AROWB + (g >> 1) * 16);
        #pragma unroll
        for (int ks = 0; ks < 4; ks++)
            ldm4(Qh4[ks], aoff + ks * 32);
    }
    __syncthreads();

    float m0 = -1e30f, m1 = -1e30f, l0 = 0.f, l1 = 0.f;
    float acc[8][4];
    #pragma unroll
    for (int i = 0; i < 8; i++)
        #pragma unroll
        for (int e = 0; e < 4; e++) acc[i][e] = 0.f;

    const h16* kbh = qkvh + (size_t)b * S_ * QKVS + D_ + hoff;
    const h16* vb  = qkvh + (size_t)b * S_ * QKVS + 2 * D_ + hoff;
    const int* mrow = mask + (size_t)b * S_;

    auto load_chunk = [&](int c) {
        uint32_t stg = sb + (c & 1) * A_STRIDE;
        int lm = tid >> 2;
        int lc = (tid & 3) * 2;
        size_t go = (size_t)(c * 64 + lm) * QKVS + lc * 8;
        uint32_t d = stg + (uint32_t)(lm * AROWB + lc * 16);
        cp16(d,            kbh + go);
        cp16(d + 16,       kbh + go + 8);
        cp16(d + A_V,      vb + go);
        cp16(d + A_V + 16, vb + go + 8);
        if (tid < 64)
            asm volatile("cp.async.ca.shared.global [%0], [%1], 4;"
                :: "r"(stg + A_M + tid * 4), "l"(mrow + c * 64 + tid));
    };

    const int NC = S_ / 64;   // 32
    load_chunk(0); CP_COMMIT();
    load_chunk(1); CP_COMMIT();

    uint32_t bKoff = (uint32_t)(((g >> 1) * 8 + r) * AROWB + (g & 1) * 16);
    uint32_t vOff  = (uint32_t)(((g & 1) * 8 + r) * AROWB + (g >> 1) * 16);

    for (int c = 0; c < NC; c++) {
        if (c + 1 < NC) { asm volatile("cp.async.wait_group 1;" ::: "memory"); }
        else            { asm volatile("cp.async.wait_group 0;" ::: "memory"); }
        __syncthreads();
        uint32_t stg = sb + (c & 1) * A_STRIDE;

        float s[8][4];
        #pragma unroll
        for (int i = 0; i < 8; i++)
            #pragma unroll
            for (int e = 0; e < 4; e++) s[i][e] = 0.f;

        // S = Q K^T (single-term fp16)
        #pragma unroll
        for (int ks = 0; ks < 4; ks++) {
            #pragma unroll
            for (int nb = 0; nb < 4; nb++) {
                uint32_t bh4[4];
                ldm4(bh4, stg + bKoff + nb * (16 * AROWB) + ks * 32);
                mma_f16(s[nb*2],   Qh4[ks], bh4[0], bh4[1]);
                mma_f16(s[nb*2+1], Qh4[ks], bh4[2], bh4[3]);
            }
        }

        // scale + mask
        const int* ms = (const int*)(smem + (size_t)(c & 1) * A_STRIDE + A_M);
        #pragma unroll
        for (int nt = 0; nt < 8; nt++) {
            int cc = nt * 8 + (lane & 3) * 2;
            int mv0 = ms[cc], mv1 = ms[cc + 1];
            #pragma unroll
            for (int e = 0; e < 4; e++) s[nt][e] *= 0.125f;
            if (mv0 == 0) { s[nt][0] = -1e9f; s[nt][2] = -1e9f; }
            if (mv1 == 0) { s[nt][1] = -1e9f; s[nt][3] = -1e9f; }
        }

        // online softmax (rows r and r+8 per thread)
        float mx0 = -1e30f, mx1 = -1e30f;
        #pragma unroll
        for (int nt = 0; nt < 8; nt++) {
            mx0 = fmaxf(mx0, fmaxf(s[nt][0], s[nt][1]));
            mx1 = fmaxf(mx1, fmaxf(s[nt][2], s[nt][3]));
        }
        mx0 = fmaxf(mx0, __shfl_xor_sync(0xffffffffu, mx0, 1));
        mx0 = fmaxf(mx0, __shfl_xor_sync(0xffffffffu, mx0, 2));
        mx1 = fmaxf(mx1, __shfl_xor_sync(0xffffffffu, mx1, 1));
        mx1 = fmaxf(mx1, __shfl_xor_sync(0xffffffffu, mx1, 2));
        float mn0 = fmaxf(m0, mx0), mn1 = fmaxf(m1, mx1);
        float sc0 = __expf(m0 - mn0), sc1 = __expf(m1 - mn1);
        m0 = mn0; m1 = mn1;
        float rs0 = 0.f, rs1 = 0.f;
        #pragma unroll
        for (int nt = 0; nt < 8; nt++) {
            s[nt][0] = __expf(s[nt][0] - mn0); rs0 += s[nt][0];
            s[nt][1] = __expf(s[nt][1] - mn0); rs0 += s[nt][1];
            s[nt][2] = __expf(s[nt][2] - mn1); rs1 += s[nt][2];
            s[nt][3] = __expf(s[nt][3] - mn1); rs1 += s[nt][3];
        }
        rs0 += __shfl_xor_sync(0xffffffffu, rs0, 1);
        rs0 += __shfl_xor_sync(0xffffffffu, rs0, 2);
        rs1 += __shfl_xor_sync(0xffffffffu, rs1, 1);
        rs1 += __shfl_xor_sync(0xffffffffu, rs1, 2);
        l0 = l0 * sc0 + rs0;
        l1 = l1 * sc1 + rs1;
        #pragma unroll
        for (int no = 0; no < 8; no++) {
            acc[no][0] *= sc0; acc[no][1] *= sc0;
            acc[no][2] *= sc1; acc[no][3] *= sc1;
        }

        // O += P V   (P fragments repacked directly as A operand)
        #pragma unroll
        for (int kb = 0; kb < 4; kb++) {
            uint32_t a4[4];
            a4[0] = pk2h(s[kb*2][0],   s[kb*2][1]);
            a4[1] = pk2h(s[kb*2][2],   s[kb*2][3]);
            a4[2] = pk2h(s[kb*2+1][0], s[kb*2+1][1]);
            a4[3] = pk2h(s[kb*2+1][2], s[kb*2+1][3]);
            #pragma unroll
            for (int db = 0; db < 4; db++) {
                uint32_t bv[4];
                ldm4t(bv, stg + A_V + vOff + kb * (16 * AROWB) + db * 32);
                mma_f16(acc[db*2],   a4, bv[0], bv[1]);
                mma_f16(acc[db*2+1], a4, bv[2], bv[3]);
            }
        }

        __syncthreads();
        if (c + 2 < NC) { load_chunk(c + 2); CP_COMMIT(); }
    }

    // ---- output: O / l -> fp16 (hi only) ----
    float inv0 = 1.f / l0, inv1 = 1.f / l1;
    int row0 = q0 + w * 16 + (lane >> 2);
    size_t t0 = (size_t)(b * S_ + row0) * D_ + hoff;
    size_t t1 = t0 + (size_t)8 * D_;
    #pragma unroll
    for (int no = 0; no < 8; no++) {
        int cc = no * 8 + (lane & 3) * 2;
        *(uint32_t*)(oh + t0 + cc) = pk2h(acc[no][0] * inv0, acc[no][1] * inv0);
        *(uint32_t*)(oh + t1 + cc) = pk2h(acc[no][2] * inv1, acc[no][3] * inv1);
    }
}

// ---------------- launch ----------------------------------------------------
extern "C" void kernel_launch(void* const* d_in, const int* in_sizes, int n_in,
                              void* d_out, int out_size)
{
    (void)in_sizes; (void)n_in; (void)out_size;
    const float* x    = (const float*)d_in[0];
    const int*   mask = (const int*)  d_in[1];
    const float* wq   = (const float*)d_in[2];
    const float* wk   = (const float*)d_in[3];
    const float* wv   = (const float*)d_in[4];
    const float* wo   = (const float*)d_in[5];
    const float* w1   = (const float*)d_in[6];
    const float* b1   = (const float*)d_in[7];
    const float* w2   = (const float*)d_in[8];
    const float* b2   = (const float*)d_in[9];
    const float* g1   = (const float*)d_in[10];
    const float* be1  = (const float*)d_in[11];
    const float* g2   = (const float*)d_in[12];
    const float* be2  = (const float*)d_in[13];
    float* out = (float*)d_out;

    float *h1;
    h16 *zh, *zl, *qkvh, *ah, *mh;
    h16 *wc, *wop, *w1p, *w2p;
    cudaGetSymbolAddress((void**)&h1, g_h1);
    cudaGetSymbolAddress((void**)&zh, g_zh);     cudaGetSymbolAddress((void**)&zl, g_zl);
    cudaGetSymbolAddress((void**)&qkvh, g_qkvh);
    cudaGetSymbolAddress((void**)&ah, g_ah);
    cudaGetSymbolAddress((void**)&mh, g_mh);
    cudaGetSymbolAddress((void**)&wc, g_wc);
    cudaGetSymbolAddress((void**)&wop, g_wo);
    cudaGetSymbolAddress((void**)&w1p, g_w1);
    cudaGetSymbolAddress((void**)&w2p, g_w2);

    cudaFuncSetAttribute(tc_gemm<true ,false,false,false,true >, cudaFuncAttributeMaxDynamicSharedMemorySize, SMEM_GEMM_ALO);
    cudaFuncSetAttribute(tc_gemm<false,false,false,true ,false>, cudaFuncAttributeMaxDynamicSharedMemorySize, SMEM_GEMM_1T);
    cudaFuncSetAttribute(tc_gemm<true ,true ,true ,false,true >, cudaFuncAttributeMaxDynamicSharedMemorySize, SMEM_GEMM_ALO);
    cudaFuncSetAttribute(tc_gemm<false,false,true ,true ,false>, cudaFuncAttributeMaxDynamicSharedMemorySize, SMEM_GEMM_1T);
    cudaFuncSetAttribute(attention_tc, cudaFuncAttributeMaxDynamicSharedMemorySize, A_SMEM);

    // 1-2: weight conversions (2 launches)
    convert_qkv<<<3072, 256>>>(wq, wk, wv, wc);
    convert_rest<<<9216, 256>>>(wo, w1, w2, wop, w1p, w2p);

    // 3: LN1
    layernorm_kernel<<<NT, 256>>>(x, g1, be1, zh, zl);

    // 4: fused QKV GEMM (N = 3072, A 2-term) -> fp16
    dim3 gQKV(QKVS / 128, NT / 128);
    tc_gemm<true,false,false,false,true><<<gQKV, 256, SMEM_GEMM_ALO>>>(
        zh, zl, wc, nullptr, nullptr, nullptr, qkvh, NT, QKVS, D_);

    // 5: attention (tensor core, single fp16) -> fp16
    dim3 gAtt(S_ / 128, B_ * H_);
    attention_tc<<<gAtt, 256, A_SMEM>>>(qkvh, mask, ah);

    // 6: h1 = x + attn @ wo^T  (A single-term)   <- ncu -s5 captures this
    dim3 gP(D_ / 128, NT / 128);
    tc_gemm<false,false,false,true,false><<<gP, 256, SMEM_GEMM_1T>>>(
        ah, nullptr, wop, nullptr, x, h1, nullptr, NT, D_, D_);

    // 7: LN2
    layernorm_kernel<<<NT, 256>>>(h1, g2, be2, zh, zl);

    // 8: FFN1: mid = relu(z @ w1^T + b1)  (A 2-term) -> fp16
    dim3 gF1(DFF_ / 128, NT / 128);
    tc_gemm<true,true,true,false,true><<<gF1, 256, SMEM_GEMM_ALO>>>(
        zh, zl, w1p, b1, nullptr, nullptr, mh, NT, DFF_, D_);

    // 9: FFN2: out = h1 + mid @ w2^T + b2  (A single-term)
    dim3 gF2(D_ / 128, NT / 128);
    tc_gemm<false,false,true,true,false><<<gF2, 256, SMEM_GEMM_1T>>>(
        mh, nullptr, w2p, b2, h1, out, nullptr, NT, D_, DFF_);
}

// round 9
// speedup vs baseline: 5.6211x; 1.0309x over previous
#include <cuda_runtime.h>
#include <cuda_fp16.h>
#include <math.h>
#include <stdint.h>

// Problem dims
#define B_  4
#define S_  2048
#define D_  1024
#define H_  16
#define DKH 64
#define DFF_ 4096
#define NT  (B_ * S_)   // 8192 tokens
#define QKVS 3072       // fused qkv row stride

typedef __half h16;

// ====================== PTX helpers (baseline ISA, sm_80+) ==================
__device__ __forceinline__ uint32_t smem_to_u32(const void* p) {
    uint32_t a;
    asm("{ .reg .u64 t; cvta.to.shared.u64 t, %1; cvt.u32.u64 %0, t; }" : "=r"(a) : "l"(p));
    return a;
}
__device__ __forceinline__ void cp16(uint32_t dst, const void* src) {
    asm volatile("cp.async.cg.shared.global [%0], [%1], 16;" :: "r"(dst), "l"(src));
}
#define CP_COMMIT() asm volatile("cp.async.commit_group;" ::: "memory")

__device__ __forceinline__ void ldm4(uint32_t* r, uint32_t addr) {
    asm volatile("ldmatrix.sync.aligned.m8n8.x4.shared.b16 {%0,%1,%2,%3}, [%4];"
        : "=r"(r[0]), "=r"(r[1]), "=r"(r[2]), "=r"(r[3]) : "r"(addr));
}
__device__ __forceinline__ void ldm4t(uint32_t* r, uint32_t addr) {
    asm volatile("ldmatrix.sync.aligned.m8n8.x4.trans.shared.b16 {%0,%1,%2,%3}, [%4];"
        : "=r"(r[0]), "=r"(r[1]), "=r"(r[2]), "=r"(r[3]) : "r"(addr));
}
__device__ __forceinline__ void mma_f16(float* d, const uint32_t* a,
                                        uint32_t b0, uint32_t b1) {
    asm volatile(
        "mma.sync.aligned.m16n8k16.row.col.f32.f16.f16.f32 "
        "{%0,%1,%2,%3}, {%4,%5,%6,%7}, {%8,%9}, {%0,%1,%2,%3};"
        : "+f"(d[0]), "+f"(d[1]), "+f"(d[2]), "+f"(d[3])
        : "r"(a[0]), "r"(a[1]), "r"(a[2]), "r"(a[3]), "r"(b0), "r"(b1));
}

// ============ fp16 hi/lo split helpers ======================================
__device__ __forceinline__ uint32_t pk2h(float a, float b) {
    return (uint32_t)__half_as_ushort(__float2half_rn(a)) |
           ((uint32_t)__half_as_ushort(__float2half_rn(b)) << 16);
}
__device__ __forceinline__ float hres(float a) {
    return a - __half2float(__float2half_rn(a));
}

// ---------------- scratch (device globals) ----------------------------------
__device__ __align__(256) float g_h1[(size_t)NT * D_];
__device__ __align__(256) h16 g_zh[(size_t)NT * D_],  g_zl[(size_t)NT * D_];
__device__ __align__(256) h16 g_qkvh[(size_t)NT * QKVS];
__device__ __align__(256) h16 g_ah[(size_t)NT * D_];
__device__ __align__(256) h16 g_mh[(size_t)NT * DFF_];
__device__ __align__(256) h16 g_wc[(size_t)3*D_*D_];
__device__ __align__(256) h16 g_wo[(size_t)D_*D_];
__device__ __align__(256) h16 g_w1[(size_t)DFF_*D_];
__device__ __align__(256) h16 g_w2[(size_t)D_*DFF_];

// ---------------- fused weight converts (2 launches) ------------------------
__global__ __launch_bounds__(256) void convert_qkv(
    const float* __restrict__ wq, const float* __restrict__ wk,
    const float* __restrict__ wv, h16* __restrict__ wc)
{
    int seg = blockIdx.x >> 10;            // 0..2
    int i = (blockIdx.x & 1023) * 256 + threadIdx.x;
    const float* src = (seg == 0) ? wq : (seg == 1) ? wk : wv;
    float4 v = ((const float4*)src)[i];
    ((uint2*)(wc + (size_t)seg * D_ * D_))[i] =
        make_uint2(pk2h(v.x, v.y), pk2h(v.z, v.w));
}
__global__ __launch_bounds__(256) void convert_rest(
    const float* __restrict__ wo, const float* __restrict__ w1,
    const float* __restrict__ w2, h16* __restrict__ dwo,
    h16* __restrict__ dw1, h16* __restrict__ dw2)
{
    int bidx = blockIdx.x;
    const float* src; h16* dst; int i;
    if (bidx < 1024)       { src = wo; dst = dwo; i = bidx * 256 + threadIdx.x; }
    else if (bidx < 5120)  { src = w1; dst = dw1; i = (bidx - 1024) * 256 + threadIdx.x; }
    else                   { src = w2; dst = dw2; i = (bidx - 5120) * 256 + threadIdx.x; }
    float4 v = ((const float4*)src)[i];
    ((uint2*)dst)[i] = make_uint2(pk2h(v.x, v.y), pk2h(v.z, v.w));
}

// ---------------- LayerNorm (Bessel ddof=1, eps=1e-9) -> fp16 hi/lo ---------
__global__ __launch_bounds__(256) void layernorm_kernel(
    const float* __restrict__ x, const float* __restrict__ gamma,
    const float* __restrict__ beta, h16* __restrict__ yh, h16* __restrict__ yl)
{
    int row = blockIdx.x;
    int t = threadIdx.x;
    const float4* xr = (const float4*)(x + (size_t)row * D_);
    float4 v = xr[t];
    float s  = v.x + v.y + v.z + v.w;
    float ss = v.x*v.x + v.y*v.y + v.z*v.z + v.w*v.w;
    #pragma unroll
    for (int o = 16; o > 0; o >>= 1) {
        s  += __shfl_xor_sync(0xffffffffu, s,  o);
        ss += __shfl_xor_sync(0xffffffffu, ss, o);
    }
    __shared__ float shs[8], shq[8];
    int w = t >> 5, l = t & 31;
    if (l == 0) { shs[w] = s; shq[w] = ss; }
    __syncthreads();
    float S = 0.f, Q = 0.f;
    #pragma unroll
    for (int i = 0; i < 8; i++) { S += shs[i]; Q += shq[i]; }
    float mean = S * (1.f / (float)D_);
    float var  = (Q - (float)D_ * mean * mean) * (1.f / (float)(D_ - 1));
    float inv  = rsqrtf(var + 1e-9f);
    const float4 g  = ((const float4*)gamma)[t];
    const float4 be = ((const float4*)beta)[t];
    float o0 = g.x * (v.x - mean) * inv + be.x;
    float o1 = g.y * (v.y - mean) * inv + be.y;
    float o2 = g.z * (v.z - mean) * inv + be.z;
    float o3 = g.w * (v.w - mean) * inv + be.w;
    size_t idx = (size_t)row * (D_/4) + t;
    ((uint2*)yh)[idx] = make_uint2(pk2h(o0, o1), pk2h(o2, o3));
    ((uint2*)yl)[idx] = make_uint2(pk2h(hres(o0), hres(o1)), pk2h(hres(o2), hres(o3)));
}

// ---------------- mma.sync fp16 GEMM (A optionally exact via hi/lo) ---------
// 128x128x64 CTA K-chunk, 256 threads (8 warps, 2m x 4n), 2-stage cp.async,
// 2 CTAs/SM, XOR-swizzled smem (128B rows, no pad). Term-outer MMA order.
#define MATB 16384   // 128 rows x 128 bytes

template<bool ALO, bool RELU, bool BIAS, bool RES, bool OUTF16>
__global__ __launch_bounds__(256, 2) void tc_gemm(
    const h16* __restrict__ Ah, const h16* __restrict__ Al,
    const h16* __restrict__ Bh,
    const float* __restrict__ bias, const float* __restrict__ res,
    float* __restrict__ Cf, h16* __restrict__ Ch,
    int M, int N, int K)
{
    constexpr int STB  = (ALO ? 3 : 2) * MATB;   // stage bytes
    constexpr int BOFF = (ALO ? 2 : 1) * MATB;   // B offset within stage
    extern __shared__ char smem[];
    uint32_t sb = smem_to_u32(smem);
    int tid = threadIdx.x;
    int lane = tid & 31, wid = tid >> 5;
    int wm = wid & 1, wn = wid >> 1;
    int row0 = blockIdx.y * 128, col0 = blockIdx.x * 128;

    // ---- loader mapping: row lm (0..127), half lc (0/1 = 64B each) ----
    int lm = tid >> 1;
    int lc = tid & 1;
    const h16* aHs = Ah + (size_t)(row0 + lm) * K + lc * 32;
    const h16* aLs = ALO ? (Al + (size_t)(row0 + lm) * K + lc * 32) : nullptr;
    const h16* bHs = Bh + (size_t)(col0 + lm) * K + lc * 32;
    uint32_t dRow = (uint32_t)(lm << 7);
    uint32_t dCol[4];
    #pragma unroll
    for (int j = 0; j < 4; j++)
        dCol[j] = (uint32_t)(((lc * 64 + j * 16) ^ ((lm & 7) << 4)));

    auto load_stage = [&](int p, int kt) {
        uint32_t s0 = sb + p * STB + dRow;
        size_t ko = (size_t)kt * 64;
        #pragma unroll
        for (int j = 0; j < 4; j++) cp16(s0 + dCol[j], aHs + ko + j * 8);
        if (ALO) {
            #pragma unroll
            for (int j = 0; j < 4; j++) cp16(s0 + MATB + dCol[j], aLs + ko + j * 8);
        }
        #pragma unroll
        for (int j = 0; j < 4; j++) cp16(s0 + BOFF + dCol[j], bHs + ko + j * 8);
    };

    // ---- ldmatrix per-lane offsets (swizzle term = r*16, lane-constant) ----
    int g = lane >> 3, r = lane & 7;
    uint32_t aRow[4], bRow[2];
    #pragma unroll
    for (int mt = 0; mt < 4; mt++)
        aRow[mt] = (uint32_t)((wm * 64 + mt * 16 + (g & 1) * 8 + r) << 7);
    #pragma unroll
    for (int nb = 0; nb < 2; nb++)
        bRow[nb] = (uint32_t)((wn * 32 + nb * 16 + (g >> 1) * 8 + r) << 7);
    uint32_t aColSw[4], bColSw[4];
    #pragma unroll
    for (int h = 0; h < 4; h++) {
        aColSw[h] = (uint32_t)(((h << 5) + ((g >> 1) << 4)) ^ (r << 4));
        bColSw[h] = (uint32_t)(((h << 5) + ((g & 1) << 4)) ^ (r << 4));
    }

    float acc[4][4][4];
    #pragma unroll
    for (int i = 0; i < 4; i++)
        #pragma unroll
        for (int j = 0; j < 4; j++)
            #pragma unroll
            for (int e = 0; e < 4; e++) acc[i][j][e] = 0.f;

    int KT = K / 64;
    load_stage(0, 0); CP_COMMIT();
    load_stage(1, 1); CP_COMMIT();

    for (int kt = 0; kt < KT; kt++) {
        int s = kt & 1;
        asm volatile("cp.async.wait_group 1;" ::: "memory");
        __syncthreads();
        uint32_t st = sb + s * STB;
        #pragma unroll
        for (int h = 0; h < 4; h++) {
            uint32_t ah[4][4], bh[2][4];
            #pragma unroll
            for (int mt = 0; mt < 4; mt++)
                ldm4(ah[mt], st + aRow[mt] + aColSw[h]);
            #pragma unroll
            for (int nb = 0; nb < 2; nb++)
                ldm4(bh[nb], st + BOFF + bRow[nb] + bColSw[h]);
            // term hh: 16 independent MMAs
            #pragma unroll
            for (int mt = 0; mt < 4; mt++)
                #pragma unroll
                for (int nt = 0; nt < 4; nt++)
                    mma_f16(acc[mt][nt], ah[mt],
                            bh[nt >> 1][(nt & 1) * 2], bh[nt >> 1][(nt & 1) * 2 + 1]);
            // term lh (A exactness)
            if (ALO) {
                uint32_t al[4][4];
                #pragma unroll
                for (int mt = 0; mt < 4; mt++)
                    ldm4(al[mt], st + MATB + aRow[mt] + aColSw[h]);
                #pragma unroll
                for (int mt = 0; mt < 4; mt++)
                    #pragma unroll
                    for (int nt = 0; nt < 4; nt++)
                        mma_f16(acc[mt][nt], al[mt],
                                bh[nt >> 1][(nt & 1) * 2], bh[nt >> 1][(nt & 1) * 2 + 1]);
            }
        }
        __syncthreads();
        if (kt + 2 < KT) load_stage(s, kt + 2);
        CP_COMMIT();
    }

    // epilogue
    #pragma unroll
    for (int mt = 0; mt < 4; mt++) {
        int r_lo = row0 + wm * 64 + mt * 16 + (lane >> 2);
        #pragma unroll
        for (int nt = 0; nt < 4; nt++) {
            int col = col0 + wn * 32 + nt * 8 + (lane & 3) * 2;
            float* d = acc[mt][nt];
            float bi0 = 0.f, bi1 = 0.f;
            if (BIAS) { bi0 = __ldg(bias + col); bi1 = __ldg(bias + col + 1); }
            #pragma unroll
            for (int half = 0; half < 2; half++) {
                int row = r_lo + half * 8;
                float v0 = d[half * 2 + 0], v1 = d[half * 2 + 1];
                if (BIAS) { v0 += bi0; v1 += bi1; }
                if (RELU) { v0 = fmaxf(v0, 0.f); v1 = fmaxf(v1, 0.f); }
                size_t base = (size_t)row * N + col;
                if (RES) {
                    float2 rr = *(const float2*)(res + base);
                    v0 += rr.x; v1 += rr.y;
                }
                if (OUTF16) {
                    *(uint32_t*)(Ch + base) = pk2h(v0, v1);
                } else {
                    *(float2*)(Cf + base) = make_float2(v0, v1);
                }
            }
        }
    }
}
#define SMEM_GEMM_ALO (2 * 3 * MATB)   // 98304
#define SMEM_GEMM_1T  (2 * 2 * MATB)   // 65536

// ---------------- Tensor-core flash attention (all single fp16) -------------
// CTA: 128 q-rows x one head. 8 warps x 16 rows. 64-key chunks, double buffer,
// 2 CTAs/SM.
#define AROWB 144
#define A_V   9216
#define A_M   18432
#define A_STRIDE 18688
#define A_SMEM (2 * A_STRIDE)   // 37376

__global__ __launch_bounds__(256, 2) void attention_tc(
    const h16* __restrict__ qkvh, const int* __restrict__ mask,
    h16* __restrict__ oh)
{
    extern __shared__ char smem[];
    uint32_t sb = smem_to_u32(smem);
    int tid = threadIdx.x, lane = tid & 31, w = tid >> 5;
    int bh_ = blockIdx.y, b = bh_ >> 4, h = bh_ & 15;
    int q0 = blockIdx.x * 128;
    size_t hoff = (size_t)h * DKH;
    int g = lane >> 3, r = lane & 7;

    // ---- stage Q (hi only) ----
    {
        int lm = tid >> 1;
        int lc = (tid & 1) * 4;
        size_t go = (size_t)(b * S_ + q0 + lm) * QKVS + hoff + lc * 8;
        uint32_t d0 = sb + (uint32_t)(lm * AROWB + lc * 16);
        #pragma unroll
        for (int j = 0; j < 4; j++)
            cp16(d0 + j * 16, qkvh + go + j * 8);
        CP_COMMIT();
    }
    asm volatile("cp.async.wait_group 0;" ::: "memory");
    __syncthreads();

    uint32_t Qh4[4][4];
    {
        uint32_t aoff = sb + (uint32_t)((w * 16 + (g & 1) * 8 + r) * AROWB + (g >> 1) * 16);
        #pragma unroll
        for (int ks = 0; ks < 4; ks++)
            ldm4(Qh4[ks], aoff + ks * 32);
    }
    __syncthreads();

    float m0 = -1e30f, m1 = -1e30f, l0 = 0.f, l1 = 0.f;
    float acc[8][4];
    #pragma unroll
    for (int i = 0; i < 8; i++)
        #pragma unroll
        for (int e = 0; e < 4; e++) acc[i][e] = 0.f;

    const h16* kbh = qkvh + (size_t)b * S_ * QKVS + D_ + hoff;
    const h16* vb  = qkvh + (size_t)b * S_ * QKVS + 2 * D_ + hoff;
    const int* mrow = mask + (size_t)b * S_;

    auto load_chunk = [&](int c) {
        uint32_t stg = sb + (c & 1) * A_STRIDE;
        int lm = tid >> 2;
        int lc = (tid & 3) * 2;
        size_t go = (size_t)(c * 64 + lm) * QKVS + lc * 8;
        uint32_t d = stg + (uint32_t)(lm * AROWB + lc * 16);
        cp16(d,            kbh + go);
        cp16(d + 16,       kbh + go + 8);
        cp16(d + A_V,      vb + go);
        cp16(d + A_V + 16, vb + go + 8);
        if (tid < 64)
            asm volatile("cp.async.ca.shared.global [%0], [%1], 4;"
                :: "r"(stg + A_M + tid * 4), "l"(mrow + c * 64 + tid));
    };

    const int NC = S_ / 64;   // 32
    load_chunk(0); CP_COMMIT();
    load_chunk(1); CP_COMMIT();

    uint32_t bKoff = (uint32_t)(((g >> 1) * 8 + r) * AROWB + (g & 1) * 16);
    uint32_t vOff  = (uint32_t)(((g & 1) * 8 + r) * AROWB + (g >> 1) * 16);

    for (int c = 0; c < NC; c++) {
        if (c + 1 < NC) { asm volatile("cp.async.wait_group 1;" ::: "memory"); }
        else            { asm volatile("cp.async.wait_group 0;" ::: "memory"); }
        __syncthreads();
        uint32_t stg = sb + (c & 1) * A_STRIDE;

        float s[8][4];
        #pragma unroll
        for (int i = 0; i < 8; i++)
            #pragma unroll
            for (int e = 0; e < 4; e++) s[i][e] = 0.f;

        // S = Q K^T (single-term fp16)
        #pragma unroll
        for (int ks = 0; ks < 4; ks++) {
            #pragma unroll
            for (int nb = 0; nb < 4; nb++) {
                uint32_t bh4[4];
                ldm4(bh4, stg + bKoff + nb * (16 * AROWB) + ks * 32);
                mma_f16(s[nb*2],   Qh4[ks], bh4[0], bh4[1]);
                mma_f16(s[nb*2+1], Qh4[ks], bh4[2], bh4[3]);
            }
        }

        // scale + mask
        const int* ms = (const int*)(smem + (size_t)(c & 1) * A_STRIDE + A_M);
        #pragma unroll
        for (int nt = 0; nt < 8; nt++) {
            int cc = nt * 8 + (lane & 3) * 2;
            int mv0 = ms[cc], mv1 = ms[cc + 1];
            #pragma unroll
            for (int e = 0; e < 4; e++) s[nt][e] *= 0.125f;
            if (mv0 == 0) { s[nt][0] = -1e9f; s[nt][2] = -1e9f; }
            if (mv1 == 0) { s[nt][1] = -1e9f; s[nt][3] = -1e9f; }
        }

        // online softmax (rows r and r+8 per thread)
        float mx0 = -1e30f, mx1 = -1e30f;
        #pragma unroll
        for (int nt = 0; nt < 8; nt++) {
            mx0 = fmaxf(mx0, fmaxf(s[nt][0], s[nt][1]));
            mx1 = fmaxf(mx1, fmaxf(s[nt][2], s[nt][3]));
        }
        mx0 = fmaxf(mx0, __shfl_xor_sync(0xffffffffu, mx0, 1));
        mx0 = fmaxf(mx0, __shfl_xor_sync(0xffffffffu, mx0, 2));
        mx1 = fmaxf(mx1, __shfl_xor_sync(0xffffffffu, mx1, 1));
        mx1 = fmaxf(mx1, __shfl_xor_sync(0xffffffffu, mx1, 2));
        float mn0 = fmaxf(m0, mx0), mn1 = fmaxf(m1, mx1);
        float sc0 = __expf(m0 - mn0), sc1 = __expf(m1 - mn1);
        m0 = mn0; m1 = mn1;
        float rs0 = 0.f, rs1 = 0.f;
        #pragma unroll
        for (int nt = 0; nt < 8; nt++) {
            s[nt][0] = __expf(s[nt][0] - mn0); rs0 += s[nt][0];
            s[nt][1] = __expf(s[nt][1] - mn0); rs0 += s[nt][1];
            s[nt][2] = __expf(s[nt][2] - mn1); rs1 += s[nt][2];
            s[nt][3] = __expf(s[nt][3] - mn1); rs1 += s[nt][3];
        }
        rs0 += __shfl_xor_sync(0xffffffffu, rs0, 1);
        rs0 += __shfl_xor_sync(0xffffffffu, rs0, 2);
        rs1 += __shfl_xor_sync(0xffffffffu, rs1, 1);
        rs1 += __shfl_xor_sync(0xffffffffu, rs1, 2);
        l0 = l0 * sc0 + rs0;
        l1 = l1 * sc1 + rs1;
        #pragma unroll
        for (int no = 0; no < 8; no++) {
            acc[no][0] *= sc0; acc[no][1] *= sc0;
            acc[no][2] *= sc1; acc[no][3] *= sc1;
        }

        // O += P V   (P fragments repacked directly as A operand)
        #pragma unroll
        for (int kb = 0; kb < 4; kb++) {
            uint32_t a4[4];
            a4[0] = pk2h(s[kb*2][0],   s[kb*2][1]);
            a4[1] = pk2h(s[kb*2][2],   s[kb*2][3]);
            a4[2] = pk2h(s[kb*2+1][0], s[kb*2+1][1]);
            a4[3] = pk2h(s[kb*2+1][2], s[kb*2+1][3]);
            #pragma unroll
            for (int db = 0; db < 4; db++) {
                uint32_t bv[4];
                ldm4t(bv, stg + A_V + vOff + kb * (16 * AROWB) + db * 32);
                mma_f16(acc[db*2],   a4, bv[0], bv[1]);
                mma_f16(acc[db*2+1], a4, bv[2], bv[3]);
            }
        }

        __syncthreads();
        if (c + 2 < NC) { load_chunk(c + 2); CP_COMMIT(); }
    }

    // ---- output: O / l -> fp16 (hi only) ----
    float inv0 = 1.f / l0, inv1 = 1.f / l1;
    int row0 = q0 + w * 16 + (lane >> 2);
    size_t t0 = (size_t)(b * S_ + row0) * D_ + hoff;
    size_t t1 = t0 + (size_t)8 * D_;
    #pragma unroll
    for (int no = 0; no < 8; no++) {
        int cc = no * 8 + (lane & 3) * 2;
        *(uint32_t*)(oh + t0 + cc) = pk2h(acc[no][0] * inv0, acc[no][1] * inv0);
        *(uint32_t*)(oh + t1 + cc) = pk2h(acc[no][2] * inv1, acc[no][3] * inv1);
    }
}

// ---------------- launch ----------------------------------------------------
extern "C" void kernel_launch(void* const* d_in, const int* in_sizes, int n_in,
                              void* d_out, int out_size)
{
    (void)in_sizes; (void)n_in; (void)out_size;
    const float* x    = (const float*)d_in[0];
    const int*   mask = (const int*)  d_in[1];
    const float* wq   = (const float*)d_in[2];
    const float* wk   = (const float*)d_in[3];
    const float* wv   = (const float*)d_in[4];
    const float* wo   = (const float*)d_in[5];
    const float* w1   = (const float*)d_in[6];
    const float* b1   = (const float*)d_in[7];
    const float* w2   = (const float*)d_in[8];
    const float* b2   = (const float*)d_in[9];
    const float* g1   = (const float*)d_in[10];
    const float* be1  = (const float*)d_in[11];
    const float* g2   = (const float*)d_in[12];
    const float* be2  = (const float*)d_in[13];
    float* out = (float*)d_out;

    float *h1;
    h16 *zh, *zl, *qkvh, *ah, *mh;
    h16 *wc, *wop, *w1p, *w2p;
    cudaGetSymbolAddress((void**)&h1, g_h1);
    cudaGetSymbolAddress((void**)&zh, g_zh);     cudaGetSymbolAddress((void**)&zl, g_zl);
    cudaGetSymbolAddress((void**)&qkvh, g_qkvh);
    cudaGetSymbolAddress((void**)&ah, g_ah);
    cudaGetSymbolAddress((void**)&mh, g_mh);
    cudaGetSymbolAddress((void**)&wc, g_wc);
    cudaGetSymbolAddress((void**)&wop, g_wo);
    cudaGetSymbolAddress((void**)&w1p, g_w1);
    cudaGetSymbolAddress((void**)&w2p, g_w2);

    cudaFuncSetAttribute(tc_gemm<true ,false,false,false,true >, cudaFuncAttributeMaxDynamicSharedMemorySize, SMEM_GEMM_ALO);
    cudaFuncSetAttribute(tc_gemm<false,false,false,true ,false>, cudaFuncAttributeMaxDynamicSharedMemorySize, SMEM_GEMM_1T);
    cudaFuncSetAttribute(tc_gemm<true ,true ,true ,false,true >, cudaFuncAttributeMaxDynamicSharedMemorySize, SMEM_GEMM_ALO);
    cudaFuncSetAttribute(tc_gemm<false,false,true ,true ,false>, cudaFuncAttributeMaxDynamicSharedMemorySize, SMEM_GEMM_1T);
    cudaFuncSetAttribute(attention_tc, cudaFuncAttributeMaxDynamicSharedMemorySize, A_SMEM);

    // 1-2: weight conversions
    convert_qkv<<<3072, 256>>>(wq, wk, wv, wc);
    convert_rest<<<9216, 256>>>(wo, w1, w2, wop, w1p, w2p);

    // 3: LN1
    layernorm_kernel<<<NT, 256>>>(x, g1, be1, zh, zl);

    // 4: fused QKV GEMM (N = 3072, A 2-term) -> fp16
    dim3 gQKV(QKVS / 128, NT / 128);
    tc_gemm<true,false,false,false,true><<<gQKV, 256, SMEM_GEMM_ALO>>>(
        zh, zl, wc, nullptr, nullptr, nullptr, qkvh, NT, QKVS, D_);

    // 5: attention (tensor core, single fp16) -> fp16
    dim3 gAtt(S_ / 128, B_ * H_);
    attention_tc<<<gAtt, 256, A_SMEM>>>(qkvh, mask, ah);

    // 6: h1 = x + attn @ wo^T  (A single-term)
    dim3 gP(D_ / 128, NT / 128);
    tc_gemm<false,false,false,true,false><<<gP, 256, SMEM_GEMM_1T>>>(
        ah, nullptr, wop, nullptr, x, h1, nullptr, NT, D_, D_);

    // 7: LN2
    layernorm_kernel<<<NT, 256>>>(h1, g2, be2, zh, zl);

    // 8: FFN1: mid = relu(z @ w1^T + b1)  (A 2-term) -> fp16
    dim3 gF1(DFF_ / 128, NT / 128);
    tc_gemm<true,true,true,false,true><<<gF1, 256, SMEM_GEMM_ALO>>>(
        zh, zl, w1p, b1, nullptr, nullptr, mh, NT, DFF_, D_);

    // 9: FFN2: out = h1 + mid @ w2^T + b2  (A single-term)
    dim3 gF2(D_ / 128, NT / 128);
    tc_gemm<false,false,true,true,false><<<gF2, 256, SMEM_GEMM_1T>>>(
        mh, nullptr, w2p, b2, h1, out, nullptr, NT, D_, DFF_);
}

// round 10
// speedup vs baseline: 7.1605x; 1.2739x over previous
#include <cuda_runtime.h>
#include <cuda_fp16.h>
#include <math.h>
#include <stdint.h>

// Problem dims
#define B_  4
#define S_  2048
#define D_  1024
#define H_  16
#define DKH 64
#define DFF_ 4096
#define NT  (B_ * S_)   // 8192 tokens
#define QKVS 3072       // fused qkv row stride

typedef __half h16;

// ====================== PTX helpers (baseline ISA, sm_80+) ==================
__device__ __forceinline__ uint32_t smem_to_u32(const void* p) {
    uint32_t a;
    asm("{ .reg .u64 t; cvta.to.shared.u64 t, %1; cvt.u32.u64 %0, t; }" : "=r"(a) : "l"(p));
    return a;
}
__device__ __forceinline__ void cp16(uint32_t dst, const void* src) {
    asm volatile("cp.async.cg.shared.global [%0], [%1], 16;" :: "r"(dst), "l"(src));
}
#define CP_COMMIT() asm volatile("cp.async.commit_group;" ::: "memory")

__device__ __forceinline__ void ldm4(uint32_t* r, uint32_t addr) {
    asm volatile("ldmatrix.sync.aligned.m8n8.x4.shared.b16 {%0,%1,%2,%3}, [%4];"
        : "=r"(r[0]), "=r"(r[1]), "=r"(r[2]), "=r"(r[3]) : "r"(addr));
}
__device__ __forceinline__ void ldm4t(uint32_t* r, uint32_t addr) {
    asm volatile("ldmatrix.sync.aligned.m8n8.x4.trans.shared.b16 {%0,%1,%2,%3}, [%4];"
        : "=r"(r[0]), "=r"(r[1]), "=r"(r[2]), "=r"(r[3]) : "r"(addr));
}
__device__ __forceinline__ void mma_f16(float* d, const uint32_t* a,
                                        uint32_t b0, uint32_t b1) {
    asm volatile(
        "mma.sync.aligned.m16n8k16.row.col.f32.f16.f16.f32 "
        "{%0,%1,%2,%3}, {%4,%5,%6,%7}, {%8,%9}, {%0,%1,%2,%3};"
        : "+f"(d[0]), "+f"(d[1]), "+f"(d[2]), "+f"(d[3])
        : "r"(a[0]), "r"(a[1]), "r"(a[2]), "r"(a[3]), "r"(b0), "r"(b1));
}

__device__ __forceinline__ uint32_t pk2h(float a, float b) {
    return (uint32_t)__half_as_ushort(__float2half_rn(a)) |
           ((uint32_t)__half_as_ushort(__float2half_rn(b)) << 16);
}

// ---------------- scratch (device globals) ----------------------------------
__device__ __align__(256) float g_h1[(size_t)NT * D_];
__device__ __align__(256) h16 g_zh[(size_t)NT * D_];
__device__ __align__(256) h16 g_qkvh[(size_t)NT * QKVS];
__device__ __align__(256) h16 g_ah[(size_t)NT * D_];
__device__ __align__(256) h16 g_mh[(size_t)NT * DFF_];
__device__ __align__(256) h16 g_wc[(size_t)3*D_*D_];
__device__ __align__(256) h16 g_wo[(size_t)D_*D_];
__device__ __align__(256) h16 g_w1[(size_t)DFF_*D_];
__device__ __align__(256) h16 g_w2[(size_t)D_*DFF_];

// ---------------- fused weight converts (2 launches) ------------------------
__global__ __launch_bounds__(256) void convert_qkv(
    const float* __restrict__ wq, const float* __restrict__ wk,
    const float* __restrict__ wv, h16* __restrict__ wc)
{
    int seg = blockIdx.x >> 10;            // 0..2
    int i = (blockIdx.x & 1023) * 256 + threadIdx.x;
    const float* src = (seg == 0) ? wq : (seg == 1) ? wk : wv;
    float4 v = ((const float4*)src)[i];
    ((uint2*)(wc + (size_t)seg * D_ * D_))[i] =
        make_uint2(pk2h(v.x, v.y), pk2h(v.z, v.w));
}
__global__ __launch_bounds__(256) void convert_rest(
    const float* __restrict__ wo, const float* __restrict__ w1,
    const float* __restrict__ w2, h16* __restrict__ dwo,
    h16* __restrict__ dw1, h16* __restrict__ dw2)
{
    int bidx = blockIdx.x;
    const float* src; h16* dst; int i;
    if (bidx < 1024)       { src = wo; dst = dwo; i = bidx * 256 + threadIdx.x; }
    else if (bidx < 5120)  { src = w1; dst = dw1; i = (bidx - 1024) * 256 + threadIdx.x; }
    else                   { src = w2; dst = dw2; i = (bidx - 5120) * 256 + threadIdx.x; }
    float4 v = ((const float4*)src)[i];
    ((uint2*)dst)[i] = make_uint2(pk2h(v.x, v.y), pk2h(v.z, v.w));
}

// ---------------- LayerNorm (Bessel ddof=1, eps=1e-9) -> fp16 ---------------
__global__ __launch_bounds__(256) void layernorm_kernel(
    const float* __restrict__ x, const float* __restrict__ gamma,
    const float* __restrict__ beta, h16* __restrict__ yh)
{
    int row = blockIdx.x;
    int t = threadIdx.x;
    const float4* xr = (const float4*)(x + (size_t)row * D_);
    float4 v = xr[t];
    float s  = v.x + v.y + v.z + v.w;
    float ss = v.x*v.x + v.y*v.y + v.z*v.z + v.w*v.w;
    #pragma unroll
    for (int o = 16; o > 0; o >>= 1) {
        s  += __shfl_xor_sync(0xffffffffu, s,  o);
        ss += __shfl_xor_sync(0xffffffffu, ss, o);
    }
    __shared__ float shs[8], shq[8];
    int w = t >> 5, l = t & 31;
    if (l == 0) { shs[w] = s; shq[w] = ss; }
    __syncthreads();
    float S = 0.f, Q = 0.f;
    #pragma unroll
    for (int i = 0; i < 8; i++) { S += shs[i]; Q += shq[i]; }
    float mean = S * (1.f / (float)D_);
    float var  = (Q - (float)D_ * mean * mean) * (1.f / (float)(D_ - 1));
    float inv  = rsqrtf(var + 1e-9f);
    const float4 g  = ((const float4*)gamma)[t];
    const float4 be = ((const float4*)beta)[t];
    float o0 = g.x * (v.x - mean) * inv + be.x;
    float o1 = g.y * (v.y - mean) * inv + be.y;
    float o2 = g.z * (v.z - mean) * inv + be.z;
    float o3 = g.w * (v.w - mean) * inv + be.w;
    size_t idx = (size_t)row * (D_/4) + t;
    ((uint2*)yh)[idx] = make_uint2(pk2h(o0, o1), pk2h(o2, o3));
}

// ---------------- mma.sync fp16 single-term GEMM ----------------------------
// 128x128x64 CTA K-chunk, 256 threads (8 warps, 2m x 4n), 2-stage cp.async,
// 2 CTAs/SM, XOR-swizzled smem (128B rows, no pad).
#define MATB 16384   // 128 rows x 128 bytes
#define STB  (2 * MATB)
#define SMEM_GEMM (2 * STB)   // 65536

template<bool RELU, bool BIAS, bool RES, bool OUTF16>
__global__ __launch_bounds__(256, 2) void tc_gemm(
    const h16* __restrict__ Ah, const h16* __restrict__ Bh,
    const float* __restrict__ bias, const float* __restrict__ res,
    float* __restrict__ Cf, h16* __restrict__ Ch,
    int M, int N, int K)
{
    extern __shared__ char smem[];
    uint32_t sb = smem_to_u32(smem);
    int tid = threadIdx.x;
    int lane = tid & 31, wid = tid >> 5;
    int wm = wid & 1, wn = wid >> 1;
    int row0 = blockIdx.y * 128, col0 = blockIdx.x * 128;

    // ---- loader mapping: row lm (0..127), half lc (0/1 = 64B each) ----
    int lm = tid >> 1;
    int lc = tid & 1;
    const h16* aHs = Ah + (size_t)(row0 + lm) * K + lc * 32;
    const h16* bHs = Bh + (size_t)(col0 + lm) * K + lc * 32;
    uint32_t dRow = (uint32_t)(lm << 7);
    uint32_t dCol[4];
    #pragma unroll
    for (int j = 0; j < 4; j++)
        dCol[j] = (uint32_t)(((lc * 64 + j * 16) ^ ((lm & 7) << 4)));

    auto load_stage = [&](int p, int kt) {
        uint32_t s0 = sb + p * STB + dRow;
        size_t ko = (size_t)kt * 64;
        #pragma unroll
        for (int j = 0; j < 4; j++) cp16(s0 + dCol[j], aHs + ko + j * 8);
        #pragma unroll
        for (int j = 0; j < 4; j++) cp16(s0 + MATB + dCol[j], bHs + ko + j * 8);
    };

    // ---- ldmatrix per-lane offsets (swizzle term = r*16, lane-constant) ----
    int g = lane >> 3, r = lane & 7;
    uint32_t aRow[4], bRow[2];
    #pragma unroll
    for (int mt = 0; mt < 4; mt++)
        aRow[mt] = (uint32_t)((wm * 64 + mt * 16 + (g & 1) * 8 + r) << 7);
    #pragma unroll
    for (int nb = 0; nb < 2; nb++)
        bRow[nb] = (uint32_t)((wn * 32 + nb * 16 + (g >> 1) * 8 + r) << 7);
    uint32_t aColSw[4], bColSw[4];
    #pragma unroll
    for (int h = 0; h < 4; h++) {
        aColSw[h] = (uint32_t)(((h << 5) + ((g >> 1) << 4)) ^ (r << 4));
        bColSw[h] = (uint32_t)(((h << 5) + ((g & 1) << 4)) ^ (r << 4));
    }

    float acc[4][4][4];
    #pragma unroll
    for (int i = 0; i < 4; i++)
        #pragma unroll
        for (int j = 0; j < 4; j++)
            #pragma unroll
            for (int e = 0; e < 4; e++) acc[i][j][e] = 0.f;

    int KT = K / 64;
    load_stage(0, 0); CP_COMMIT();
    load_stage(1, 1); CP_COMMIT();

    for (int kt = 0; kt < KT; kt++) {
        int s = kt & 1;
        asm volatile("cp.async.wait_group 1;" ::: "memory");
        __syncthreads();
        uint32_t st = sb + s * STB;
        #pragma unroll
        for (int h = 0; h < 4; h++) {
            uint32_t ah[4][4], bh[2][4];
            #pragma unroll
            for (int mt = 0; mt < 4; mt++)
                ldm4(ah[mt], st + aRow[mt] + aColSw[h]);
            #pragma unroll
            for (int nb = 0; nb < 2; nb++)
                ldm4(bh[nb], st + MATB + bRow[nb] + bColSw[h]);
            #pragma unroll
            for (int mt = 0; mt < 4; mt++)
                #pragma unroll
                for (int nt = 0; nt < 4; nt++)
                    mma_f16(acc[mt][nt], ah[mt],
                            bh[nt >> 1][(nt & 1) * 2], bh[nt >> 1][(nt & 1) * 2 + 1]);
        }
        __syncthreads();
        if (kt + 2 < KT) load_stage(s, kt + 2);
        CP_COMMIT();
    }

    // epilogue
    #pragma unroll
    for (int mt = 0; mt < 4; mt++) {
        int r_lo = row0 + wm * 64 + mt * 16 + (lane >> 2);
        #pragma unroll
        for (int nt = 0; nt < 4; nt++) {
            int col = col0 + wn * 32 + nt * 8 + (lane & 3) * 2;
            float* d = acc[mt][nt];
            float bi0 = 0.f, bi1 = 0.f;
            if (BIAS) { bi0 = __ldg(bias + col); bi1 = __ldg(bias + col + 1); }
            #pragma unroll
            for (int half = 0; half < 2; half++) {
                int row = r_lo + half * 8;
                float v0 = d[half * 2 + 0], v1 = d[half * 2 + 1];
                if (BIAS) { v0 += bi0; v1 += bi1; }
                if (RELU) { v0 = fmaxf(v0, 0.f); v1 = fmaxf(v1, 0.f); }
                size_t base = (size_t)row * N + col;
                if (RES) {
                    float2 rr = *(const float2*)(res + base);
                    v0 += rr.x; v1 += rr.y;
                }
                if (OUTF16) {
                    *(uint32_t*)(Ch + base) = pk2h(v0, v1);
                } else {
                    *(float2*)(Cf + base) = make_float2(v0, v1);
                }
            }
        }
    }
}

// ---------------- Tensor-core flash attention (all single fp16) -------------
// CTA: 128 q-rows x one head. 8 warps x 16 rows. 64-key chunks, double buffer,
// 2 CTAs/SM.
#define AROWB 144
#define A_V   9216
#define A_M   18432
#define A_STRIDE 18688
#define A_SMEM (2 * A_STRIDE)   // 37376

__global__ __launch_bounds__(256, 2) void attention_tc(
    const h16* __restrict__ qkvh, const int* __restrict__ mask,
    h16* __restrict__ oh)
{
    extern __shared__ char smem[];
    uint32_t sb = smem_to_u32(smem);
    int tid = threadIdx.x, lane = tid & 31, w = tid >> 5;
    int bh_ = blockIdx.y, b = bh_ >> 4, h = bh_ & 15;
    int q0 = blockIdx.x * 128;
    size_t hoff = (size_t)h * DKH;
    int g = lane >> 3, r = lane & 7;

    // ---- stage Q (hi only) ----
    {
        int lm = tid >> 1;
        int lc = (tid & 1) * 4;
        size_t go = (size_t)(b * S_ + q0 + lm) * QKVS + hoff + lc * 8;
        uint32_t d0 = sb + (uint32_t)(lm * AROWB + lc * 16);
        #pragma unroll
        for (int j = 0; j < 4; j++)
            cp16(d0 + j * 16, qkvh + go + j * 8);
        CP_COMMIT();
    }
    asm volatile("cp.async.wait_group 0;" ::: "memory");
    __syncthreads();

    uint32_t Qh4[4][4];
    {
        uint32_t aoff = sb + (uint32_t)((w * 16 + (g & 1) * 8 + r) * AROWB + (g >> 1) * 16);
        #pragma unroll
        for (int ks = 0; ks < 4; ks++)
            ldm4(Qh4[ks], aoff + ks * 32);
    }
    __syncthreads();

    float m0 = -1e30f, m1 = -1e30f, l0 = 0.f, l1 = 0.f;
    float acc[8][4];
    #pragma unroll
    for (int i = 0; i < 8; i++)
        #pragma unroll
        for (int e = 0; e < 4; e++) acc[i][e] = 0.f;

    const h16* kbh = qkvh + (size_t)b * S_ * QKVS + D_ + hoff;
    const h16* vb  = qkvh + (size_t)b * S_ * QKVS + 2 * D_ + hoff;
    const int* mrow = mask + (size_t)b * S_;

    auto load_chunk = [&](int c) {
        uint32_t stg = sb + (c & 1) * A_STRIDE;
        int lm = tid >> 2;
        int lc = (tid & 3) * 2;
        size_t go = (size_t)(c * 64 + lm) * QKVS + lc * 8;
        uint32_t d = stg + (uint32_t)(lm * AROWB + lc * 16);
        cp16(d,            kbh + go);
        cp16(d + 16,       kbh + go + 8);
        cp16(d + A_V,      vb + go);
        cp16(d + A_V + 16, vb + go + 8);
        if (tid < 64)
            asm volatile("cp.async.ca.shared.global [%0], [%1], 4;"
                :: "r"(stg + A_M + tid * 4), "l"(mrow + c * 64 + tid));
    };

    const int NC = S_ / 64;   // 32
    load_chunk(0); CP_COMMIT();
    load_chunk(1); CP_COMMIT();

    uint32_t bKoff = (uint32_t)(((g >> 1) * 8 + r) * AROWB + (g & 1) * 16);
    uint32_t vOff  = (uint32_t)(((g & 1) * 8 + r) * AROWB + (g >> 1) * 16);

    for (int c = 0; c < NC; c++) {
        if (c + 1 < NC) { asm volatile("cp.async.wait_group 1;" ::: "memory"); }
        else            { asm volatile("cp.async.wait_group 0;" ::: "memory"); }
        __syncthreads();
        uint32_t stg = sb + (c & 1) * A_STRIDE;

        float s[8][4];
        #pragma unroll
        for (int i = 0; i < 8; i++)
            #pragma unroll
            for (int e = 0; e < 4; e++) s[i][e] = 0.f;

        // S = Q K^T (single-term fp16)
        #pragma unroll
        for (int ks = 0; ks < 4; ks++) {
            #pragma unroll
            for (int nb = 0; nb < 4; nb++) {
                uint32_t bh4[4];
                ldm4(bh4, stg + bKoff + nb * (16 * AROWB) + ks * 32);
                mma_f16(s[nb*2],   Qh4[ks], bh4[0], bh4[1]);
                mma_f16(s[nb*2+1], Qh4[ks], bh4[2], bh4[3]);
            }
        }

        // scale + mask
        const int* ms = (const int*)(smem + (size_t)(c & 1) * A_STRIDE + A_M);
        #pragma unroll
        for (int nt = 0; nt < 8; nt++) {
            int cc = nt * 8 + (lane & 3) * 2;
            int mv0 = ms[cc], mv1 = ms[cc + 1];
            #pragma unroll
            for (int e = 0; e < 4; e++) s[nt][e] *= 0.125f;
            if (mv0 == 0) { s[nt][0] = -1e9f; s[nt][2] = -1e9f; }
            if (mv1 == 0) { s[nt][1] = -1e9f; s[nt][3] = -1e9f; }
        }

        // online softmax (rows r and r+8 per thread)
        float mx0 = -1e30f, mx1 = -1e30f;
        #pragma unroll
        for (int nt = 0; nt < 8; nt++) {
            mx0 = fmaxf(mx0, fmaxf(s[nt][0], s[nt][1]));
            mx1 = fmaxf(mx1, fmaxf(s[nt][2], s[nt][3]));
        }
        mx0 = fmaxf(mx0, __shfl_xor_sync(0xffffffffu, mx0, 1));
        mx0 = fmaxf(mx0, __shfl_xor_sync(0xffffffffu, mx0, 2));
        mx1 = fmaxf(mx1, __shfl_xor_sync(0xffffffffu, mx1, 1));
        mx1 = fmaxf(mx1, __shfl_xor_sync(0xffffffffu, mx1, 2));
        float mn0 = fmaxf(m0, mx0), mn1 = fmaxf(m1, mx1);
        float sc0 = __expf(m0 - mn0), sc1 = __expf(m1 - mn1);
        m0 = mn0; m1 = mn1;
        float rs0 = 0.f, rs1 = 0.f;
        #pragma unroll
        for (int nt = 0; nt < 8; nt++) {
            s[nt][0] = __expf(s[nt][0] - mn0); rs0 += s[nt][0];
            s[nt][1] = __expf(s[nt][1] - mn0); rs0 += s[nt][1];
            s[nt][2] = __expf(s[nt][2] - mn1); rs1 += s[nt][2];
            s[nt][3] = __expf(s[nt][3] - mn1); rs1 += s[nt][3];
        }
        rs0 += __shfl_xor_sync(0xffffffffu, rs0, 1);
        rs0 += __shfl_xor_sync(0xffffffffu, rs0, 2);
        rs1 += __shfl_xor_sync(0xffffffffu, rs1, 1);
        rs1 += __shfl_xor_sync(0xffffffffu, rs1, 2);
        l0 = l0 * sc0 + rs0;
        l1 = l1 * sc1 + rs1;
        #pragma unroll
        for (int no = 0; no < 8; no++) {
            acc[no][0] *= sc0; acc[no][1] *= sc0;
            acc[no][2] *= sc1; acc[no][3] *= sc1;
        }

        // O += P V   (P fragments repacked directly as A operand)
        #pragma unroll
        for (int kb = 0; kb < 4; kb++) {
            uint32_t a4[4];
            a4[0] = pk2h(s[kb*2][0],   s[kb*2][1]);
            a4[1] = pk2h(s[kb*2][2],   s[kb*2][3]);
            a4[2] = pk2h(s[kb*2+1][0], s[kb*2+1][1]);
            a4[3] = pk2h(s[kb*2+1][2], s[kb*2+1][3]);
            #pragma unroll
            for (int db = 0; db < 4; db++) {
                uint32_t bv[4];
                ldm4t(bv, stg + A_V + vOff + kb * (16 * AROWB) + db * 32);
                mma_f16(acc[db*2],   a4, bv[0], bv[1]);
                mma_f16(acc[db*2+1], a4, bv[2], bv[3]);
            }
        }

        __syncthreads();
        if (c + 2 < NC) { load_chunk(c + 2); CP_COMMIT(); }
    }

    // ---- output: O / l -> fp16 (hi only) ----
    float inv0 = 1.f / l0, inv1 = 1.f / l1;
    int row0 = q0 + w * 16 + (lane >> 2);
    size_t t0 = (size_t)(b * S_ + row0) * D_ + hoff;
    size_t t1 = t0 + (size_t)8 * D_;
    #pragma unroll
    for (int no = 0; no < 8; no++) {
        int cc = no * 8 + (lane & 3) * 2;
        *(uint32_t*)(oh + t0 + cc) = pk2h(acc[no][0] * inv0, acc[no][1] * inv0);
        *(uint32_t*)(oh + t1 + cc) = pk2h(acc[no][2] * inv1, acc[no][3] * inv1);
    }
}

// ---------------- launch ----------------------------------------------------
extern "C" void kernel_launch(void* const* d_in, const int* in_sizes, int n_in,
                              void* d_out, int out_size)
{
    (void)in_sizes; (void)n_in; (void)out_size;
    const float* x    = (const float*)d_in[0];
    const int*   mask = (const int*)  d_in[1];
    const float* wq   = (const float*)d_in[2];
    const float* wk   = (const float*)d_in[3];
    const float* wv   = (const float*)d_in[4];
    const float* wo   = (const float*)d_in[5];
    const float* w1   = (const float*)d_in[6];
    const float* b1   = (const float*)d_in[7];
    const float* w2   = (const float*)d_in[8];
    const float* b2   = (const float*)d_in[9];
    const float* g1   = (const float*)d_in[10];
    const float* be1  = (const float*)d_in[11];
    const float* g2   = (const float*)d_in[12];
    const float* be2  = (const float*)d_in[13];
    float* out = (float*)d_out;

    float *h1;
    h16 *zh, *qkvh, *ah, *mh;
    h16 *wc, *wop, *w1p, *w2p;
    cudaGetSymbolAddress((void**)&h1, g_h1);
    cudaGetSymbolAddress((void**)&zh, g_zh);
    cudaGetSymbolAddress((void**)&qkvh, g_qkvh);
    cudaGetSymbolAddress((void**)&ah, g_ah);
    cudaGetSymbolAddress((void**)&mh, g_mh);
    cudaGetSymbolAddress((void**)&wc, g_wc);
    cudaGetSymbolAddress((void**)&wop, g_wo);
    cudaGetSymbolAddress((void**)&w1p, g_w1);
    cudaGetSymbolAddress((void**)&w2p, g_w2);

    cudaFuncSetAttribute(tc_gemm<false,false,false,true >, cudaFuncAttributeMaxDynamicSharedMemorySize, SMEM_GEMM);
    cudaFuncSetAttribute(tc_gemm<false,false,true ,false>, cudaFuncAttributeMaxDynamicSharedMemorySize, SMEM_GEMM);
    cudaFuncSetAttribute(tc_gemm<true ,true ,false,true >, cudaFuncAttributeMaxDynamicSharedMemorySize, SMEM_GEMM);
    cudaFuncSetAttribute(tc_gemm<false,true ,true ,false>, cudaFuncAttributeMaxDynamicSharedMemorySize, SMEM_GEMM);
    cudaFuncSetAttribute(attention_tc, cudaFuncAttributeMaxDynamicSharedMemorySize, A_SMEM);

    // 1-2: weight conversions
    convert_qkv<<<3072, 256>>>(wq, wk, wv, wc);
    convert_rest<<<9216, 256>>>(wo, w1, w2, wop, w1p, w2p);

    // 3: LN1 -> fp16
    layernorm_kernel<<<NT, 256>>>(x, g1, be1, zh);

    // 4: fused QKV GEMM (N = 3072) -> fp16
    dim3 gQKV(QKVS / 128, NT / 128);
    tc_gemm<false,false,false,true><<<gQKV, 256, SMEM_GEMM>>>(
        zh, wc, nullptr, nullptr, nullptr, qkvh, NT, QKVS, D_);

    // 5: attention (tensor core) -> fp16
    dim3 gAtt(S_ / 128, B_ * H_);
    attention_tc<<<gAtt, 256, A_SMEM>>>(qkvh, mask, ah);

    // 6: h1 = x + attn @ wo^T
    dim3 gP(D_ / 128, NT / 128);
    tc_gemm<false,false,true,false><<<gP, 256, SMEM_GEMM>>>(
        ah, wop, nullptr, x, h1, nullptr, NT, D_, D_);

    // 7: LN2 -> fp16
    layernorm_kernel<<<NT, 256>>>(h1, g2, be2, zh);

    // 8: FFN1: mid = relu(z @ w1^T + b1) -> fp16
    dim3 gF1(DFF_ / 128, NT / 128);
    tc_gemm<true,true,false,true><<<gF1, 256, SMEM_GEMM>>>(
        zh, w1p, b1, nullptr, nullptr, mh, NT, DFF_, D_);

    // 9: FFN2: out = h1 + mid @ w2^T + b2
    dim3 gF2(D_ / 128, NT / 128);
    tc_gemm<false,true,true,false><<<gF2, 256, SMEM_GEMM>>>(
        mh, w2p, b2, h1, out, nullptr, NT, D_, DFF_);
}

// round 11
// speedup vs baseline: 7.2169x; 1.0079x over previous
#include <cuda_runtime.h>
#include <cuda_fp16.h>
#include <math.h>
#include <stdint.h>

// Problem dims
#define B_  4
#define S_  2048
#define D_  1024
#define H_  16
#define DKH 64
#define DFF_ 4096
#define NT  (B_ * S_)   // 8192 tokens
#define QKVS 3072       // fused qkv row stride

typedef __half h16;

// ====================== PTX helpers (baseline ISA, sm_80+) ==================
__device__ __forceinline__ uint32_t smem_to_u32(const void* p) {
    uint32_t a;
    asm("{ .reg .u64 t; cvta.to.shared.u64 t, %1; cvt.u32.u64 %0, t; }" : "=r"(a) : "l"(p));
    return a;
}
__device__ __forceinline__ void cp16(uint32_t dst, const void* src) {
    asm volatile("cp.async.cg.shared.global [%0], [%1], 16;" :: "r"(dst), "l"(src));
}
#define CP_COMMIT() asm volatile("cp.async.commit_group;" ::: "memory")

__device__ __forceinline__ void ldm4(uint32_t* r, uint32_t addr) {
    asm volatile("ldmatrix.sync.aligned.m8n8.x4.shared.b16 {%0,%1,%2,%3}, [%4];"
        : "=r"(r[0]), "=r"(r[1]), "=r"(r[2]), "=r"(r[3]) : "r"(addr));
}
__device__ __forceinline__ void ldm4t(uint32_t* r, uint32_t addr) {
    asm volatile("ldmatrix.sync.aligned.m8n8.x4.trans.shared.b16 {%0,%1,%2,%3}, [%4];"
        : "=r"(r[0]), "=r"(r[1]), "=r"(r[2]), "=r"(r[3]) : "r"(addr));
}
__device__ __forceinline__ void mma_f16(float* d, const uint32_t* a,
                                        uint32_t b0, uint32_t b1) {
    asm volatile(
        "mma.sync.aligned.m16n8k16.row.col.f32.f16.f16.f32 "
        "{%0,%1,%2,%3}, {%4,%5,%6,%7}, {%8,%9}, {%0,%1,%2,%3};"
        : "+f"(d[0]), "+f"(d[1]), "+f"(d[2]), "+f"(d[3])
        : "r"(a[0]), "r"(a[1]), "r"(a[2]), "r"(a[3]), "r"(b0), "r"(b1));
}

__device__ __forceinline__ uint32_t pk2h(float a, float b) {
    return (uint32_t)__half_as_ushort(__float2half_rn(a)) |
           ((uint32_t)__half_as_ushort(__float2half_rn(b)) << 16);
}

// ---------------- scratch (device globals) ----------------------------------
__device__ __align__(256) float g_h1[(size_t)NT * D_];
__device__ __align__(256) h16 g_zh[(size_t)NT * D_];
__device__ __align__(256) h16 g_qkvh[(size_t)NT * QKVS];
__device__ __align__(256) h16 g_ah[(size_t)NT * D_];
__device__ __align__(256) h16 g_mh[(size_t)NT * DFF_];
__device__ __align__(256) h16 g_wc[(size_t)3*D_*D_];
__device__ __align__(256) h16 g_wo[(size_t)D_*D_];
__device__ __align__(256) h16 g_w1[(size_t)DFF_*D_];
__device__ __align__(256) h16 g_w2[(size_t)D_*DFF_];

// ---------------- fused weight converts (2 launches) ------------------------
__global__ __launch_bounds__(256) void convert_qkv(
    const float* __restrict__ wq, const float* __restrict__ wk,
    const float* __restrict__ wv, h16* __restrict__ wc)
{
    int seg = blockIdx.x >> 10;            // 0..2
    int i = (blockIdx.x & 1023) * 256 + threadIdx.x;
    const float* src = (seg == 0) ? wq : (seg == 1) ? wk : wv;
    float4 v = ((const float4*)src)[i];
    ((uint2*)(wc + (size_t)seg * D_ * D_))[i] =
        make_uint2(pk2h(v.x, v.y), pk2h(v.z, v.w));
}
__global__ __launch_bounds__(256) void convert_rest(
    const float* __restrict__ wo, const float* __restrict__ w1,
    const float* __restrict__ w2, h16* __restrict__ dwo,
    h16* __restrict__ dw1, h16* __restrict__ dw2)
{
    int bidx = blockIdx.x;
    const float* src; h16* dst; int i;
    if (bidx < 1024)       { src = wo; dst = dwo; i = bidx * 256 + threadIdx.x; }
    else if (bidx < 5120)  { src = w1; dst = dw1; i = (bidx - 1024) * 256 + threadIdx.x; }
    else                   { src = w2; dst = dw2; i = (bidx - 5120) * 256 + threadIdx.x; }
    float4 v = ((const float4*)src)[i];
    ((uint2*)dst)[i] = make_uint2(pk2h(v.x, v.y), pk2h(v.z, v.w));
}

// ---------------- LayerNorm (Bessel ddof=1, eps=1e-9) -> fp16 ---------------
__global__ __launch_bounds__(256) void layernorm_kernel(
    const float* __restrict__ x, const float* __restrict__ gamma,
    const float* __restrict__ beta, h16* __restrict__ yh)
{
    int row = blockIdx.x;
    int t = threadIdx.x;
    const float4* xr = (const float4*)(x + (size_t)row * D_);
    float4 v = xr[t];
    float s  = v.x + v.y + v.z + v.w;
    float ss = v.x*v.x + v.y*v.y + v.z*v.z + v.w*v.w;
    #pragma unroll
    for (int o = 16; o > 0; o >>= 1) {
        s  += __shfl_xor_sync(0xffffffffu, s,  o);
        ss += __shfl_xor_sync(0xffffffffu, ss, o);
    }
    __shared__ float shs[8], shq[8];
    int w = t >> 5, l = t & 31;
    if (l == 0) { shs[w] = s; shq[w] = ss; }
    __syncthreads();
    float S = 0.f, Q = 0.f;
    #pragma unroll
    for (int i = 0; i < 8; i++) { S += shs[i]; Q += shq[i]; }
    float mean = S * (1.f / (float)D_);
    float var  = (Q - (float)D_ * mean * mean) * (1.f / (float)(D_ - 1));
    float inv  = rsqrtf(var + 1e-9f);
    const float4 g  = ((const float4*)gamma)[t];
    const float4 be = ((const float4*)beta)[t];
    float o0 = g.x * (v.x - mean) * inv + be.x;
    float o1 = g.y * (v.y - mean) * inv + be.y;
    float o2 = g.z * (v.z - mean) * inv + be.z;
    float o3 = g.w * (v.w - mean) * inv + be.w;
    size_t idx = (size_t)row * (D_/4) + t;
    ((uint2*)yh)[idx] = make_uint2(pk2h(o0, o1), pk2h(o2, o3));
}

// ---------------- mma.sync fp16 single-term GEMM ----------------------------
// 128x128x64 CTA K-chunk, 256 threads (8 warps, 2m x 4n), 3-stage cp.async,
// single barrier per iteration, 2 CTAs/SM, XOR-swizzled smem (no pad).
#define MATB 16384   // 128 rows x 128 bytes
#define STB  (2 * MATB)
#define SMEM_GEMM (3 * STB)   // 98304

template<bool RELU, bool BIAS, bool RES, bool OUTF16>
__global__ __launch_bounds__(256, 2) void tc_gemm(
    const h16* __restrict__ Ah, const h16* __restrict__ Bh,
    const float* __restrict__ bias, const float* __restrict__ res,
    float* __restrict__ Cf, h16* __restrict__ Ch,
    int M, int N, int K)
{
    extern __shared__ char smem[];
    uint32_t sb = smem_to_u32(smem);
    int tid = threadIdx.x;
    int lane = tid & 31, wid = tid >> 5;
    int wm = wid & 1, wn = wid >> 1;
    int row0 = blockIdx.y * 128, col0 = blockIdx.x * 128;

    // ---- loader mapping: row lm (0..127), half lc (0/1 = 64B each) ----
    int lm = tid >> 1;
    int lc = tid & 1;
    const h16* aHs = Ah + (size_t)(row0 + lm) * K + lc * 32;
    const h16* bHs = Bh + (size_t)(col0 + lm) * K + lc * 32;
    uint32_t dRow = (uint32_t)(lm << 7);
    uint32_t dCol[4];
    #pragma unroll
    for (int j = 0; j < 4; j++)
        dCol[j] = (uint32_t)(((lc * 64 + j * 16) ^ ((lm & 7) << 4)));

    auto load_stage = [&](int p, int kt) {
        uint32_t s0 = sb + p * STB + dRow;
        size_t ko = (size_t)kt * 64;
        #pragma unroll
        for (int j = 0; j < 4; j++) cp16(s0 + dCol[j], aHs + ko + j * 8);
        #pragma unroll
        for (int j = 0; j < 4; j++) cp16(s0 + MATB + dCol[j], bHs + ko + j * 8);
    };

    // ---- ldmatrix per-lane offsets (swizzle term = r*16, lane-constant) ----
    int g = lane >> 3, r = lane & 7;
    uint32_t aRow[4], bRow[2];
    #pragma unroll
    for (int mt = 0; mt < 4; mt++)
        aRow[mt] = (uint32_t)((wm * 64 + mt * 16 + (g & 1) * 8 + r) << 7);
    #pragma unroll
    for (int nb = 0; nb < 2; nb++)
        bRow[nb] = (uint32_t)((wn * 32 + nb * 16 + (g >> 1) * 8 + r) << 7);
    uint32_t aColSw[4], bColSw[4];
    #pragma unroll
    for (int h = 0; h < 4; h++) {
        aColSw[h] = (uint32_t)(((h << 5) + ((g >> 1) << 4)) ^ (r << 4));
        bColSw[h] = (uint32_t)(((h << 5) + ((g & 1) << 4)) ^ (r << 4));
    }

    float acc[4][4][4];
    #pragma unroll
    for (int i = 0; i < 4; i++)
        #pragma unroll
        for (int j = 0; j < 4; j++)
            #pragma unroll
            for (int e = 0; e < 4; e++) acc[i][j][e] = 0.f;

    int KT = K / 64;
    load_stage(0, 0); CP_COMMIT();
    load_stage(1, 1); CP_COMMIT();

    int s = 0;
    for (int kt = 0; kt < KT; kt++) {
        __syncthreads();                   // stage (kt-1)%3 fully consumed
        if (kt + 2 < KT) {
            int sw = s + 2; if (sw >= 3) sw -= 3;
            load_stage(sw, kt + 2);        // overlaps with MMA below
        }
        CP_COMMIT();
        asm volatile("cp.async.wait_group 2;" ::: "memory");  // stage kt ready
        uint32_t st = sb + s * STB;
        #pragma unroll
        for (int h = 0; h < 4; h++) {
            uint32_t ah[4][4], bh[2][4];
            #pragma unroll
            for (int mt = 0; mt < 4; mt++)
                ldm4(ah[mt], st + aRow[mt] + aColSw[h]);
            #pragma unroll
            for (int nb = 0; nb < 2; nb++)
                ldm4(bh[nb], st + MATB + bRow[nb] + bColSw[h]);
            #pragma unroll
            for (int mt = 0; mt < 4; mt++)
                #pragma unroll
                for (int nt = 0; nt < 4; nt++)
                    mma_f16(acc[mt][nt], ah[mt],
                            bh[nt >> 1][(nt & 1) * 2], bh[nt >> 1][(nt & 1) * 2 + 1]);
        }
        if (++s >= 3) s = 0;
    }

    // epilogue
    #pragma unroll
    for (int mt = 0; mt < 4; mt++) {
        int r_lo = row0 + wm * 64 + mt * 16 + (lane >> 2);
        #pragma unroll
        for (int nt = 0; nt < 4; nt++) {
            int col = col0 + wn * 32 + nt * 8 + (lane & 3) * 2;
            float* d = acc[mt][nt];
            float bi0 = 0.f, bi1 = 0.f;
            if (BIAS) { bi0 = __ldg(bias + col); bi1 = __ldg(bias + col + 1); }
            #pragma unroll
            for (int half = 0; half < 2; half++) {
                int row = r_lo + half * 8;
                float v0 = d[half * 2 + 0], v1 = d[half * 2 + 1];
                if (BIAS) { v0 += bi0; v1 += bi1; }
                if (RELU) { v0 = fmaxf(v0, 0.f); v1 = fmaxf(v1, 0.f); }
                size_t base = (size_t)row * N + col;
                if (RES) {
                    float2 rr = *(const float2*)(res + base);
                    v0 += rr.x; v1 += rr.y;
                }
                if (OUTF16) {
                    *(uint32_t*)(Ch + base) = pk2h(v0, v1);
                } else {
                    *(float2*)(Cf + base) = make_float2(v0, v1);
                }
            }
        }
    }
}

// ---------------- Tensor-core flash attention (all single fp16) -------------
// CTA: 128 q-rows x one head. 8 warps x 16 rows. 64-key chunks, 3-stage
// cp.async ring, single barrier per chunk, 2 CTAs/SM.
#define AROWB 144
#define A_V   9216
#define A_M   18432
#define A_STRIDE 18688
#define A_SMEM (3 * A_STRIDE)   // 56064

__global__ __launch_bounds__(256, 2) void attention_tc(
    const h16* __restrict__ qkvh, const int* __restrict__ mask,
    h16* __restrict__ oh)
{
    extern __shared__ char smem[];
    uint32_t sb = smem_to_u32(smem);
    int tid = threadIdx.x, lane = tid & 31, w = tid >> 5;
    int bh_ = blockIdx.y, b = bh_ >> 4, h = bh_ & 15;
    int q0 = blockIdx.x * 128;
    size_t hoff = (size_t)h * DKH;
    int g = lane >> 3, r = lane & 7;

    // ---- stage Q (hi only) into stage-0 region, read to regs, then reuse ---
    {
        int lm = tid >> 1;
        int lc = (tid & 1) * 4;
        size_t go = (size_t)(b * S_ + q0 + lm) * QKVS + hoff + lc * 8;
        uint32_t d0 = sb + (uint32_t)(lm * AROWB + lc * 16);
        #pragma unroll
        for (int j = 0; j < 4; j++)
            cp16(d0 + j * 16, qkvh + go + j * 8);
        CP_COMMIT();
    }
    asm volatile("cp.async.wait_group 0;" ::: "memory");
    __syncthreads();

    uint32_t Qh4[4][4];
    {
        uint32_t aoff = sb + (uint32_t)((w * 16 + (g & 1) * 8 + r) * AROWB + (g >> 1) * 16);
        #pragma unroll
        for (int ks = 0; ks < 4; ks++)
            ldm4(Qh4[ks], aoff + ks * 32);
    }
    __syncthreads();   // protect stage-0 region before K/V chunk 0 overwrites

    float m0 = -1e30f, m1 = -1e30f, l0 = 0.f, l1 = 0.f;
    float acc[8][4];
    #pragma unroll
    for (int i = 0; i < 8; i++)
        #pragma unroll
        for (int e = 0; e < 4; e++) acc[i][e] = 0.f;

    const h16* kbh = qkvh + (size_t)b * S_ * QKVS + D_ + hoff;
    const h16* vb  = qkvh + (size_t)b * S_ * QKVS + 2 * D_ + hoff;
    const int* mrow = mask + (size_t)b * S_;

    auto load_chunk = [&](int stg_i, int c) {
        uint32_t stg = sb + stg_i * A_STRIDE;
        int lm = tid >> 2;
        int lc = (tid & 3) * 2;
        size_t go = (size_t)(c * 64 + lm) * QKVS + lc * 8;
        uint32_t d = stg + (uint32_t)(lm * AROWB + lc * 16);
        cp16(d,            kbh + go);
        cp16(d + 16,       kbh + go + 8);
        cp16(d + A_V,      vb + go);
        cp16(d + A_V + 16, vb + go + 8);
        if (tid < 64)
            asm volatile("cp.async.ca.shared.global [%0], [%1], 4;"
                :: "r"(stg + A_M + tid * 4), "l"(mrow + c * 64 + tid));
    };

    const int NC = S_ / 64;   // 32
    load_chunk(0, 0); CP_COMMIT();
    load_chunk(1, 1); CP_COMMIT();

    uint32_t bKoff = (uint32_t)(((g >> 1) * 8 + r) * AROWB + (g & 1) * 16);
    uint32_t vOff  = (uint32_t)(((g & 1) * 8 + r) * AROWB + (g >> 1) * 16);

    int si = 0;
    for (int c = 0; c < NC; c++) {
        __syncthreads();                    // stage (c-1)%3 fully consumed
        if (c + 2 < NC) {
            int sw = si + 2; if (sw >= 3) sw -= 3;
            load_chunk(sw, c + 2);          // overlaps with compute below
        }
        CP_COMMIT();
        asm volatile("cp.async.wait_group 2;" ::: "memory");   // chunk c ready
        uint32_t stg = sb + si * A_STRIDE;

        float s[8][4];
        #pragma unroll
        for (int i = 0; i < 8; i++)
            #pragma unroll
            for (int e = 0; e < 4; e++) s[i][e] = 0.f;

        // S = Q K^T (single-term fp16)
        #pragma unroll
        for (int ks = 0; ks < 4; ks++) {
            #pragma unroll
            for (int nb = 0; nb < 4; nb++) {
                uint32_t bh4[4];
                ldm4(bh4, stg + bKoff + nb * (16 * AROWB) + ks * 32);
                mma_f16(s[nb*2],   Qh4[ks], bh4[0], bh4[1]);
                mma_f16(s[nb*2+1], Qh4[ks], bh4[2], bh4[3]);
            }
        }

        // scale + mask
        const int* ms = (const int*)(smem + (size_t)si * A_STRIDE + A_M);
        #pragma unroll
        for (int nt = 0; nt < 8; nt++) {
            int cc = nt * 8 + (lane & 3) * 2;
            int mv0 = ms[cc], mv1 = ms[cc + 1];
            #pragma unroll
            for (int e = 0; e < 4; e++) s[nt][e] *= 0.125f;
            if (mv0 == 0) { s[nt][0] = -1e9f; s[nt][2] = -1e9f; }
            if (mv1 == 0) { s[nt][1] = -1e9f; s[nt][3] = -1e9f; }
        }

        // online softmax (rows r and r+8 per thread)
        float mx0 = -1e30f, mx1 = -1e30f;
        #pragma unroll
        for (int nt = 0; nt < 8; nt++) {
            mx0 = fmaxf(mx0, fmaxf(s[nt][0], s[nt][1]));
            mx1 = fmaxf(mx1, fmaxf(s[nt][2], s[nt][3]));
        }
        mx0 = fmaxf(mx0, __shfl_xor_sync(0xffffffffu, mx0, 1));
        mx0 = fmaxf(mx0, __shfl_xor_sync(0xffffffffu, mx0, 2));
        mx1 = fmaxf(mx1, __shfl_xor_sync(0xffffffffu, mx1, 1));
        mx1 = fmaxf(mx1, __shfl_xor_sync(0xffffffffu, mx1, 2));
        float mn0 = fmaxf(m0, mx0), mn1 = fmaxf(m1, mx1);
        float sc0 = __expf(m0 - mn0), sc1 = __expf(m1 - mn1);
        m0 = mn0; m1 = mn1;
        float rs0 = 0.f, rs1 = 0.f;
        #pragma unroll
        for (int nt = 0; nt < 8; nt++) {
            s[nt][0] = __expf(s[nt][0] - mn0); rs0 += s[nt][0];
            s[nt][1] = __expf(s[nt][1] - mn0); rs0 += s[nt][1];
            s[nt][2] = __expf(s[nt][2] - mn1); rs1 += s[nt][2];
            s[nt][3] = __expf(s[nt][3] - mn1); rs1 += s[nt][3];
        }
        rs0 += __shfl_xor_sync(0xffffffffu, rs0, 1);
        rs0 += __shfl_xor_sync(0xffffffffu, rs0, 2);
        rs1 += __shfl_xor_sync(0xffffffffu, rs1, 1);
        rs1 += __shfl_xor_sync(0xffffffffu, rs1, 2);
        l0 = l0 * sc0 + rs0;
        l1 = l1 * sc1 + rs1;
        #pragma unroll
        for (int no = 0; no < 8; no++) {
            acc[no][0] *= sc0; acc[no][1] *= sc0;
            acc[no][2] *= sc1; acc[no][3] *= sc1;
        }

        // O += P V   (P fragments repacked directly as A operand)
        #pragma unroll
        for (int kb = 0; kb < 4; kb++) {
            uint32_t a4[4];
            a4[0] = pk2h(s[kb*2][0],   s[kb*2][1]);
            a4[1] = pk2h(s[kb*2][2],   s[kb*2][3]);
            a4[2] = pk2h(s[kb*2+1][0], s[kb*2+1][1]);
            a4[3] = pk2h(s[kb*2+1][2], s[kb*2+1][3]);
            #pragma unroll
            for (int db = 0; db < 4; db++) {
                uint32_t bv[4];
                ldm4t(bv, stg + A_V + vOff + kb * (16 * AROWB) + db * 32);
                mma_f16(acc[db*2],   a4, bv[0], bv[1]);
                mma_f16(acc[db*2+1], a4, bv[2], bv[3]);
            }
        }

        if (++si >= 3) si = 0;
    }

    // ---- output: O / l -> fp16 (hi only) ----
    float inv0 = 1.f / l0, inv1 = 1.f / l1;
    int row0 = q0 + w * 16 + (lane >> 2);
    size_t t0 = (size_t)(b * S_ + row0) * D_ + hoff;
    size_t t1 = t0 + (size_t)8 * D_;
    #pragma unroll
    for (int no = 0; no < 8; no++) {
        int cc = no * 8 + (lane & 3) * 2;
        *(uint32_t*)(oh + t0 + cc) = pk2h(acc[no][0] * inv0, acc[no][1] * inv0);
        *(uint32_t*)(oh + t1 + cc) = pk2h(acc[no][2] * inv1, acc[no][3] * inv1);
    }
}

// ---------------- launch ----------------------------------------------------
extern "C" void kernel_launch(void* const* d_in, const int* in_sizes, int n_in,
                              void* d_out, int out_size)
{
    (void)in_sizes; (void)n_in; (void)out_size;
    const float* x    = (const float*)d_in[0];
    const int*   mask = (const int*)  d_in[1];
    const float* wq   = (const float*)d_in[2];
    const float* wk   = (const float*)d_in[3];
    const float* wv   = (const float*)d_in[4];
    const float* wo   = (const float*)d_in[5];
    const float* w1   = (const float*)d_in[6];
    const float* b1   = (const float*)d_in[7];
    const float* w2   = (const float*)d_in[8];
    const float* b2   = (const float*)d_in[9];
    const float* g1   = (const float*)d_in[10];
    const float* be1  = (const float*)d_in[11];
    const float* g2   = (const float*)d_in[12];
    const float* be2  = (const float*)d_in[13];
    float* out = (float*)d_out;

    float *h1;
    h16 *zh, *qkvh, *ah, *mh;
    h16 *wc, *wop, *w1p, *w2p;
    cudaGetSymbolAddress((void**)&h1, g_h1);
    cudaGetSymbolAddress((void**)&zh, g_zh);
    cudaGetSymbolAddress((void**)&qkvh, g_qkvh);
    cudaGetSymbolAddress((void**)&ah, g_ah);
    cudaGetSymbolAddress((void**)&mh, g_mh);
    cudaGetSymbolAddress((void**)&wc, g_wc);
    cudaGetSymbolAddress((void**)&wop, g_wo);
    cudaGetSymbolAddress((void**)&w1p, g_w1);
    cudaGetSymbolAddress((void**)&w2p, g_w2);

    cudaFuncSetAttribute(tc_gemm<false,false,false,true >, cudaFuncAttributeMaxDynamicSharedMemorySize, SMEM_GEMM);
    cudaFuncSetAttribute(tc_gemm<false,false,true ,false>, cudaFuncAttributeMaxDynamicSharedMemorySize, SMEM_GEMM);
    cudaFuncSetAttribute(tc_gemm<true ,true ,false,true >, cudaFuncAttributeMaxDynamicSharedMemorySize, SMEM_GEMM);
    cudaFuncSetAttribute(tc_gemm<false,true ,true ,false>, cudaFuncAttributeMaxDynamicSharedMemorySize, SMEM_GEMM);
    cudaFuncSetAttribute(attention_tc, cudaFuncAttributeMaxDynamicSharedMemorySize, A_SMEM);

    // 1-2: weight conversions
    convert_qkv<<<3072, 256>>>(wq, wk, wv, wc);
    convert_rest<<<9216, 256>>>(wo, w1, w2, wop, w1p, w2p);

    // 3: LN1 -> fp16
    layernorm_kernel<<<NT, 256>>>(x, g1, be1, zh);

    // 4: fused QKV GEMM (N = 3072) -> fp16
    dim3 gQKV(QKVS / 128, NT / 128);
    tc_gemm<false,false,false,true><<<gQKV, 256, SMEM_GEMM>>>(
        zh, wc, nullptr, nullptr, nullptr, qkvh, NT, QKVS, D_);

    // 5: attention (tensor core) -> fp16
    dim3 gAtt(S_ / 128, B_ * H_);
    attention_tc<<<gAtt, 256, A_SMEM>>>(qkvh, mask, ah);

    // 6: h1 = x + attn @ wo^T
    dim3 gP(D_ / 128, NT / 128);
    tc_gemm<false,false,true,false><<<gP, 256, SMEM_GEMM>>>(
        ah, wop, nullptr, x, h1, nullptr, NT, D_, D_);

    // 7: LN2 -> fp16
    layernorm_kernel<<<NT, 256>>>(h1, g2, be2, zh);

    // 8: FFN1: mid = relu(z @ w1^T + b1) -> fp16
    dim3 gF1(DFF_ / 128, NT / 128);
    tc_gemm<true,true,false,true><<<gF1, 256, SMEM_GEMM>>>(
        zh, w1p, b1, nullptr, nullptr, mh, NT, DFF_, D_);

    // 9: FFN2: out = h1 + mid @ w2^T + b2
    dim3 gF2(D_ / 128, NT / 128);
    tc_gemm<false,true,true,false><<<gF2, 256, SMEM_GEMM>>>(
        mh, w2p, b2, h1, out, nullptr, NT, D_, DFF_);
}